// round 6
// baseline (speedup 1.0000x reference)
#include <cuda_runtime.h>
#include <cuda_bf16.h>
#include <math.h>
#include <stdint.h>

#define NE 200000
#define NN 10000
typedef unsigned short ushort_t;

// ---------------- scratch ----------------
__device__ float gS[NN * 128];
__device__ float gV[NN * 384];
__device__ ushort_t gHaH[NE * 64], gHaL[NE * 64];
__device__ ushort_t gHbH[NE * 64], gHbL[NE * 64];
__device__ ushort_t gTH[(size_t)NE * 512], gTL[(size_t)NE * 512];
__device__ ushort_t gSCH[(size_t)NE * 256], gSCL[(size_t)NE * 256];
__device__ ushort_t gVEH[(size_t)NE * 768], gVEL[(size_t)NE * 768];
__device__ float gCST;
__device__ int   gIdx64;

// ---------------- helpers ----------------
__device__ __forceinline__ uint32_t smem_u32(const void* p) {
    uint32_t a;
    asm("{ .reg .u64 t; cvta.to.shared.u64 t, %1; cvt.u32.u64 %0, t; }" : "=r"(a) : "l"(p));
    return a;
}
__device__ __forceinline__ unsigned pk_bf2(float x, float y) {
    __nv_bfloat162 t = __floats2bfloat162_rn(x, y);
    return *(unsigned*)&t;
}
__device__ __forceinline__ void split_bf(float x, ushort_t& h, ushort_t& l) {
    __nv_bfloat16 hb = __float2bfloat16_rn(x);
    float r = x - __bfloat162float(hb);
    __nv_bfloat16 lb = __float2bfloat16_rn(r);
    h = *(ushort_t*)&hb; l = *(ushort_t*)&lb;
}
__device__ __forceinline__ float bf2f(ushort_t u) {
    __nv_bfloat16 b = *(__nv_bfloat16*)&u;
    return __bfloat162float(b);
}
__device__ __forceinline__ void mma_bf16(float c[4], const unsigned a[4], const unsigned b[2]) {
    asm volatile("mma.sync.aligned.m16n8k16.row.col.f32.bf16.bf16.f32 "
        "{%0,%1,%2,%3}, {%4,%5,%6,%7}, {%8,%9}, {%0,%1,%2,%3};\n"
        : "+f"(c[0]), "+f"(c[1]), "+f"(c[2]), "+f"(c[3])
        : "r"(a[0]), "r"(a[1]), "r"(a[2]), "r"(a[3]), "r"(b[0]), "r"(b[1]));
}
__device__ __forceinline__ void ldsm4(unsigned r[4], uint32_t addr) {
    asm volatile("ldmatrix.sync.aligned.m8n8.x4.shared.b16 {%0,%1,%2,%3}, [%4];"
        : "=r"(r[0]), "=r"(r[1]), "=r"(r[2]), "=r"(r[3]) : "r"(addr));
}

// ---------------- tensor GEMM, A pre-split bf16 hi/lo in DRAM ------------------
// C[r][c] = scale * sum_k (Ah+Al)[r][k] * B[k][c]
// Ah/Al: [M,lda] bf16 row-major. B: [K,ldb] fp32. Tile 128x64, BK=32, 8 warps.
// OUTB: write Ch/Cl bf16 pair (intermediates). CMODE1: r=3e+m interleave (fp32).
template <int SILU, int CMODE, int OUTB>
__global__ __launch_bounds__(256, 2) void mma_gemm(
        const ushort_t* __restrict__ AhG, const ushort_t* __restrict__ AlG, int lda,
        const float* __restrict__ B, int ldb,
        float* __restrict__ C, ushort_t* __restrict__ Ch, ushort_t* __restrict__ Cl,
        int ldc, int M, int K, float scale) {
    const int PK = 40;
    __shared__ __align__(16) ushort_t Ah[128][PK];
    __shared__ __align__(16) ushort_t Al[128][PK];
    __shared__ __align__(16) ushort_t Bh2[64][PK];
    __shared__ __align__(16) ushort_t Bl2[64][PK];

    int tid = threadIdx.x;
    int wid = tid >> 5, lane = tid & 31;
    int warp_m = wid & 3, warp_n = wid >> 2;
    int g = lane >> 2, tg = lane & 3;
    int row0 = blockIdx.x * 128, col0 = blockIdx.y * 64;
    int am = warp_m * 32, bn = warp_n * 32;

    int arow = (lane & 7) + ((lane >> 3) & 1) * 8;
    int acol = (lane >> 4) * 8;
    uint32_t aAddrH = smem_u32(&Ah[am + arow][acol]);
    uint32_t aAddrL = smem_u32(&Al[am + arow][acol]);
    int brow = (lane & 7) + ((lane >> 4) & 1) * 8;
    int bcol = ((lane >> 3) & 1) * 8;
    uint32_t bAddrH = smem_u32(&Bh2[bn + brow][bcol]);
    uint32_t bAddrL = smem_u32(&Bl2[bn + brow][bcol]);

    float acc[2][4][4];
#pragma unroll
    for (int mt = 0; mt < 2; mt++)
#pragma unroll
        for (int nt = 0; nt < 4; nt++)
#pragma unroll
            for (int j = 0; j < 4; j++) acc[mt][nt][j] = 0.f;

    // A staging: idx = tid + i*256; r = idx>>2 (0..127), c8 = (idx&3)*8
    int sAr[2], sAc = (tid & 3) * 8;
    sAr[0] = tid >> 2; sAr[1] = (tid + 256) >> 2;
    uint4 aSh[2], aSl[2];
    // B staging
    int sBn = tid & 63, sBk = (tid >> 6) * 8;
    float bS[8];

    int nchunks = K / 32;
    // prologue
#pragma unroll
    for (int i = 0; i < 2; i++) {
        int gr = row0 + sAr[i];
        if (gr < M) {
            aSh[i] = *(const uint4*)(AhG + (size_t)gr * lda + sAc);
            aSl[i] = *(const uint4*)(AlG + (size_t)gr * lda + sAc);
        } else {
            aSh[i] = make_uint4(0, 0, 0, 0); aSl[i] = make_uint4(0, 0, 0, 0);
        }
    }
    {
        const float* Bp = B + (size_t)sBk * ldb + col0 + sBn;
#pragma unroll
        for (int j = 0; j < 8; j++) bS[j] = Bp[(size_t)j * ldb];
    }

    for (int ci = 0; ci < nchunks; ci++) {
        // stage to smem
#pragma unroll
        for (int i = 0; i < 2; i++) {
            *(uint4*)&Ah[sAr[i]][sAc] = aSh[i];
            *(uint4*)&Al[sAr[i]][sAc] = aSl[i];
        }
        {
            unsigned hv[4], lv[4];
#pragma unroll
            for (int j = 0; j < 4; j++) {
                float h0 = __bfloat162float(__float2bfloat16_rn(bS[2 * j]));
                float h1 = __bfloat162float(__float2bfloat16_rn(bS[2 * j + 1]));
                hv[j] = pk_bf2(bS[2 * j], bS[2 * j + 1]);
                lv[j] = pk_bf2(bS[2 * j] - h0, bS[2 * j + 1] - h1);
            }
            *(uint4*)&Bh2[sBn][sBk] = *(uint4*)hv;
            *(uint4*)&Bl2[sBn][sBk] = *(uint4*)lv;
        }
        __syncthreads();

        // prefetch next chunk
        if (ci + 1 < nchunks) {
            int kn = (ci + 1) * 32;
#pragma unroll
            for (int i = 0; i < 2; i++) {
                int gr = row0 + sAr[i];
                if (gr < M) {
                    aSh[i] = *(const uint4*)(AhG + (size_t)gr * lda + kn + sAc);
                    aSl[i] = *(const uint4*)(AlG + (size_t)gr * lda + kn + sAc);
                } else {
                    aSh[i] = make_uint4(0, 0, 0, 0); aSl[i] = make_uint4(0, 0, 0, 0);
                }
            }
            const float* Bp = B + (size_t)(kn + sBk) * ldb + col0 + sBn;
#pragma unroll
            for (int j = 0; j < 8; j++) bS[j] = Bp[(size_t)j * ldb];
        }

        // MMA
#pragma unroll
        for (int ks = 0; ks < 2; ks++) {
            unsigned ah[2][4], al[2][4], bh[2][4], bl[2][4];
#pragma unroll
            for (int mt = 0; mt < 2; mt++) {
                ldsm4(ah[mt], aAddrH + mt * (16 * PK * 2) + ks * 32);
                ldsm4(al[mt], aAddrL + mt * (16 * PK * 2) + ks * 32);
            }
#pragma unroll
            for (int np = 0; np < 2; np++) {
                ldsm4(bh[np], bAddrH + np * (16 * PK * 2) + ks * 32);
                ldsm4(bl[np], bAddrL + np * (16 * PK * 2) + ks * 32);
            }
#pragma unroll
            for (int mt = 0; mt < 2; mt++)
#pragma unroll
                for (int nt = 0; nt < 4; nt++) {
                    const unsigned* bhf = &bh[nt >> 1][(nt & 1) * 2];
                    const unsigned* blf = &bl[nt >> 1][(nt & 1) * 2];
                    mma_bf16(acc[mt][nt], ah[mt], bhf);
                    mma_bf16(acc[mt][nt], ah[mt], blf);
                    mma_bf16(acc[mt][nt], al[mt], bhf);
                }
        }
        __syncthreads();
    }

    // epilogue
    float cst = SILU ? gCST : 1.f;
#pragma unroll
    for (int mt = 0; mt < 2; mt++) {
        int rr[2]; rr[0] = row0 + am + mt * 16 + g; rr[1] = rr[0] + 8;
#pragma unroll
        for (int nt = 0; nt < 4; nt++) {
            int cc = col0 + bn + nt * 8 + tg * 2;
            float xs[4];
#pragma unroll
            for (int j = 0; j < 4; j++) xs[j] = acc[mt][nt][j] * scale;
            if (SILU) {
#pragma unroll
                for (int j = 0; j < 4; j++)
                    xs[j] = xs[j] / (1.f + __expf(-xs[j])) * cst;
            }
#pragma unroll
            for (int h = 0; h < 2; h++) {
                int r = rr[h];
                if (r >= M) continue;
                float x0 = xs[2 * h], x1 = xs[2 * h + 1];
                if (OUTB) {
                    ushort_t h0, l0, h1, l1;
                    split_bf(x0, h0, l0); split_bf(x1, h1, l1);
                    ushort2 ph; ph.x = h0; ph.y = h1;
                    ushort2 pl; pl.x = l0; pl.y = l1;
                    *(ushort2*)&Ch[(size_t)r * ldc + cc] = ph;
                    *(ushort2*)&Cl[(size_t)r * ldc + cc] = pl;
                } else if (CMODE == 0) {
                    float2 o = make_float2(x0, x1);
                    *(float2*)&C[(size_t)r * ldc + cc] = o;
                } else {
                    int e = r / 3, m = r - 3 * e;
                    C[(size_t)e * 512 + 128 + m + 3 * cc] = x0;
                    C[(size_t)e * 512 + 128 + m + 3 * (cc + 1)] = x1;
                }
            }
        }
    }
}

// ---------------- idx dtype detector ----------------
__global__ void detect_idx_kernel(const int* __restrict__ idx32) {
    if (threadIdx.x == 0) {
        int any = 0;
        for (int i = 1; i < 256; i += 2) any |= (idx32[i] != 0);
        gIdx64 = (any == 0) ? 1 : 0;
    }
}

// ---------------- SILU_CST ----------------
__global__ void cst_kernel() {
    __shared__ double red[256];
    int t = threadIdx.x;
    double acc = 0.0;
    for (int j = t; j <= 200000; j += 256) {
        double z = -12.0 + 24.0 * ((double)j / 200000.0);
        double pdf = exp(-0.5 * z * z) * 0.39894228040143267794;
        double s = z / (1.0 + exp(-z));
        double f = s * s * pdf;
        if (j == 0 || j == 200000) f *= 0.5;
        acc += f;
    }
    red[t] = acc;
    __syncthreads();
    for (int o = 128; o > 0; o >>= 1) {
        if (t < o) red[t] += red[t + o];
        __syncthreads();
    }
    if (t == 0) gCST = (float)(1.0 / sqrt(red[0] * (24.0 / 200000.0)));
}

// ---------------- SIMT GEMM ----------------
__device__ __forceinline__ unsigned long long pk2(float x) {
    unsigned long long r; unsigned u = __float_as_uint(x);
    asm("mov.b64 %0, {%1, %1};" : "=l"(r) : "r"(u));
    return r;
}
__device__ __forceinline__ void ffma2(unsigned long long& d, unsigned long long a,
                                      unsigned long long b) {
    asm("fma.rn.f32x2 %0, %1, %2, %0;" : "+l"(d) : "l"(a), "l"(b));
}
__device__ __forceinline__ float2 upk(unsigned long long v) {
    unsigned lo, hi;
    asm("mov.b64 {%0, %1}, %2;" : "=r"(lo), "=r"(hi) : "l"(v));
    return make_float2(__uint_as_float(lo), __uint_as_float(hi));
}

// epi 0: none; 1: silu fp32; 2: silu + write bf16 pair (Ch/Cl)
template <bool VECA>
__global__ void gemm_k(const float* __restrict__ A, int lda, int offA, int sA,
                       const float* __restrict__ B, int ldb,
                       float* __restrict__ C, ushort_t* __restrict__ Ch,
                       ushort_t* __restrict__ Cl, int ldc, int offC,
                       int M, int N, int K, float scale, int epi) {
    const int BM = 64, BN = 64, BK = 16;
    __shared__ unsigned long long As2[BK][BM];
    __shared__ __align__(16) float Bs[BK][BN];
    int tid = threadIdx.x;
    int tx = tid & 15, ty = tid >> 4;
    int row0 = blockIdx.x * BM, col0 = blockIdx.y * BN;
    unsigned long long acc[4][2];
#pragma unroll
    for (int i = 0; i < 4; i++) { acc[i][0] = 0ull; acc[i][1] = 0ull; }
    int la_m = tid >> 2, la_k = (tid & 3) * 4;
    int lb_k = tid >> 4, lb_n = (tid & 15) * 4;
    for (int kt = 0; kt < K; kt += BK) {
        float a0 = 0.f, a1 = 0.f, a2 = 0.f, a3 = 0.f;
        int r = row0 + la_m;
        if (r < M) {
            if (VECA) {
                if (kt + la_k < K) {
                    float4 v4 = *(const float4*)(A + (size_t)r * lda + offA + kt + la_k);
                    a0 = v4.x; a1 = v4.y; a2 = v4.z; a3 = v4.w;
                }
            } else {
                int kb = kt + la_k;
                if (kb + 0 < K) a0 = A[(size_t)r * lda + offA + (kb + 0) * sA];
                if (kb + 1 < K) a1 = A[(size_t)r * lda + offA + (kb + 1) * sA];
                if (kb + 2 < K) a2 = A[(size_t)r * lda + offA + (kb + 2) * sA];
                if (kb + 3 < K) a3 = A[(size_t)r * lda + offA + (kb + 3) * sA];
            }
        }
        As2[la_k + 0][la_m] = pk2(a0);
        As2[la_k + 1][la_m] = pk2(a1);
        As2[la_k + 2][la_m] = pk2(a2);
        As2[la_k + 3][la_m] = pk2(a3);
        int kb = kt + lb_k;
        float4 b4 = make_float4(0.f, 0.f, 0.f, 0.f);
        if (kb < K) b4 = *(const float4*)(B + (size_t)kb * ldb + col0 + lb_n);
        *(float4*)&Bs[lb_k][lb_n] = b4;
        __syncthreads();
#pragma unroll
        for (int kk = 0; kk < BK; kk++) {
            ulonglong2 b01 = *(const ulonglong2*)&Bs[kk][tx * 4];
            unsigned long long av[4];
#pragma unroll
            for (int i = 0; i < 4; i++) av[i] = As2[kk][ty * 4 + i];
#pragma unroll
            for (int i = 0; i < 4; i++) {
                ffma2(acc[i][0], av[i], b01.x);
                ffma2(acc[i][1], av[i], b01.y);
            }
        }
        __syncthreads();
    }
    float cst = (epi >= 1) ? gCST : 1.f;
#pragma unroll
    for (int i = 0; i < 4; i++) {
        int r = row0 + ty * 4 + i;
        if (r >= M) continue;
#pragma unroll
        for (int jp = 0; jp < 2; jp++) {
            float2 v = upk(acc[i][jp]);
            int c0 = col0 + tx * 4 + jp * 2;
#pragma unroll
            for (int q = 0; q < 2; q++) {
                float x = ((q == 0) ? v.x : v.y) * scale;
                if (epi >= 1) x = x / (1.f + __expf(-x)) * cst;
                if (epi == 2) {
                    ushort_t h, l; split_bf(x, h, l);
                    Ch[(size_t)r * ldc + offC + c0 + q] = h;
                    Cl[(size_t)r * ldc + offC + c0 + q] = l;
                } else {
                    C[(size_t)r * ldc + offC + c0 + q] = x;
                }
            }
        }
    }
}

// ---------------- gather + tensor product (bf16 pair I/O) ----------------------
__global__ void ew_kernel(const void* __restrict__ eidx_raw,
                          const float* __restrict__ eattr) {
    int e = blockIdx.x * 2 + (threadIdx.x >> 7);
    int u = threadIdx.x & 127;
    if (e >= NE) return;
    const int* e32 = (const int*)eidx_raw;
    const long long* e64 = (const long long*)eidx_raw;
    int snd = gIdx64 ? (int)e64[e] : e32[e];
    snd = min(max(snd, 0), NN - 1);
    float y0 = eattr[4 * e + 0];
    float y10 = eattr[4 * e + 1], y11 = eattr[4 * e + 2], y12 = eattr[4 * e + 3];
    const size_t tb = (size_t)e * 512;
    float wa = bf2f(gTH[tb + u]) + bf2f(gTL[tb + u]);
    float wb = bf2f(gTH[tb + 128 + u]) + bf2f(gTL[tb + 128 + u]);
    float wc = bf2f(gTH[tb + 256 + u]) + bf2f(gTL[tb + 256 + u]);
    float wd = bf2f(gTH[tb + 384 + u]) + bf2f(gTL[tb + 384 + u]);
    float s1 = gS[snd * 128 + u];
    const float* Vp = gV + snd * 384;
    float v0 = Vp[u], v1 = Vp[128 + u], v2 = Vp[256 + u];

    size_t sb = (size_t)e * 256;
    float o0 = wa * s1 * y0;
    float o1 = wb * (v0 * y10 + v1 * y11 + v2 * y12) * 0.57735026918962576f;
    ushort_t h, l;
    split_bf(o0, h, l); gSCH[sb + u] = h; gSCL[sb + u] = l;
    split_bf(o1, h, l); gSCH[sb + 128 + u] = h; gSCL[sb + 128 + u] = l;

    float wcs = wc * s1, wdy = wd * y0;
    size_t vb = (size_t)e * 768;
    float vals[6] = { wcs * y10, wdy * v0, wcs * y11, wdy * v1, wcs * y12, wdy * v2 };
    const int offs[6] = { 0, 128, 256, 384, 512, 640 };
#pragma unroll
    for (int j = 0; j < 6; j++) {
        split_bf(vals[j], h, l);
        gVEH[vb + offs[j] + u] = h;
        gVEL[vb + offs[j] + u] = l;
    }
}

// ---------------- launch ----------------
extern "C" void kernel_launch(void* const* d_in, const int* in_sizes, int n_in,
                              void* d_out, int out_size) {
    const float* node_feats = (const float*)d_in[0];
    const void*  edge_index = d_in[1];
    const float* edge_attrs = (const float*)d_in[2];
    const float* edge_feats = (const float*)d_in[3];
    const float* W_up_s     = (const float*)d_in[4];
    const float* W_up_v     = (const float*)d_in[5];
    const float* W1         = (const float*)d_in[6];
    const float* W2         = (const float*)d_in[7];
    const float* W3         = (const float*)d_in[8];
    const float* W4         = (const float*)d_in[9];
    const float* W_out_s    = (const float*)d_in[10];
    const float* W_out_v    = (const float*)d_in[11];
    float* out = (float*)d_out;

    float *pS, *pV;
    ushort_t *pHaH, *pHaL, *pHbH, *pHbL, *pTH, *pTL, *pSCH, *pSCL, *pVEH, *pVEL;
    cudaGetSymbolAddress((void**)&pS,  gS);
    cudaGetSymbolAddress((void**)&pV,  gV);
    cudaGetSymbolAddress((void**)&pHaH, gHaH);
    cudaGetSymbolAddress((void**)&pHaL, gHaL);
    cudaGetSymbolAddress((void**)&pHbH, gHbH);
    cudaGetSymbolAddress((void**)&pHbL, gHbL);
    cudaGetSymbolAddress((void**)&pTH,  gTH);
    cudaGetSymbolAddress((void**)&pTL,  gTL);
    cudaGetSymbolAddress((void**)&pSCH, gSCH);
    cudaGetSymbolAddress((void**)&pSCL, gSCL);
    cudaGetSymbolAddress((void**)&pVEH, gVEH);
    cudaGetSymbolAddress((void**)&pVEL, gVEL);

    const float inv_m  = 0.08838834764831845f;
    const float inv_8  = 0.35355339059327373f;
    const float inv_64 = 0.125f;
    const float inv_2m = 0.0625f;

    cst_kernel<<<1, 256>>>();
    detect_idx_kernel<<<1, 32>>>((const int*)edge_index);

    // node up-projections (SIMT fp32)
    gemm_k<true><<<dim3(157, 2), 256>>>(node_feats, 512, 0, 1, W_up_s, 128,
                                        pS, nullptr, nullptr, 128, 0,
                                        NN, 128, 128, inv_m, 0);
    for (int m = 0; m < 3; m++)
        gemm_k<false><<<dim3(157, 2), 256>>>(node_feats, 512, 128 + m, 3, W_up_v, 128,
                                             pV, nullptr, nullptr, 384, m * 128,
                                             NN, 128, 128, inv_m, 0);

    // MLP1 (K=8, SIMT) -> bf16 pair Ha
    gemm_k<true><<<dim3(3125, 1), 256>>>(edge_feats, 8, 0, 1, W1, 64,
                                         nullptr, pHaH, pHaL, 64, 0,
                                         NE, 64, 8, inv_8, 2);
    // MLP2: Ha -> Hb (bf16 pair, silu)
    mma_gemm<1, 0, 1><<<dim3(1563, 1), 256>>>(pHaH, pHaL, 64, W2, 64,
                                              nullptr, pHbH, pHbL, 64, NE, 64, inv_64);
    // MLP3: Hb -> Ha (reuse)
    mma_gemm<1, 0, 1><<<dim3(1563, 1), 256>>>(pHbH, pHbL, 64, W3, 64,
                                              nullptr, pHaH, pHaL, 64, NE, 64, inv_64);
    // W4: Ha -> T (bf16 pair)
    mma_gemm<0, 0, 1><<<dim3(1563, 8), 256>>>(pHaH, pHaL, 64, W4, 512,
                                              nullptr, pTH, pTL, 512, NE, 64, inv_64);

    // gather + tensor product
    ew_kernel<<<100000, 256>>>(edge_index, edge_attrs);

    // out_s: SCAL -> out[:, :128] (fp32)
    mma_gemm<0, 0, 0><<<dim3(1563, 2), 256>>>(pSCH, pSCL, 256, W_out_s, 128,
                                              out, nullptr, nullptr, 512, NE, 256, inv_2m);
    // out_v: VEC -> out[:, 128:512] interleaved
    mma_gemm<0, 1, 0><<<dim3(4688, 2), 256>>>(pVEH, pVEL, 256, W_out_v, 128,
                                              out, nullptr, nullptr, 0, 3 * NE, 256, inv_2m);
    (void)in_sizes; (void)n_in; (void)out_size;
}

// round 7
// speedup vs baseline: 1.0215x; 1.0215x over previous
#include <cuda_runtime.h>
#include <cuda_bf16.h>
#include <math.h>
#include <stdint.h>

#define NE 200000
#define NN 10000
typedef unsigned short ushort_t;

// ---------------- scratch ----------------
__device__ float gS[NN * 128];
__device__ float gV[NN * 384];
__device__ ushort_t gHaH[NE * 64], gHaL[NE * 64];
__device__ ushort_t gHbH[NE * 64], gHbL[NE * 64];
__device__ ushort_t gTH[(size_t)NE * 512], gTL[(size_t)NE * 512];
__device__ ushort_t gSCH[(size_t)NE * 256], gSCL[(size_t)NE * 256];
__device__ ushort_t gVEH[(size_t)NE * 768], gVEL[(size_t)NE * 768];
__device__ float gCST;
__device__ int   gIdx64;

// ---------------- helpers ----------------
__device__ __forceinline__ uint32_t smem_u32(const void* p) {
    uint32_t a;
    asm("{ .reg .u64 t; cvta.to.shared.u64 t, %1; cvt.u32.u64 %0, t; }" : "=r"(a) : "l"(p));
    return a;
}
__device__ __forceinline__ unsigned pk_bf2(float x, float y) {
    __nv_bfloat162 t = __floats2bfloat162_rn(x, y);
    return *(unsigned*)&t;
}
__device__ __forceinline__ void split_bf(float x, ushort_t& h, ushort_t& l) {
    __nv_bfloat16 hb = __float2bfloat16_rn(x);
    float r = x - __bfloat162float(hb);
    __nv_bfloat16 lb = __float2bfloat16_rn(r);
    h = *(ushort_t*)&hb; l = *(ushort_t*)&lb;
}
__device__ __forceinline__ float bf2f(ushort_t u) {
    __nv_bfloat16 b = *(__nv_bfloat16*)&u;
    return __bfloat162float(b);
}
__device__ __forceinline__ void mma_bf16(float c[4], const unsigned a[4], const unsigned b[2]) {
    asm volatile("mma.sync.aligned.m16n8k16.row.col.f32.bf16.bf16.f32 "
        "{%0,%1,%2,%3}, {%4,%5,%6,%7}, {%8,%9}, {%0,%1,%2,%3};\n"
        : "+f"(c[0]), "+f"(c[1]), "+f"(c[2]), "+f"(c[3])
        : "r"(a[0]), "r"(a[1]), "r"(a[2]), "r"(a[3]), "r"(b[0]), "r"(b[1]));
}
__device__ __forceinline__ void ldsm4(unsigned r[4], uint32_t addr) {
    asm volatile("ldmatrix.sync.aligned.m8n8.x4.shared.b16 {%0,%1,%2,%3}, [%4];"
        : "=r"(r[0]), "=r"(r[1]), "=r"(r[2]), "=r"(r[3]) : "r"(addr));
}

// ---------------- tensor GEMM, NT n-tiles per CTA ------------------------------
// C[r][c] = scale * sum_k (Ah+Al)[r][k] * B[k][c]
// Ah/Al: [M,lda] bf16. B: [K,ldb] fp32. Tile 128 x (NT*64), BK=32, 8 warps.
// OUTB: write Ch/Cl bf16 pair. CMODE1: r=3e+m -> C[e*512+128+m+3c] (fp32).
template <int NT, int SILU, int CMODE, int OUTB>
__global__ __launch_bounds__(256, 2) void mma_gemm(
        const ushort_t* __restrict__ AhG, const ushort_t* __restrict__ AlG, int lda,
        const float* __restrict__ B, int ldb,
        float* __restrict__ C, ushort_t* __restrict__ Ch, ushort_t* __restrict__ Cl,
        int ldc, int M, int K, float scale) {
    const int PK = 40;
    __shared__ __align__(16) ushort_t Ah[128][PK];
    __shared__ __align__(16) ushort_t Al[128][PK];
    __shared__ __align__(16) ushort_t Bh2[NT * 64][PK];
    __shared__ __align__(16) ushort_t Bl2[NT * 64][PK];

    int tid = threadIdx.x;
    int wid = tid >> 5, lane = tid & 31;
    int warp_m = wid & 3, warp_n = wid >> 2;
    int g = lane >> 2, tg = lane & 3;
    int row0 = blockIdx.x * 128, col0 = blockIdx.y * (NT * 64);
    int am = warp_m * 32, bn = warp_n * 32;

    int arow = (lane & 7) + ((lane >> 3) & 1) * 8;
    int acol = (lane >> 4) * 8;
    uint32_t aAddrH = smem_u32(&Ah[am + arow][acol]);
    uint32_t aAddrL = smem_u32(&Al[am + arow][acol]);
    int brow = (lane & 7) + ((lane >> 4) & 1) * 8;
    int bcol = ((lane >> 3) & 1) * 8;
    uint32_t bAddrH = smem_u32(&Bh2[bn + brow][bcol]);
    uint32_t bAddrL = smem_u32(&Bl2[bn + brow][bcol]);

    float acc[NT][2][4][4];
#pragma unroll
    for (int n2 = 0; n2 < NT; n2++)
#pragma unroll
        for (int mt = 0; mt < 2; mt++)
#pragma unroll
            for (int nt = 0; nt < 4; nt++)
#pragma unroll
                for (int j = 0; j < 4; j++) acc[n2][mt][nt][j] = 0.f;

    int sAr = tid >> 2, sAc = (tid & 3) * 8;
    int sBn = tid & 63, sBk = (tid >> 6) * 8;

    for (int kc = 0; kc < K; kc += 32) {
        // A: global -> smem (pure copy, pre-split)
#pragma unroll
        for (int i = 0; i < 2; i++) {
            int r = sAr + i * 64;
            int gr = row0 + r;
            uint4 h, l;
            if (gr < M) {
                h = *(const uint4*)(AhG + (size_t)gr * lda + kc + sAc);
                l = *(const uint4*)(AlG + (size_t)gr * lda + kc + sAc);
            } else {
                h = make_uint4(0, 0, 0, 0); l = make_uint4(0, 0, 0, 0);
            }
            *(uint4*)&Ah[r][sAc] = h;
            *(uint4*)&Al[r][sAc] = l;
        }
        // B: load fp32, split, store (B is small weights; L2 resident)
#pragma unroll
        for (int n2 = 0; n2 < NT; n2++) {
            const float* Bp = B + (size_t)(kc + sBk) * ldb + col0 + n2 * 64 + sBn;
            float bS[8];
#pragma unroll
            for (int j = 0; j < 8; j++) bS[j] = Bp[(size_t)j * ldb];
            unsigned hv[4], lv[4];
#pragma unroll
            for (int j = 0; j < 4; j++) {
                float h0 = __bfloat162float(__float2bfloat16_rn(bS[2 * j]));
                float h1 = __bfloat162float(__float2bfloat16_rn(bS[2 * j + 1]));
                hv[j] = pk_bf2(bS[2 * j], bS[2 * j + 1]);
                lv[j] = pk_bf2(bS[2 * j] - h0, bS[2 * j + 1] - h1);
            }
            *(uint4*)&Bh2[n2 * 64 + sBn][sBk] = *(uint4*)hv;
            *(uint4*)&Bl2[n2 * 64 + sBn][sBk] = *(uint4*)lv;
        }
        __syncthreads();

#pragma unroll
        for (int ks = 0; ks < 2; ks++) {
            unsigned ah[2][4], al[2][4];
#pragma unroll
            for (int mt = 0; mt < 2; mt++) {
                ldsm4(ah[mt], aAddrH + mt * (16 * PK * 2) + ks * 32);
                ldsm4(al[mt], aAddrL + mt * (16 * PK * 2) + ks * 32);
            }
#pragma unroll
            for (int n2 = 0; n2 < NT; n2++) {
                unsigned bh[2][4], bl[2][4];
#pragma unroll
                for (int np = 0; np < 2; np++) {
                    ldsm4(bh[np], bAddrH + n2 * (64 * PK * 2) + np * (16 * PK * 2) + ks * 32);
                    ldsm4(bl[np], bAddrL + n2 * (64 * PK * 2) + np * (16 * PK * 2) + ks * 32);
                }
                // 3 passes, adjacent MMAs hit different accumulators
#pragma unroll
                for (int mt = 0; mt < 2; mt++)
#pragma unroll
                    for (int nt = 0; nt < 4; nt++)
                        mma_bf16(acc[n2][mt][nt], ah[mt], &bh[nt >> 1][(nt & 1) * 2]);
#pragma unroll
                for (int mt = 0; mt < 2; mt++)
#pragma unroll
                    for (int nt = 0; nt < 4; nt++)
                        mma_bf16(acc[n2][mt][nt], ah[mt], &bl[nt >> 1][(nt & 1) * 2]);
#pragma unroll
                for (int mt = 0; mt < 2; mt++)
#pragma unroll
                    for (int nt = 0; nt < 4; nt++)
                        mma_bf16(acc[n2][mt][nt], al[mt], &bh[nt >> 1][(nt & 1) * 2]);
            }
        }
        __syncthreads();
    }

    // epilogue
    float cst = SILU ? gCST : 1.f;
#pragma unroll
    for (int n2 = 0; n2 < NT; n2++) {
#pragma unroll
        for (int mt = 0; mt < 2; mt++) {
            int rr[2]; rr[0] = row0 + am + mt * 16 + g; rr[1] = rr[0] + 8;
#pragma unroll
            for (int nt = 0; nt < 4; nt++) {
                int cc = col0 + n2 * 64 + bn + nt * 8 + tg * 2;
                float xs[4];
#pragma unroll
                for (int j = 0; j < 4; j++) xs[j] = acc[n2][mt][nt][j] * scale;
                if (SILU) {
#pragma unroll
                    for (int j = 0; j < 4; j++)
                        xs[j] = xs[j] / (1.f + __expf(-xs[j])) * cst;
                }
#pragma unroll
                for (int h = 0; h < 2; h++) {
                    int r = rr[h];
                    if (r >= M) continue;
                    float x0 = xs[2 * h], x1 = xs[2 * h + 1];
                    if (OUTB) {
                        ushort_t h0, l0, h1, l1;
                        split_bf(x0, h0, l0); split_bf(x1, h1, l1);
                        ushort2 ph; ph.x = h0; ph.y = h1;
                        ushort2 pl; pl.x = l0; pl.y = l1;
                        *(ushort2*)&Ch[(size_t)r * ldc + cc] = ph;
                        *(ushort2*)&Cl[(size_t)r * ldc + cc] = pl;
                    } else if (CMODE == 0) {
                        float2 o = make_float2(x0, x1);
                        *(float2*)&C[(size_t)r * ldc + cc] = o;
                    } else {
                        int e = r / 3, m = r - 3 * e;
                        C[(size_t)e * 512 + 128 + m + 3 * cc] = x0;
                        C[(size_t)e * 512 + 128 + m + 3 * (cc + 1)] = x1;
                    }
                }
            }
        }
    }
}

// ---------------- idx dtype detector ----------------
__global__ void detect_idx_kernel(const int* __restrict__ idx32) {
    if (threadIdx.x == 0) {
        int any = 0;
        for (int i = 1; i < 256; i += 2) any |= (idx32[i] != 0);
        gIdx64 = (any == 0) ? 1 : 0;
    }
}

// ---------------- SILU_CST ----------------
__global__ void cst_kernel() {
    __shared__ double red[256];
    int t = threadIdx.x;
    double acc = 0.0;
    for (int j = t; j <= 200000; j += 256) {
        double z = -12.0 + 24.0 * ((double)j / 200000.0);
        double pdf = exp(-0.5 * z * z) * 0.39894228040143267794;
        double s = z / (1.0 + exp(-z));
        double f = s * s * pdf;
        if (j == 0 || j == 200000) f *= 0.5;
        acc += f;
    }
    red[t] = acc;
    __syncthreads();
    for (int o = 128; o > 0; o >>= 1) {
        if (t < o) red[t] += red[t + o];
        __syncthreads();
    }
    if (t == 0) gCST = (float)(1.0 / sqrt(red[0] * (24.0 / 200000.0)));
}

// ---------------- SIMT GEMM ----------------
__device__ __forceinline__ unsigned long long pk2(float x) {
    unsigned long long r; unsigned u = __float_as_uint(x);
    asm("mov.b64 %0, {%1, %1};" : "=l"(r) : "r"(u));
    return r;
}
__device__ __forceinline__ void ffma2(unsigned long long& d, unsigned long long a,
                                      unsigned long long b) {
    asm("fma.rn.f32x2 %0, %1, %2, %0;" : "+l"(d) : "l"(a), "l"(b));
}
__device__ __forceinline__ float2 upk(unsigned long long v) {
    unsigned lo, hi;
    asm("mov.b64 {%0, %1}, %2;" : "=r"(lo), "=r"(hi) : "l"(v));
    return make_float2(__uint_as_float(lo), __uint_as_float(hi));
}

// epi 0: none; 1: silu fp32; 2: silu + write bf16 pair (Ch/Cl)
template <bool VECA>
__global__ void gemm_k(const float* __restrict__ A, int lda, int offA, int sA,
                       const float* __restrict__ B, int ldb,
                       float* __restrict__ C, ushort_t* __restrict__ Ch,
                       ushort_t* __restrict__ Cl, int ldc, int offC,
                       int M, int N, int K, float scale, int epi) {
    const int BM = 64, BN = 64, BK = 16;
    __shared__ unsigned long long As2[BK][BM];
    __shared__ __align__(16) float Bs[BK][BN];
    int tid = threadIdx.x;
    int tx = tid & 15, ty = tid >> 4;
    int row0 = blockIdx.x * BM, col0 = blockIdx.y * BN;
    unsigned long long acc[4][2];
#pragma unroll
    for (int i = 0; i < 4; i++) { acc[i][0] = 0ull; acc[i][1] = 0ull; }
    int la_m = tid >> 2, la_k = (tid & 3) * 4;
    int lb_k = tid >> 4, lb_n = (tid & 15) * 4;
    for (int kt = 0; kt < K; kt += BK) {
        float a0 = 0.f, a1 = 0.f, a2 = 0.f, a3 = 0.f;
        int r = row0 + la_m;
        if (r < M) {
            if (VECA) {
                if (kt + la_k < K) {
                    float4 v4 = *(const float4*)(A + (size_t)r * lda + offA + kt + la_k);
                    a0 = v4.x; a1 = v4.y; a2 = v4.z; a3 = v4.w;
                }
            } else {
                int kb = kt + la_k;
                if (kb + 0 < K) a0 = A[(size_t)r * lda + offA + (kb + 0) * sA];
                if (kb + 1 < K) a1 = A[(size_t)r * lda + offA + (kb + 1) * sA];
                if (kb + 2 < K) a2 = A[(size_t)r * lda + offA + (kb + 2) * sA];
                if (kb + 3 < K) a3 = A[(size_t)r * lda + offA + (kb + 3) * sA];
            }
        }
        As2[la_k + 0][la_m] = pk2(a0);
        As2[la_k + 1][la_m] = pk2(a1);
        As2[la_k + 2][la_m] = pk2(a2);
        As2[la_k + 3][la_m] = pk2(a3);
        int kb = kt + lb_k;
        float4 b4 = make_float4(0.f, 0.f, 0.f, 0.f);
        if (kb < K) b4 = *(const float4*)(B + (size_t)kb * ldb + col0 + lb_n);
        *(float4*)&Bs[lb_k][lb_n] = b4;
        __syncthreads();
#pragma unroll
        for (int kk = 0; kk < BK; kk++) {
            ulonglong2 b01 = *(const ulonglong2*)&Bs[kk][tx * 4];
            unsigned long long av[4];
#pragma unroll
            for (int i = 0; i < 4; i++) av[i] = As2[kk][ty * 4 + i];
#pragma unroll
            for (int i = 0; i < 4; i++) {
                ffma2(acc[i][0], av[i], b01.x);
                ffma2(acc[i][1], av[i], b01.y);
            }
        }
        __syncthreads();
    }
    float cst = (epi >= 1) ? gCST : 1.f;
#pragma unroll
    for (int i = 0; i < 4; i++) {
        int r = row0 + ty * 4 + i;
        if (r >= M) continue;
#pragma unroll
        for (int jp = 0; jp < 2; jp++) {
            float2 v = upk(acc[i][jp]);
            int c0 = col0 + tx * 4 + jp * 2;
#pragma unroll
            for (int q = 0; q < 2; q++) {
                float x = ((q == 0) ? v.x : v.y) * scale;
                if (epi >= 1) x = x / (1.f + __expf(-x)) * cst;
                if (epi == 2) {
                    ushort_t h, l; split_bf(x, h, l);
                    Ch[(size_t)r * ldc + offC + c0 + q] = h;
                    Cl[(size_t)r * ldc + offC + c0 + q] = l;
                } else {
                    C[(size_t)r * ldc + offC + c0 + q] = x;
                }
            }
        }
    }
}

// ---------------- gather + tensor product (bf16 pair I/O) ----------------------
__global__ void ew_kernel(const void* __restrict__ eidx_raw,
                          const float* __restrict__ eattr) {
    int e = blockIdx.x * 2 + (threadIdx.x >> 7);
    int u = threadIdx.x & 127;
    if (e >= NE) return;
    const int* e32 = (const int*)eidx_raw;
    const long long* e64 = (const long long*)eidx_raw;
    int snd = gIdx64 ? (int)e64[e] : e32[e];
    snd = min(max(snd, 0), NN - 1);
    float y0 = eattr[4 * e + 0];
    float y10 = eattr[4 * e + 1], y11 = eattr[4 * e + 2], y12 = eattr[4 * e + 3];
    const size_t tb = (size_t)e * 512;
    float wa = bf2f(gTH[tb + u]) + bf2f(gTL[tb + u]);
    float wb = bf2f(gTH[tb + 128 + u]) + bf2f(gTL[tb + 128 + u]);
    float wc = bf2f(gTH[tb + 256 + u]) + bf2f(gTL[tb + 256 + u]);
    float wd = bf2f(gTH[tb + 384 + u]) + bf2f(gTL[tb + 384 + u]);
    float s1 = gS[snd * 128 + u];
    const float* Vp = gV + snd * 384;
    float v0 = Vp[u], v1 = Vp[128 + u], v2 = Vp[256 + u];

    size_t sb = (size_t)e * 256;
    float o0 = wa * s1 * y0;
    float o1 = wb * (v0 * y10 + v1 * y11 + v2 * y12) * 0.57735026918962576f;
    ushort_t h, l;
    split_bf(o0, h, l); gSCH[sb + u] = h; gSCL[sb + u] = l;
    split_bf(o1, h, l); gSCH[sb + 128 + u] = h; gSCL[sb + 128 + u] = l;

    float wcs = wc * s1, wdy = wd * y0;
    size_t vb = (size_t)e * 768;
    float vals[6] = { wcs * y10, wdy * v0, wcs * y11, wdy * v1, wcs * y12, wdy * v2 };
    const int offs[6] = { 0, 128, 256, 384, 512, 640 };
#pragma unroll
    for (int j = 0; j < 6; j++) {
        split_bf(vals[j], h, l);
        gVEH[vb + offs[j] + u] = h;
        gVEL[vb + offs[j] + u] = l;
    }
}

// ---------------- launch ----------------
extern "C" void kernel_launch(void* const* d_in, const int* in_sizes, int n_in,
                              void* d_out, int out_size) {
    const float* node_feats = (const float*)d_in[0];
    const void*  edge_index = d_in[1];
    const float* edge_attrs = (const float*)d_in[2];
    const float* edge_feats = (const float*)d_in[3];
    const float* W_up_s     = (const float*)d_in[4];
    const float* W_up_v     = (const float*)d_in[5];
    const float* W1         = (const float*)d_in[6];
    const float* W2         = (const float*)d_in[7];
    const float* W3         = (const float*)d_in[8];
    const float* W4         = (const float*)d_in[9];
    const float* W_out_s    = (const float*)d_in[10];
    const float* W_out_v    = (const float*)d_in[11];
    float* out = (float*)d_out;

    float *pS, *pV;
    ushort_t *pHaH, *pHaL, *pHbH, *pHbL, *pTH, *pTL, *pSCH, *pSCL, *pVEH, *pVEL;
    cudaGetSymbolAddress((void**)&pS,  gS);
    cudaGetSymbolAddress((void**)&pV,  gV);
    cudaGetSymbolAddress((void**)&pHaH, gHaH);
    cudaGetSymbolAddress((void**)&pHaL, gHaL);
    cudaGetSymbolAddress((void**)&pHbH, gHbH);
    cudaGetSymbolAddress((void**)&pHbL, gHbL);
    cudaGetSymbolAddress((void**)&pTH,  gTH);
    cudaGetSymbolAddress((void**)&pTL,  gTL);
    cudaGetSymbolAddress((void**)&pSCH, gSCH);
    cudaGetSymbolAddress((void**)&pSCL, gSCL);
    cudaGetSymbolAddress((void**)&pVEH, gVEH);
    cudaGetSymbolAddress((void**)&pVEL, gVEL);

    const float inv_m  = 0.08838834764831845f;
    const float inv_8  = 0.35355339059327373f;
    const float inv_64 = 0.125f;
    const float inv_2m = 0.0625f;

    // Launch order chosen so ncu (-s 5 -c 1) captures launch #6 = W4 mma_gemm.
    cst_kernel<<<1, 256>>>();                                              // 1
    detect_idx_kernel<<<1, 32>>>((const int*)edge_index);                  // 2
    // MLP1 (K=8, SIMT) -> bf16 pair Ha
    gemm_k<true><<<dim3(3125, 1), 256>>>(edge_feats, 8, 0, 1, W1, 64,      // 3
                                         nullptr, pHaH, pHaL, 64, 0,
                                         NE, 64, 8, inv_8, 2);
    // MLP2: Ha -> Hb ; MLP3: Hb -> Ha
    mma_gemm<1, 1, 0, 1><<<dim3(1563, 1), 256>>>(pHaH, pHaL, 64, W2, 64,   // 4
                                                 nullptr, pHbH, pHbL, 64, NE, 64, inv_64);
    mma_gemm<1, 1, 0, 1><<<dim3(1563, 1), 256>>>(pHbH, pHbL, 64, W3, 64,   // 5
                                                 nullptr, pHaH, pHaL, 64, NE, 64, inv_64);
    // W4: Ha -> T   (captured by ncu)
    mma_gemm<2, 0, 0, 1><<<dim3(1563, 4), 256>>>(pHaH, pHaL, 64, W4, 512,  // 6
                                                 nullptr, pTH, pTL, 512, NE, 64, inv_64);
    // node up-projections (SIMT fp32) — needed only by ew
    gemm_k<true><<<dim3(157, 2), 256>>>(node_feats, 512, 0, 1, W_up_s, 128,
                                        pS, nullptr, nullptr, 128, 0,
                                        NN, 128, 128, inv_m, 0);
    for (int m = 0; m < 3; m++)
        gemm_k<false><<<dim3(157, 2), 256>>>(node_feats, 512, 128 + m, 3, W_up_v, 128,
                                             pV, nullptr, nullptr, 384, m * 128,
                                             NN, 128, 128, inv_m, 0);
    // gather + tensor product
    ew_kernel<<<100000, 256>>>(edge_index, edge_attrs);
    // out_s: SCAL -> out[:, :128] (fp32), N=128 in one pass
    mma_gemm<2, 0, 0, 0><<<dim3(1563, 1), 256>>>(pSCH, pSCL, 256, W_out_s, 128,
                                                 out, nullptr, nullptr, 512, NE, 256, inv_2m);
    // out_v: VEC -> out[:, 128:512] interleaved, N=128 in one pass
    mma_gemm<2, 0, 1, 0><<<dim3(4688, 1), 256>>>(pVEH, pVEL, 256, W_out_v, 128,
                                                 out, nullptr, nullptr, 0, 3 * NE, 256, inv_2m);
    (void)in_sizes; (void)n_in; (void)out_size;
}

// round 8
// speedup vs baseline: 1.0330x; 1.0112x over previous
#include <cuda_runtime.h>
#include <cuda_bf16.h>
#include <math.h>
#include <stdint.h>

#define NE 200000
#define NN 10000
typedef unsigned short ushort_t;

// ---------------- scratch ----------------
__device__ float gS[NN * 128];
__device__ float gV[NN * 384];
__device__ ushort_t gHaH[NE * 64], gHaL[NE * 64];
__device__ ushort_t gHbH[NE * 64], gHbL[NE * 64];
__device__ ushort_t gTH[(size_t)NE * 512], gTL[(size_t)NE * 512];
__device__ ushort_t gSCH[(size_t)NE * 256], gSCL[(size_t)NE * 256];
__device__ ushort_t gVEH[(size_t)NE * 768], gVEL[(size_t)NE * 768];
// pre-split transposed weights [N][K]
__device__ ushort_t gW2H[64 * 64],  gW2L[64 * 64];
__device__ ushort_t gW3H[64 * 64],  gW3L[64 * 64];
__device__ ushort_t gW4H[512 * 64], gW4L[512 * 64];
__device__ ushort_t gWsH[128 * 256], gWsL[128 * 256];
__device__ ushort_t gWvH[128 * 256], gWvL[128 * 256];
__device__ float gCST;
__device__ int   gIdx64;

// ---------------- helpers ----------------
__device__ __forceinline__ uint32_t smem_u32(const void* p) {
    uint32_t a;
    asm("{ .reg .u64 t; cvta.to.shared.u64 t, %1; cvt.u32.u64 %0, t; }" : "=r"(a) : "l"(p));
    return a;
}
__device__ __forceinline__ void split_bf(float x, ushort_t& h, ushort_t& l) {
    __nv_bfloat16 hb = __float2bfloat16_rn(x);
    float r = x - __bfloat162float(hb);
    __nv_bfloat16 lb = __float2bfloat16_rn(r);
    h = *(ushort_t*)&hb; l = *(ushort_t*)&lb;
}
__device__ __forceinline__ float bf2f(ushort_t u) {
    __nv_bfloat16 b = *(__nv_bfloat16*)&u;
    return __bfloat162float(b);
}
__device__ __forceinline__ void mma_bf16(float c[4], const unsigned a[4], const unsigned b[2]) {
    asm volatile("mma.sync.aligned.m16n8k16.row.col.f32.bf16.bf16.f32 "
        "{%0,%1,%2,%3}, {%4,%5,%6,%7}, {%8,%9}, {%0,%1,%2,%3};\n"
        : "+f"(c[0]), "+f"(c[1]), "+f"(c[2]), "+f"(c[3])
        : "r"(a[0]), "r"(a[1]), "r"(a[2]), "r"(a[3]), "r"(b[0]), "r"(b[1]));
}
__device__ __forceinline__ void ldsm4(unsigned r[4], uint32_t addr) {
    asm volatile("ldmatrix.sync.aligned.m8n8.x4.shared.b16 {%0,%1,%2,%3}, [%4];"
        : "=r"(r[0]), "=r"(r[1]), "=r"(r[2]), "=r"(r[3]) : "r"(addr));
}
__device__ __forceinline__ void cpasync16(uint32_t dst, const void* src) {
    asm volatile("cp.async.ca.shared.global [%0], [%1], 16;" :: "r"(dst), "l"(src));
}
#define CP_COMMIT() asm volatile("cp.async.commit_group;" ::: "memory")
#define CP_WAIT1()  asm volatile("cp.async.wait_group 1;" ::: "memory")
#define CP_WAIT0()  asm volatile("cp.async.wait_group 0;" ::: "memory")

// ---------------- weight prep: W[K][N] fp32 -> WT[N][K] bf16 hi/lo --------------
__global__ void prep_w(const float* __restrict__ W, int Kd, int Nd,
                       ushort_t* __restrict__ Th, ushort_t* __restrict__ Tl) {
    int idx = blockIdx.x * 256 + threadIdx.x;
    if (idx >= Kd * Nd) return;
    int n = idx / Kd, k = idx - n * Kd;
    float x = W[(size_t)k * Nd + n];
    ushort_t h, l; split_bf(x, h, l);
    Th[(size_t)n * Kd + k] = h;
    Tl[(size_t)n * Kd + k] = l;
}

// ---------------- tensor GEMM: cp.async double-buffered, all-presplit ----------
// C[r][c] = scale * sum_k (Ah+Al)[r][k] * (BTh+BTl)[c][k]
// A: [M][lda] bf16 hi/lo.  BT: [N][K] bf16 hi/lo (transposed).
// Tile 128 x (NT*64), BK=32, 256 threads (8 warps 4x2).
template <int NT, int SILU, int CMODE, int OUTB>
__global__ __launch_bounds__(256, 2) void mma_gemm(
        const ushort_t* __restrict__ AhG, const ushort_t* __restrict__ AlG, int lda,
        const ushort_t* __restrict__ BTh, const ushort_t* __restrict__ BTl,
        float* __restrict__ C, ushort_t* __restrict__ Ch, ushort_t* __restrict__ Cl,
        int ldc, int M, int K, float scale) {
    const int PK = 40;
    const int ASZ = 128 * PK * 2;           // 10240 B per A array
    const int BSZ = NT * 64 * PK * 2;       // per B array
    const int BOFF = 2 * ASZ;
    const int STAGE = 2 * ASZ + 2 * BSZ;
    extern __shared__ __align__(16) char sm[];
    uint32_t sb = smem_u32(sm);

    int tid = threadIdx.x;
    int wid = tid >> 5, lane = tid & 31;
    int warp_m = wid & 3, warp_n = wid >> 2;
    int g = lane >> 2, tg = lane & 3;
    int row0 = blockIdx.x * 128, col0 = blockIdx.y * (NT * 64);
    int am = warp_m * 32, bn = warp_n * 32;

    int arow = (lane & 7) + ((lane >> 3) & 1) * 8;
    int acol = (lane >> 4) * 8;
    uint32_t aAddrH = sb + (am + arow) * (PK * 2) + acol * 2;
    int brow = (lane & 7) + ((lane >> 4) & 1) * 8;
    int bcol = ((lane >> 3) & 1) * 8;
    uint32_t bAddrH = sb + BOFF + (bn + brow) * (PK * 2) + bcol * 2;

    float acc[NT][2][4][4];
#pragma unroll
    for (int n2 = 0; n2 < NT; n2++)
#pragma unroll
        for (int mt = 0; mt < 2; mt++)
#pragma unroll
            for (int nt = 0; nt < 4; nt++)
#pragma unroll
                for (int j = 0; j < 4; j++) acc[n2][mt][nt][j] = 0.f;

    int nc = K / 32;
    // async stage issue: A 128x32 hi/lo + B NT*64x32 hi/lo, 16B per cp
    auto issue_stage = [&](int kc, uint32_t stOff) {
#pragma unroll
        for (int i = 0; i < 2; i++) {
            int idx = tid + i * 256;
            int r = idx >> 2, c8 = (idx & 3) * 8;
            int gr = min(row0 + r, M - 1);
            uint32_t d = sb + stOff + r * (PK * 2) + c8 * 2;
            cpasync16(d, AhG + (size_t)gr * lda + kc + c8);
            cpasync16(d + ASZ, AlG + (size_t)gr * lda + kc + c8);
        }
#pragma unroll
        for (int i = 0; i < NT; i++) {
            int idx = tid + i * 256;
            int r = idx >> 2, c8 = (idx & 3) * 8;
            int gn = col0 + r;
            uint32_t d = sb + stOff + BOFF + r * (PK * 2) + c8 * 2;
            cpasync16(d, BTh + (size_t)gn * K + kc + c8);
            cpasync16(d + BSZ, BTl + (size_t)gn * K + kc + c8);
        }
    };

    issue_stage(0, 0);
    CP_COMMIT();

    for (int ci = 0; ci < nc; ci++) {
        if (ci + 1 < nc) {
            issue_stage((ci + 1) * 32, ((ci + 1) & 1) * STAGE);
            CP_COMMIT();
            CP_WAIT1();
        } else {
            CP_WAIT0();
        }
        __syncthreads();
        uint32_t st = (ci & 1) * STAGE;

#pragma unroll
        for (int ks = 0; ks < 2; ks++) {
            unsigned ah[2][4], al[2][4];
#pragma unroll
            for (int mt = 0; mt < 2; mt++) {
                ldsm4(ah[mt], aAddrH + st + mt * (16 * PK * 2) + ks * 32);
                ldsm4(al[mt], aAddrH + st + ASZ + mt * (16 * PK * 2) + ks * 32);
            }
#pragma unroll
            for (int n2 = 0; n2 < NT; n2++) {
                unsigned bh[2][4], bl[2][4];
#pragma unroll
                for (int np = 0; np < 2; np++) {
                    uint32_t ba = bAddrH + st + n2 * (64 * PK * 2) + np * (16 * PK * 2) + ks * 32;
                    ldsm4(bh[np], ba);
                    ldsm4(bl[np], ba + BSZ);
                }
#pragma unroll
                for (int mt = 0; mt < 2; mt++)
#pragma unroll
                    for (int nt = 0; nt < 4; nt++)
                        mma_bf16(acc[n2][mt][nt], ah[mt], &bh[nt >> 1][(nt & 1) * 2]);
#pragma unroll
                for (int mt = 0; mt < 2; mt++)
#pragma unroll
                    for (int nt = 0; nt < 4; nt++)
                        mma_bf16(acc[n2][mt][nt], ah[mt], &bl[nt >> 1][(nt & 1) * 2]);
#pragma unroll
                for (int mt = 0; mt < 2; mt++)
#pragma unroll
                    for (int nt = 0; nt < 4; nt++)
                        mma_bf16(acc[n2][mt][nt], al[mt], &bh[nt >> 1][(nt & 1) * 2]);
            }
        }
        __syncthreads();
    }

    // epilogue
    float cst = SILU ? gCST : 1.f;
#pragma unroll
    for (int n2 = 0; n2 < NT; n2++) {
#pragma unroll
        for (int mt = 0; mt < 2; mt++) {
            int rr[2]; rr[0] = row0 + am + mt * 16 + g; rr[1] = rr[0] + 8;
#pragma unroll
            for (int nt = 0; nt < 4; nt++) {
                int cc = col0 + n2 * 64 + bn + nt * 8 + tg * 2;
                float xs[4];
#pragma unroll
                for (int j = 0; j < 4; j++) xs[j] = acc[n2][mt][nt][j] * scale;
                if (SILU) {
#pragma unroll
                    for (int j = 0; j < 4; j++)
                        xs[j] = xs[j] / (1.f + __expf(-xs[j])) * cst;
                }
#pragma unroll
                for (int h = 0; h < 2; h++) {
                    int r = rr[h];
                    if (r >= M) continue;
                    float x0 = xs[2 * h], x1 = xs[2 * h + 1];
                    if (OUTB) {
                        ushort_t h0, l0, h1, l1;
                        split_bf(x0, h0, l0); split_bf(x1, h1, l1);
                        ushort2 ph; ph.x = h0; ph.y = h1;
                        ushort2 pl; pl.x = l0; pl.y = l1;
                        *(ushort2*)&Ch[(size_t)r * ldc + cc] = ph;
                        *(ushort2*)&Cl[(size_t)r * ldc + cc] = pl;
                    } else if (CMODE == 0) {
                        float2 o = make_float2(x0, x1);
                        *(float2*)&C[(size_t)r * ldc + cc] = o;
                    } else {
                        int e = r / 3, m = r - 3 * e;
                        C[(size_t)e * 512 + 128 + m + 3 * cc] = x0;
                        C[(size_t)e * 512 + 128 + m + 3 * (cc + 1)] = x1;
                    }
                }
            }
        }
    }
}

// ---------------- idx dtype detector ----------------
__global__ void detect_idx_kernel(const int* __restrict__ idx32) {
    if (threadIdx.x == 0) {
        int any = 0;
        for (int i = 1; i < 256; i += 2) any |= (idx32[i] != 0);
        gIdx64 = (any == 0) ? 1 : 0;
    }
}

// ---------------- SILU_CST ----------------
__global__ void cst_kernel() {
    __shared__ double red[1024];
    int t = threadIdx.x;
    double acc = 0.0;
    for (int j = t; j <= 200000; j += 1024) {
        double z = -12.0 + 24.0 * ((double)j / 200000.0);
        double pdf = exp(-0.5 * z * z) * 0.39894228040143267794;
        double s = z / (1.0 + exp(-z));
        double f = s * s * pdf;
        if (j == 0 || j == 200000) f *= 0.5;
        acc += f;
    }
    red[t] = acc;
    __syncthreads();
    for (int o = 512; o > 0; o >>= 1) {
        if (t < o) red[t] += red[t + o];
        __syncthreads();
    }
    if (t == 0) gCST = (float)(1.0 / sqrt(red[0] * (24.0 / 200000.0)));
}

// ---------------- SIMT GEMM ----------------
__device__ __forceinline__ unsigned long long pk2(float x) {
    unsigned long long r; unsigned u = __float_as_uint(x);
    asm("mov.b64 %0, {%1, %1};" : "=l"(r) : "r"(u));
    return r;
}
__device__ __forceinline__ void ffma2(unsigned long long& d, unsigned long long a,
                                      unsigned long long b) {
    asm("fma.rn.f32x2 %0, %1, %2, %0;" : "+l"(d) : "l"(a), "l"(b));
}
__device__ __forceinline__ float2 upk(unsigned long long v) {
    unsigned lo, hi;
    asm("mov.b64 {%0, %1}, %2;" : "=r"(lo), "=r"(hi) : "l"(v));
    return make_float2(__uint_as_float(lo), __uint_as_float(hi));
}

template <bool VECA>
__global__ void gemm_k(const float* __restrict__ A, int lda, int offA, int sA,
                       const float* __restrict__ B, int ldb,
                       float* __restrict__ C, ushort_t* __restrict__ Ch,
                       ushort_t* __restrict__ Cl, int ldc, int offC,
                       int M, int N, int K, float scale, int epi) {
    const int BM = 64, BN = 64, BK = 16;
    __shared__ unsigned long long As2[BK][BM];
    __shared__ __align__(16) float Bs[BK][BN];
    int tid = threadIdx.x;
    int tx = tid & 15, ty = tid >> 4;
    int row0 = blockIdx.x * BM, col0 = blockIdx.y * BN;
    unsigned long long acc[4][2];
#pragma unroll
    for (int i = 0; i < 4; i++) { acc[i][0] = 0ull; acc[i][1] = 0ull; }
    int la_m = tid >> 2, la_k = (tid & 3) * 4;
    int lb_k = tid >> 4, lb_n = (tid & 15) * 4;
    for (int kt = 0; kt < K; kt += BK) {
        float a0 = 0.f, a1 = 0.f, a2 = 0.f, a3 = 0.f;
        int r = row0 + la_m;
        if (r < M) {
            if (VECA) {
                if (kt + la_k < K) {
                    float4 v4 = *(const float4*)(A + (size_t)r * lda + offA + kt + la_k);
                    a0 = v4.x; a1 = v4.y; a2 = v4.z; a3 = v4.w;
                }
            } else {
                int kb = kt + la_k;
                if (kb + 0 < K) a0 = A[(size_t)r * lda + offA + (kb + 0) * sA];
                if (kb + 1 < K) a1 = A[(size_t)r * lda + offA + (kb + 1) * sA];
                if (kb + 2 < K) a2 = A[(size_t)r * lda + offA + (kb + 2) * sA];
                if (kb + 3 < K) a3 = A[(size_t)r * lda + offA + (kb + 3) * sA];
            }
        }
        As2[la_k + 0][la_m] = pk2(a0);
        As2[la_k + 1][la_m] = pk2(a1);
        As2[la_k + 2][la_m] = pk2(a2);
        As2[la_k + 3][la_m] = pk2(a3);
        int kb = kt + lb_k;
        float4 b4 = make_float4(0.f, 0.f, 0.f, 0.f);
        if (kb < K) b4 = *(const float4*)(B + (size_t)kb * ldb + col0 + lb_n);
        *(float4*)&Bs[lb_k][lb_n] = b4;
        __syncthreads();
#pragma unroll
        for (int kk = 0; kk < BK; kk++) {
            ulonglong2 b01 = *(const ulonglong2*)&Bs[kk][tx * 4];
            unsigned long long av[4];
#pragma unroll
            for (int i = 0; i < 4; i++) av[i] = As2[kk][ty * 4 + i];
#pragma unroll
            for (int i = 0; i < 4; i++) {
                ffma2(acc[i][0], av[i], b01.x);
                ffma2(acc[i][1], av[i], b01.y);
            }
        }
        __syncthreads();
    }
    float cst = (epi >= 1) ? gCST : 1.f;
#pragma unroll
    for (int i = 0; i < 4; i++) {
        int r = row0 + ty * 4 + i;
        if (r >= M) continue;
#pragma unroll
        for (int jp = 0; jp < 2; jp++) {
            float2 v = upk(acc[i][jp]);
            int c0 = col0 + tx * 4 + jp * 2;
#pragma unroll
            for (int q = 0; q < 2; q++) {
                float x = ((q == 0) ? v.x : v.y) * scale;
                if (epi >= 1) x = x / (1.f + __expf(-x)) * cst;
                if (epi == 2) {
                    ushort_t h, l; split_bf(x, h, l);
                    Ch[(size_t)r * ldc + offC + c0 + q] = h;
                    Cl[(size_t)r * ldc + offC + c0 + q] = l;
                } else {
                    C[(size_t)r * ldc + offC + c0 + q] = x;
                }
            }
        }
    }
}

// ---------------- gather + tensor product (bf16 pair I/O) ----------------------
__global__ void ew_kernel(const void* __restrict__ eidx_raw,
                          const float* __restrict__ eattr) {
    int e = blockIdx.x * 2 + (threadIdx.x >> 7);
    int u = threadIdx.x & 127;
    if (e >= NE) return;
    const int* e32 = (const int*)eidx_raw;
    const long long* e64 = (const long long*)eidx_raw;
    int snd = gIdx64 ? (int)e64[e] : e32[e];
    snd = min(max(snd, 0), NN - 1);
    float y0 = eattr[4 * e + 0];
    float y10 = eattr[4 * e + 1], y11 = eattr[4 * e + 2], y12 = eattr[4 * e + 3];
    const size_t tb = (size_t)e * 512;
    float wa = bf2f(gTH[tb + u]) + bf2f(gTL[tb + u]);
    float wb = bf2f(gTH[tb + 128 + u]) + bf2f(gTL[tb + 128 + u]);
    float wc = bf2f(gTH[tb + 256 + u]) + bf2f(gTL[tb + 256 + u]);
    float wd = bf2f(gTH[tb + 384 + u]) + bf2f(gTL[tb + 384 + u]);
    float s1 = gS[snd * 128 + u];
    const float* Vp = gV + snd * 384;
    float v0 = Vp[u], v1 = Vp[128 + u], v2 = Vp[256 + u];

    size_t sb = (size_t)e * 256;
    float o0 = wa * s1 * y0;
    float o1 = wb * (v0 * y10 + v1 * y11 + v2 * y12) * 0.57735026918962576f;
    ushort_t h, l;
    split_bf(o0, h, l); gSCH[sb + u] = h; gSCL[sb + u] = l;
    split_bf(o1, h, l); gSCH[sb + 128 + u] = h; gSCL[sb + 128 + u] = l;

    float wcs = wc * s1, wdy = wd * y0;
    size_t vb = (size_t)e * 768;
    float vals[6] = { wcs * y10, wdy * v0, wcs * y11, wdy * v1, wcs * y12, wdy * v2 };
    const int offs[6] = { 0, 128, 256, 384, 512, 640 };
#pragma unroll
    for (int j = 0; j < 6; j++) {
        split_bf(vals[j], h, l);
        gVEH[vb + offs[j] + u] = h;
        gVEL[vb + offs[j] + u] = l;
    }
}

// ---------------- launch ----------------
extern "C" void kernel_launch(void* const* d_in, const int* in_sizes, int n_in,
                              void* d_out, int out_size) {
    const float* node_feats = (const float*)d_in[0];
    const void*  edge_index = d_in[1];
    const float* edge_attrs = (const float*)d_in[2];
    const float* edge_feats = (const float*)d_in[3];
    const float* W_up_s     = (const float*)d_in[4];
    const float* W_up_v     = (const float*)d_in[5];
    const float* W1         = (const float*)d_in[6];
    const float* W2         = (const float*)d_in[7];
    const float* W3         = (const float*)d_in[8];
    const float* W4         = (const float*)d_in[9];
    const float* W_out_s    = (const float*)d_in[10];
    const float* W_out_v    = (const float*)d_in[11];
    float* out = (float*)d_out;

    float *pS, *pV;
    ushort_t *pHaH, *pHaL, *pHbH, *pHbL, *pTH, *pTL, *pSCH, *pSCL, *pVEH, *pVEL;
    ushort_t *pW2H, *pW2L, *pW3H, *pW3L, *pW4H, *pW4L, *pWsH, *pWsL, *pWvH, *pWvL;
    cudaGetSymbolAddress((void**)&pS,  gS);
    cudaGetSymbolAddress((void**)&pV,  gV);
    cudaGetSymbolAddress((void**)&pHaH, gHaH);
    cudaGetSymbolAddress((void**)&pHaL, gHaL);
    cudaGetSymbolAddress((void**)&pHbH, gHbH);
    cudaGetSymbolAddress((void**)&pHbL, gHbL);
    cudaGetSymbolAddress((void**)&pTH,  gTH);
    cudaGetSymbolAddress((void**)&pTL,  gTL);
    cudaGetSymbolAddress((void**)&pSCH, gSCH);
    cudaGetSymbolAddress((void**)&pSCL, gSCL);
    cudaGetSymbolAddress((void**)&pVEH, gVEH);
    cudaGetSymbolAddress((void**)&pVEL, gVEL);
    cudaGetSymbolAddress((void**)&pW2H, gW2H);
    cudaGetSymbolAddress((void**)&pW2L, gW2L);
    cudaGetSymbolAddress((void**)&pW3H, gW3H);
    cudaGetSymbolAddress((void**)&pW3L, gW3L);
    cudaGetSymbolAddress((void**)&pW4H, gW4H);
    cudaGetSymbolAddress((void**)&pW4L, gW4L);
    cudaGetSymbolAddress((void**)&pWsH, gWsH);
    cudaGetSymbolAddress((void**)&pWsL, gWsL);
    cudaGetSymbolAddress((void**)&pWvH, gWvH);
    cudaGetSymbolAddress((void**)&pWvL, gWvL);

    const float inv_m  = 0.08838834764831845f;
    const float inv_8  = 0.35355339059327373f;
    const float inv_64 = 0.125f;
    const float inv_2m = 0.0625f;

    const int SM1 = 61440;   // NT=1 double-buffered
    const int SM2 = 81920;   // NT=2
    cudaFuncSetAttribute(mma_gemm<1, 1, 0, 1>, cudaFuncAttributeMaxDynamicSharedMemorySize, SM1);
    cudaFuncSetAttribute(mma_gemm<2, 0, 0, 1>, cudaFuncAttributeMaxDynamicSharedMemorySize, SM2);
    cudaFuncSetAttribute(mma_gemm<2, 0, 0, 0>, cudaFuncAttributeMaxDynamicSharedMemorySize, SM2);
    cudaFuncSetAttribute(mma_gemm<2, 0, 1, 0>, cudaFuncAttributeMaxDynamicSharedMemorySize, SM2);

    cst_kernel<<<1, 1024>>>();                                             // 1
    detect_idx_kernel<<<1, 32>>>((const int*)edge_index);                  // 2
    // MLP1 (K=8, SIMT) -> bf16 pair Ha
    gemm_k<true><<<dim3(3125, 1), 256>>>(edge_feats, 8, 0, 1, W1, 64,      // 3
                                         nullptr, pHaH, pHaL, 64, 0,
                                         NE, 64, 8, inv_8, 2);
    prep_w<<<(64 * 64 + 255) / 256, 256>>>(W2, 64, 64, pW2H, pW2L);        // 4
    prep_w<<<(64 * 64 + 255) / 256, 256>>>(W3, 64, 64, pW3H, pW3L);        // 5
    // MLP2: Ha -> Hb   (captured by ncu: launch #6)
    mma_gemm<1, 1, 0, 1><<<dim3(1563, 1), 256, SM1>>>(pHaH, pHaL, 64, pW2H, pW2L,
                                                      nullptr, pHbH, pHbL, 64, NE, 64, inv_64);
    // MLP3: Hb -> Ha
    mma_gemm<1, 1, 0, 1><<<dim3(1563, 1), 256, SM1>>>(pHbH, pHbL, 64, pW3H, pW3L,
                                                      nullptr, pHaH, pHaL, 64, NE, 64, inv_64);
    prep_w<<<(512 * 64 + 255) / 256, 256>>>(W4, 64, 512, pW4H, pW4L);
    // W4: Ha -> T
    mma_gemm<2, 0, 0, 1><<<dim3(1563, 4), 256, SM2>>>(pHaH, pHaL, 64, pW4H, pW4L,
                                                      nullptr, pTH, pTL, 512, NE, 64, inv_64);
    // node up-projections (SIMT fp32)
    gemm_k<true><<<dim3(157, 2), 256>>>(node_feats, 512, 0, 1, W_up_s, 128,
                                        pS, nullptr, nullptr, 128, 0,
                                        NN, 128, 128, inv_m, 0);
    for (int m = 0; m < 3; m++)
        gemm_k<false><<<dim3(157, 2), 256>>>(node_feats, 512, 128 + m, 3, W_up_v, 128,
                                             pV, nullptr, nullptr, 384, m * 128,
                                             NN, 128, 128, inv_m, 0);
    // gather + tensor product
    ew_kernel<<<100000, 256>>>(edge_index, edge_attrs);
    prep_w<<<(128 * 256 + 255) / 256, 256>>>(W_out_s, 256, 128, pWsH, pWsL);
    prep_w<<<(128 * 256 + 255) / 256, 256>>>(W_out_v, 256, 128, pWvH, pWvL);
    // out_s: SCAL -> out[:, :128]
    mma_gemm<2, 0, 0, 0><<<dim3(1563, 1), 256, SM2>>>(pSCH, pSCL, 256, pWsH, pWsL,
                                                      out, nullptr, nullptr, 512, NE, 256, inv_2m);
    // out_v: VEC -> out[:, 128:512] interleaved
    mma_gemm<2, 0, 1, 0><<<dim3(4688, 1), 256, SM2>>>(pVEH, pVEL, 256, pWvH, pWvL,
                                                      out, nullptr, nullptr, 0, 3 * NE, 256, inv_2m);
    (void)in_sizes; (void)n_in; (void)out_size;
}

// round 9
// speedup vs baseline: 3.2426x; 3.1391x over previous
#include <cuda_runtime.h>
#include <cuda_bf16.h>
#include <math.h>
#include <stdint.h>

#define NE 200000
#define NN 10000
typedef unsigned short ushort_t;

// ---------------- scratch ----------------
__device__ float gS[NN * 128];
__device__ float gV[NN * 384];                       // [n][m][u]
__device__ ushort_t gHaH[NE * 64], gHaL[NE * 64];
__device__ ushort_t gHbH[NE * 64], gHbL[NE * 64];
__device__ ushort_t gTH[(size_t)NE * 512], gTL[(size_t)NE * 512];
// pre-split transposed weights [N][K]
__device__ ushort_t gW2H[64 * 64],  gW2L[64 * 64];
__device__ ushort_t gW3H[64 * 64],  gW3L[64 * 64];
__device__ ushort_t gW4H[512 * 64], gW4L[512 * 64];
__device__ ushort_t gWsH[128 * 256], gWsL[128 * 256];
__device__ ushort_t gWvH[128 * 256], gWvL[128 * 256];
__device__ int gIdx64;

// ---------------- helpers ----------------
__device__ __forceinline__ uint32_t smem_u32(const void* p) {
    uint32_t a;
    asm("{ .reg .u64 t; cvta.to.shared.u64 t, %1; cvt.u32.u64 %0, t; }" : "=r"(a) : "l"(p));
    return a;
}
__device__ __forceinline__ void split_bf(float x, ushort_t& h, ushort_t& l) {
    __nv_bfloat16 hb = __float2bfloat16_rn(x);
    float r = x - __bfloat162float(hb);
    __nv_bfloat16 lb = __float2bfloat16_rn(r);
    h = *(ushort_t*)&hb; l = *(ushort_t*)&lb;
}
__device__ __forceinline__ float bf2f(ushort_t u) {
    __nv_bfloat16 b = *(__nv_bfloat16*)&u;
    return __bfloat162float(b);
}
__device__ __forceinline__ void mma_bf16(float c[4], const unsigned a[4], const unsigned b[2]) {
    asm volatile("mma.sync.aligned.m16n8k16.row.col.f32.bf16.bf16.f32 "
        "{%0,%1,%2,%3}, {%4,%5,%6,%7}, {%8,%9}, {%0,%1,%2,%3};\n"
        : "+f"(c[0]), "+f"(c[1]), "+f"(c[2]), "+f"(c[3])
        : "r"(a[0]), "r"(a[1]), "r"(a[2]), "r"(a[3]), "r"(b[0]), "r"(b[1]));
}
__device__ __forceinline__ void ldsm4(unsigned r[4], uint32_t addr) {
    asm volatile("ldmatrix.sync.aligned.m8n8.x4.shared.b16 {%0,%1,%2,%3}, [%4];"
        : "=r"(r[0]), "=r"(r[1]), "=r"(r[2]), "=r"(r[3]) : "r"(addr));
}
__device__ __forceinline__ void cpasync16(uint32_t dst, const void* src) {
    asm volatile("cp.async.ca.shared.global [%0], [%1], 16;" :: "r"(dst), "l"(src));
}
#define CP_COMMIT() asm volatile("cp.async.commit_group;" ::: "memory")
#define CP_WAIT1()  asm volatile("cp.async.wait_group 1;" ::: "memory")
#define CP_WAIT0()  asm volatile("cp.async.wait_group 0;" ::: "memory")

// ---------------- weight prep: W[K][N] fp32 -> WT[N][K] bf16 hi/lo --------------
__global__ void prep_w(const float* __restrict__ W, int Kd, int Nd,
                       ushort_t* __restrict__ Th, ushort_t* __restrict__ Tl) {
    int idx = blockIdx.x * 256 + threadIdx.x;
    if (idx >= Kd * Nd) return;
    int n = idx / Kd, k = idx - n * Kd;
    float x = W[(size_t)k * Nd + n];
    ushort_t h, l; split_bf(x, h, l);
    Th[(size_t)n * Kd + k] = h;
    Tl[(size_t)n * Kd + k] = l;
}

// ---------------- idx dtype detector ----------------
__global__ void detect_idx_kernel(const int* __restrict__ idx32) {
    if (threadIdx.x == 0) {
        int any = 0;
        for (int i = 1; i < 256; i += 2) any |= (idx32[i] != 0);
        gIdx64 = (any == 0) ? 1 : 0;
    }
}

// ---------------- generic tc GEMM (MLP2/3, W4): cp.async double-buffered --------
template <int NT, int SILU, int OUTB>
__global__ __launch_bounds__(256, 2) void mma_gemm(
        const ushort_t* __restrict__ AhG, const ushort_t* __restrict__ AlG, int lda,
        const ushort_t* __restrict__ BTh, const ushort_t* __restrict__ BTl,
        ushort_t* __restrict__ Ch, ushort_t* __restrict__ Cl,
        int ldc, int M, int K, float scale, float cstv) {
    const int PK = 40;
    const int ASZ = 128 * PK * 2;
    const int BSZ = NT * 64 * PK * 2;
    const int BOFF = 2 * ASZ;
    const int STAGE = 2 * ASZ + 2 * BSZ;
    extern __shared__ __align__(16) char sm[];
    uint32_t sb = smem_u32(sm);

    int tid = threadIdx.x;
    int wid = tid >> 5, lane = tid & 31;
    int warp_m = wid & 3, warp_n = wid >> 2;
    int g = lane >> 2, tg = lane & 3;
    int row0 = blockIdx.x * 128, col0 = blockIdx.y * (NT * 64);
    int am = warp_m * 32, bn = warp_n * 32;

    int arow = (lane & 7) + ((lane >> 3) & 1) * 8;
    int acol = (lane >> 4) * 8;
    uint32_t aAddr = sb + (am + arow) * (PK * 2) + acol * 2;
    int brow = (lane & 7) + ((lane >> 4) & 1) * 8;
    int bcol = ((lane >> 3) & 1) * 8;
    uint32_t bAddr = sb + BOFF + (bn + brow) * (PK * 2) + bcol * 2;

    float acc[NT][2][4][4];
#pragma unroll
    for (int n2 = 0; n2 < NT; n2++)
#pragma unroll
        for (int mt = 0; mt < 2; mt++)
#pragma unroll
            for (int nt = 0; nt < 4; nt++)
#pragma unroll
                for (int j = 0; j < 4; j++) acc[n2][mt][nt][j] = 0.f;

    int nc = K / 32;
    auto issue_stage = [&](int kc, uint32_t stOff) {
#pragma unroll
        for (int i = 0; i < 2; i++) {
            int idx = tid + i * 256;
            int r = idx >> 2, c8 = (idx & 3) * 8;
            int gr = min(row0 + r, M - 1);
            uint32_t d = sb + stOff + r * (PK * 2) + c8 * 2;
            cpasync16(d, AhG + (size_t)gr * lda + kc + c8);
            cpasync16(d + ASZ, AlG + (size_t)gr * lda + kc + c8);
        }
#pragma unroll
        for (int i = 0; i < NT; i++) {
            int idx = tid + i * 256;
            int r = idx >> 2, c8 = (idx & 3) * 8;
            int gn = col0 + r;
            uint32_t d = sb + stOff + BOFF + r * (PK * 2) + c8 * 2;
            cpasync16(d, BTh + (size_t)gn * K + kc + c8);
            cpasync16(d + BSZ, BTl + (size_t)gn * K + kc + c8);
        }
    };

    issue_stage(0, 0);
    CP_COMMIT();

    for (int ci = 0; ci < nc; ci++) {
        if (ci + 1 < nc) {
            issue_stage((ci + 1) * 32, ((ci + 1) & 1) * STAGE);
            CP_COMMIT();
            CP_WAIT1();
        } else {
            CP_WAIT0();
        }
        __syncthreads();
        uint32_t st = (ci & 1) * STAGE;

#pragma unroll
        for (int ks = 0; ks < 2; ks++) {
            unsigned ah[2][4], al[2][4];
#pragma unroll
            for (int mt = 0; mt < 2; mt++) {
                ldsm4(ah[mt], aAddr + st + mt * (16 * PK * 2) + ks * 32);
                ldsm4(al[mt], aAddr + st + ASZ + mt * (16 * PK * 2) + ks * 32);
            }
#pragma unroll
            for (int n2 = 0; n2 < NT; n2++) {
                unsigned bh[2][4], bl[2][4];
#pragma unroll
                for (int np = 0; np < 2; np++) {
                    uint32_t ba = bAddr + st + n2 * (64 * PK * 2) + np * (16 * PK * 2) + ks * 32;
                    ldsm4(bh[np], ba);
                    ldsm4(bl[np], ba + BSZ);
                }
#pragma unroll
                for (int mt = 0; mt < 2; mt++)
#pragma unroll
                    for (int nt = 0; nt < 4; nt++)
                        mma_bf16(acc[n2][mt][nt], ah[mt], &bh[nt >> 1][(nt & 1) * 2]);
#pragma unroll
                for (int mt = 0; mt < 2; mt++)
#pragma unroll
                    for (int nt = 0; nt < 4; nt++)
                        mma_bf16(acc[n2][mt][nt], ah[mt], &bl[nt >> 1][(nt & 1) * 2]);
#pragma unroll
                for (int mt = 0; mt < 2; mt++)
#pragma unroll
                    for (int nt = 0; nt < 4; nt++)
                        mma_bf16(acc[n2][mt][nt], al[mt], &bh[nt >> 1][(nt & 1) * 2]);
            }
        }
        __syncthreads();
    }

#pragma unroll
    for (int n2 = 0; n2 < NT; n2++) {
#pragma unroll
        for (int mt = 0; mt < 2; mt++) {
            int rr[2]; rr[0] = row0 + am + mt * 16 + g; rr[1] = rr[0] + 8;
#pragma unroll
            for (int nt = 0; nt < 4; nt++) {
                int cc = col0 + n2 * 64 + bn + nt * 8 + tg * 2;
                float xs[4];
#pragma unroll
                for (int j = 0; j < 4; j++) xs[j] = acc[n2][mt][nt][j] * scale;
                if (SILU) {
#pragma unroll
                    for (int j = 0; j < 4; j++)
                        xs[j] = xs[j] / (1.f + __expf(-xs[j])) * cstv;
                }
#pragma unroll
                for (int h = 0; h < 2; h++) {
                    int r = rr[h];
                    if (r >= M) continue;
                    ushort_t h0, l0, h1, l1;
                    split_bf(xs[2 * h], h0, l0); split_bf(xs[2 * h + 1], h1, l1);
                    ushort2 ph; ph.x = h0; ph.y = h1;
                    ushort2 pl; pl.x = l0; pl.y = l1;
                    *(ushort2*)&Ch[(size_t)r * ldc + cc] = ph;
                    *(ushort2*)&Cl[(size_t)r * ldc + cc] = pl;
                }
            }
        }
    }
    (void)OUTB;
}

// ---------------- fused out_s: A staged from T + gather, C = out[:, :128] -------
__global__ __launch_bounds__(256, 2) void mma_outs(
        const void* __restrict__ eidx, const float* __restrict__ eattr,
        float* __restrict__ C) {
    const int PK = 40;
    __shared__ __align__(16) ushort_t Ah[128][PK], Al[128][PK];
    __shared__ __align__(16) ushort_t Bh[128][PK], Bl[128][PK];
    __shared__ int sSnd[128];
    __shared__ float4 sY[128];

    int tid = threadIdx.x;
    int wid = tid >> 5, lane = tid & 31;
    int warp_m = wid & 3, warp_n = wid >> 2;
    int g = lane >> 2, tg = lane & 3;
    int row0 = blockIdx.x * 128;
    int am = warp_m * 32, bn = warp_n * 32;

    if (tid < 128) {
        int e = min(row0 + tid, NE - 1);
        int snd = gIdx64 ? (int)((const long long*)eidx)[e] : ((const int*)eidx)[e];
        sSnd[tid] = min(max(snd, 0), NN - 1);
        sY[tid] = *(const float4*)(eattr + 4 * e);
    }
    __syncthreads();

    int arow = (lane & 7) + ((lane >> 3) & 1) * 8;
    int acol = (lane >> 4) * 8;
    uint32_t aH = smem_u32(&Ah[am + arow][acol]);
    uint32_t aL = smem_u32(&Al[am + arow][acol]);
    int brow = (lane & 7) + ((lane >> 4) & 1) * 8;
    int bcol = ((lane >> 3) & 1) * 8;
    uint32_t bH = smem_u32(&Bh[bn + brow][bcol]);
    uint32_t bL = smem_u32(&Bl[bn + brow][bcol]);

    float acc[2][2][4][4];
#pragma unroll
    for (int n2 = 0; n2 < 2; n2++)
#pragma unroll
        for (int mt = 0; mt < 2; mt++)
#pragma unroll
            for (int nt = 0; nt < 4; nt++)
#pragma unroll
                for (int j = 0; j < 4; j++) acc[n2][mt][nt][j] = 0.f;

    int r = tid >> 1, half = tid & 1;
    int e = min(row0 + r, NE - 1);
    int snd = sSnd[r];
    float4 y = sY[r];

    for (int kc = 0; kc < 8; kc++) {
        int u0 = (kc & 3) * 32 + half * 16;
        size_t tb = (size_t)e * 512 + (kc < 4 ? 0 : 128) + u0;
        __align__(16) ushort_t th[16], tl[16];
        *(uint4*)&th[0] = *(const uint4*)(gTH + tb);
        *(uint4*)&th[8] = *(const uint4*)(gTH + tb + 8);
        *(uint4*)&tl[0] = *(const uint4*)(gTL + tb);
        *(uint4*)&tl[8] = *(const uint4*)(gTL + tb + 8);
        float av[16];
        if (kc < 4) {
            const float* sp = gS + (size_t)snd * 128 + u0;
#pragma unroll
            for (int j = 0; j < 16; j++)
                av[j] = (bf2f(th[j]) + bf2f(tl[j])) * sp[j] * y.x;
        } else {
            const float* vp = gV + (size_t)snd * 384 + u0;
#pragma unroll
            for (int j = 0; j < 16; j++) {
                float dv = vp[j] * y.y + vp[128 + j] * y.z + vp[256 + j] * y.w;
                av[j] = (bf2f(th[j]) + bf2f(tl[j])) * dv * 0.57735026918962576f;
            }
        }
        __align__(16) ushort_t hh[16], ll[16];
#pragma unroll
        for (int j = 0; j < 16; j++) split_bf(av[j], hh[j], ll[j]);
        *(uint4*)&Ah[r][half * 16] = *(uint4*)&hh[0];
        *(uint4*)&Ah[r][half * 16 + 8] = *(uint4*)&hh[8];
        *(uint4*)&Al[r][half * 16] = *(uint4*)&ll[0];
        *(uint4*)&Al[r][half * 16 + 8] = *(uint4*)&ll[8];
        {
            const ushort_t* ph = gWsH + (size_t)r * 256 + kc * 32 + half * 16;
            const ushort_t* pl = gWsL + (size_t)r * 256 + kc * 32 + half * 16;
            *(uint4*)&Bh[r][half * 16] = *(const uint4*)ph;
            *(uint4*)&Bh[r][half * 16 + 8] = *(const uint4*)(ph + 8);
            *(uint4*)&Bl[r][half * 16] = *(const uint4*)pl;
            *(uint4*)&Bl[r][half * 16 + 8] = *(const uint4*)(pl + 8);
        }
        __syncthreads();

#pragma unroll
        for (int ks = 0; ks < 2; ks++) {
            unsigned ah[2][4], al[2][4];
#pragma unroll
            for (int mt = 0; mt < 2; mt++) {
                ldsm4(ah[mt], aH + mt * (16 * PK * 2) + ks * 32);
                ldsm4(al[mt], aL + mt * (16 * PK * 2) + ks * 32);
            }
#pragma unroll
            for (int n2 = 0; n2 < 2; n2++) {
                unsigned bh[2][4], bl[2][4];
#pragma unroll
                for (int np = 0; np < 2; np++) {
                    ldsm4(bh[np], bH + n2 * (64 * PK * 2) + np * (16 * PK * 2) + ks * 32);
                    ldsm4(bl[np], bL + n2 * (64 * PK * 2) + np * (16 * PK * 2) + ks * 32);
                }
#pragma unroll
                for (int mt = 0; mt < 2; mt++)
#pragma unroll
                    for (int nt = 0; nt < 4; nt++)
                        mma_bf16(acc[n2][mt][nt], ah[mt], &bh[nt >> 1][(nt & 1) * 2]);
#pragma unroll
                for (int mt = 0; mt < 2; mt++)
#pragma unroll
                    for (int nt = 0; nt < 4; nt++)
                        mma_bf16(acc[n2][mt][nt], ah[mt], &bl[nt >> 1][(nt & 1) * 2]);
#pragma unroll
                for (int mt = 0; mt < 2; mt++)
#pragma unroll
                    for (int nt = 0; nt < 4; nt++)
                        mma_bf16(acc[n2][mt][nt], al[mt], &bh[nt >> 1][(nt & 1) * 2]);
            }
        }
        __syncthreads();
    }

#pragma unroll
    for (int n2 = 0; n2 < 2; n2++) {
#pragma unroll
        for (int mt = 0; mt < 2; mt++) {
            int rr[2]; rr[0] = row0 + am + mt * 16 + g; rr[1] = rr[0] + 8;
#pragma unroll
            for (int nt = 0; nt < 4; nt++) {
                int cc = n2 * 64 + bn + nt * 8 + tg * 2;
#pragma unroll
                for (int h = 0; h < 2; h++) {
                    int gr = rr[h];
                    if (gr >= NE) continue;
                    float x0 = acc[n2][mt][nt][2 * h] * 0.0625f;
                    float x1 = acc[n2][mt][nt][2 * h + 1] * 0.0625f;
                    *(float2*)&C[(size_t)gr * 512 + cc] = make_float2(x0, x1);
                }
            }
        }
    }
}

// ---------------- fused out_v: rows (e,m)=3e+m, interleaved epilogue ------------
__global__ __launch_bounds__(256, 2) void mma_outv(
        const void* __restrict__ eidx, const float* __restrict__ eattr,
        float* __restrict__ C) {
    const int PK = 40;
    __shared__ __align__(16) ushort_t Ah[128][PK], Al[128][PK];
    __shared__ __align__(16) ushort_t Bh[128][PK], Bl[128][PK];
    __shared__ int sSnd[128];
    __shared__ float sY0[128], sYm[128];

    int tid = threadIdx.x;
    int wid = tid >> 5, lane = tid & 31;
    int warp_m = wid & 3, warp_n = wid >> 2;
    int g = lane >> 2, tg = lane & 3;
    int row0 = blockIdx.x * 128;
    int am = warp_m * 32, bn = warp_n * 32;

    if (tid < 128) {
        int gr = min(row0 + tid, 3 * NE - 1);
        int e = gr / 3, m = gr - 3 * e;
        int snd = gIdx64 ? (int)((const long long*)eidx)[e] : ((const int*)eidx)[e];
        sSnd[tid] = min(max(snd, 0), NN - 1);
        float4 y = *(const float4*)(eattr + 4 * e);
        sY0[tid] = y.x;
        sYm[tid] = (m == 0) ? y.y : ((m == 1) ? y.z : y.w);
    }
    __syncthreads();

    int arow = (lane & 7) + ((lane >> 3) & 1) * 8;
    int acol = (lane >> 4) * 8;
    uint32_t aH = smem_u32(&Ah[am + arow][acol]);
    uint32_t aL = smem_u32(&Al[am + arow][acol]);
    int brow = (lane & 7) + ((lane >> 4) & 1) * 8;
    int bcol = ((lane >> 3) & 1) * 8;
    uint32_t bH = smem_u32(&Bh[bn + brow][bcol]);
    uint32_t bL = smem_u32(&Bl[bn + brow][bcol]);

    float acc[2][2][4][4];
#pragma unroll
    for (int n2 = 0; n2 < 2; n2++)
#pragma unroll
        for (int mt = 0; mt < 2; mt++)
#pragma unroll
            for (int nt = 0; nt < 4; nt++)
#pragma unroll
                for (int j = 0; j < 4; j++) acc[n2][mt][nt][j] = 0.f;

    int r = tid >> 1, half = tid & 1;
    int grr = min(row0 + r, 3 * NE - 1);
    int e = grr / 3, m = grr - 3 * e;
    int snd = sSnd[r];
    float y0 = sY0[r], ym = sYm[r];

    for (int kc = 0; kc < 8; kc++) {
        int u0 = (kc & 3) * 32 + half * 16;
        size_t tb = (size_t)e * 512 + (kc < 4 ? 256 : 384) + u0;
        __align__(16) ushort_t th[16], tl[16];
        *(uint4*)&th[0] = *(const uint4*)(gTH + tb);
        *(uint4*)&th[8] = *(const uint4*)(gTH + tb + 8);
        *(uint4*)&tl[0] = *(const uint4*)(gTL + tb);
        *(uint4*)&tl[8] = *(const uint4*)(gTL + tb + 8);
        float av[16];
        if (kc < 4) {
            const float* sp = gS + (size_t)snd * 128 + u0;
#pragma unroll
            for (int j = 0; j < 16; j++)
                av[j] = (bf2f(th[j]) + bf2f(tl[j])) * sp[j] * ym;
        } else {
            const float* vp = gV + (size_t)snd * 384 + m * 128 + u0;
#pragma unroll
            for (int j = 0; j < 16; j++)
                av[j] = (bf2f(th[j]) + bf2f(tl[j])) * y0 * vp[j];
        }
        __align__(16) ushort_t hh[16], ll[16];
#pragma unroll
        for (int j = 0; j < 16; j++) split_bf(av[j], hh[j], ll[j]);
        *(uint4*)&Ah[r][half * 16] = *(uint4*)&hh[0];
        *(uint4*)&Ah[r][half * 16 + 8] = *(uint4*)&hh[8];
        *(uint4*)&Al[r][half * 16] = *(uint4*)&ll[0];
        *(uint4*)&Al[r][half * 16 + 8] = *(uint4*)&ll[8];
        {
            const ushort_t* ph = gWvH + (size_t)r * 256 + kc * 32 + half * 16;
            const ushort_t* pl = gWvL + (size_t)r * 256 + kc * 32 + half * 16;
            *(uint4*)&Bh[r][half * 16] = *(const uint4*)ph;
            *(uint4*)&Bh[r][half * 16 + 8] = *(const uint4*)(ph + 8);
            *(uint4*)&Bl[r][half * 16] = *(const uint4*)pl;
            *(uint4*)&Bl[r][half * 16 + 8] = *(const uint4*)(pl + 8);
        }
        __syncthreads();

#pragma unroll
        for (int ks = 0; ks < 2; ks++) {
            unsigned ah[2][4], al[2][4];
#pragma unroll
            for (int mt = 0; mt < 2; mt++) {
                ldsm4(ah[mt], aH + mt * (16 * PK * 2) + ks * 32);
                ldsm4(al[mt], aL + mt * (16 * PK * 2) + ks * 32);
            }
#pragma unroll
            for (int n2 = 0; n2 < 2; n2++) {
                unsigned bh[2][4], bl[2][4];
#pragma unroll
                for (int np = 0; np < 2; np++) {
                    ldsm4(bh[np], bH + n2 * (64 * PK * 2) + np * (16 * PK * 2) + ks * 32);
                    ldsm4(bl[np], bL + n2 * (64 * PK * 2) + np * (16 * PK * 2) + ks * 32);
                }
#pragma unroll
                for (int mt = 0; mt < 2; mt++)
#pragma unroll
                    for (int nt = 0; nt < 4; nt++)
                        mma_bf16(acc[n2][mt][nt], ah[mt], &bh[nt >> 1][(nt & 1) * 2]);
#pragma unroll
                for (int mt = 0; mt < 2; mt++)
#pragma unroll
                    for (int nt = 0; nt < 4; nt++)
                        mma_bf16(acc[n2][mt][nt], ah[mt], &bl[nt >> 1][(nt & 1) * 2]);
#pragma unroll
                for (int mt = 0; mt < 2; mt++)
#pragma unroll
                    for (int nt = 0; nt < 4; nt++)
                        mma_bf16(acc[n2][mt][nt], al[mt], &bh[nt >> 1][(nt & 1) * 2]);
            }
        }
        __syncthreads();
    }

#pragma unroll
    for (int n2 = 0; n2 < 2; n2++) {
#pragma unroll
        for (int mt = 0; mt < 2; mt++) {
            int rr[2]; rr[0] = row0 + am + mt * 16 + g; rr[1] = rr[0] + 8;
#pragma unroll
            for (int nt = 0; nt < 4; nt++) {
                int cc = n2 * 64 + bn + nt * 8 + tg * 2;
#pragma unroll
                for (int h = 0; h < 2; h++) {
                    int gr = rr[h];
                    if (gr >= 3 * NE) continue;
                    int ee = gr / 3, mm = gr - 3 * ee;
                    float x0 = acc[n2][mt][nt][2 * h] * 0.0625f;
                    float x1 = acc[n2][mt][nt][2 * h + 1] * 0.0625f;
                    C[(size_t)ee * 512 + 128 + mm + 3 * cc] = x0;
                    C[(size_t)ee * 512 + 128 + mm + 3 * (cc + 1)] = x1;
                }
            }
        }
    }
}

// ---------------- SIMT GEMM (node up-proj + MLP1) ----------------
__device__ __forceinline__ unsigned long long pk2(float x) {
    unsigned long long r; unsigned u = __float_as_uint(x);
    asm("mov.b64 %0, {%1, %1};" : "=l"(r) : "r"(u));
    return r;
}
__device__ __forceinline__ void ffma2(unsigned long long& d, unsigned long long a,
                                      unsigned long long b) {
    asm("fma.rn.f32x2 %0, %1, %2, %0;" : "+l"(d) : "l"(a), "l"(b));
}
__device__ __forceinline__ float2 upk(unsigned long long v) {
    unsigned lo, hi;
    asm("mov.b64 {%0, %1}, %2;" : "=r"(lo), "=r"(hi) : "l"(v));
    return make_float2(__uint_as_float(lo), __uint_as_float(hi));
}

// epi 0: fp32 out; 2: silu + write bf16 pair
template <bool VECA>
__global__ void gemm_k(const float* __restrict__ A, int lda, int offA, int sA,
                       const float* __restrict__ B, int ldb,
                       float* __restrict__ C, ushort_t* __restrict__ Ch,
                       ushort_t* __restrict__ Cl, int ldc, int offC,
                       int M, int N, int K, float scale, int epi, float cstv) {
    const int BM = 64, BN = 64, BK = 16;
    __shared__ unsigned long long As2[BK][BM];
    __shared__ __align__(16) float Bs[BK][BN];
    int tid = threadIdx.x;
    int tx = tid & 15, ty = tid >> 4;
    int row0 = blockIdx.x * BM, col0 = blockIdx.y * BN;
    unsigned long long acc[4][2];
#pragma unroll
    for (int i = 0; i < 4; i++) { acc[i][0] = 0ull; acc[i][1] = 0ull; }
    int la_m = tid >> 2, la_k = (tid & 3) * 4;
    int lb_k = tid >> 4, lb_n = (tid & 15) * 4;
    for (int kt = 0; kt < K; kt += BK) {
        float a0 = 0.f, a1 = 0.f, a2 = 0.f, a3 = 0.f;
        int r = row0 + la_m;
        if (r < M) {
            if (VECA) {
                if (kt + la_k < K) {
                    float4 v4 = *(const float4*)(A + (size_t)r * lda + offA + kt + la_k);
                    a0 = v4.x; a1 = v4.y; a2 = v4.z; a3 = v4.w;
                }
            } else {
                int kb = kt + la_k;
                if (kb + 0 < K) a0 = A[(size_t)r * lda + offA + (kb + 0) * sA];
                if (kb + 1 < K) a1 = A[(size_t)r * lda + offA + (kb + 1) * sA];
                if (kb + 2 < K) a2 = A[(size_t)r * lda + offA + (kb + 2) * sA];
                if (kb + 3 < K) a3 = A[(size_t)r * lda + offA + (kb + 3) * sA];
            }
        }
        As2[la_k + 0][la_m] = pk2(a0);
        As2[la_k + 1][la_m] = pk2(a1);
        As2[la_k + 2][la_m] = pk2(a2);
        As2[la_k + 3][la_m] = pk2(a3);
        int kb = kt + lb_k;
        float4 b4 = make_float4(0.f, 0.f, 0.f, 0.f);
        if (kb < K) b4 = *(const float4*)(B + (size_t)kb * ldb + col0 + lb_n);
        *(float4*)&Bs[lb_k][lb_n] = b4;
        __syncthreads();
#pragma unroll
        for (int kk = 0; kk < BK; kk++) {
            ulonglong2 b01 = *(const ulonglong2*)&Bs[kk][tx * 4];
            unsigned long long av[4];
#pragma unroll
            for (int i = 0; i < 4; i++) av[i] = As2[kk][ty * 4 + i];
#pragma unroll
            for (int i = 0; i < 4; i++) {
                ffma2(acc[i][0], av[i], b01.x);
                ffma2(acc[i][1], av[i], b01.y);
            }
        }
        __syncthreads();
    }
#pragma unroll
    for (int i = 0; i < 4; i++) {
        int r = row0 + ty * 4 + i;
        if (r >= M) continue;
#pragma unroll
        for (int jp = 0; jp < 2; jp++) {
            float2 v = upk(acc[i][jp]);
            int c0 = col0 + tx * 4 + jp * 2;
#pragma unroll
            for (int q = 0; q < 2; q++) {
                float x = ((q == 0) ? v.x : v.y) * scale;
                if (epi == 2) {
                    x = x / (1.f + __expf(-x)) * cstv;
                    ushort_t h, l; split_bf(x, h, l);
                    Ch[(size_t)r * ldc + offC + c0 + q] = h;
                    Cl[(size_t)r * ldc + offC + c0 + q] = l;
                } else {
                    C[(size_t)r * ldc + offC + c0 + q] = x;
                }
            }
        }
    }
}

// ---------------- launch ----------------
extern "C" void kernel_launch(void* const* d_in, const int* in_sizes, int n_in,
                              void* d_out, int out_size) {
    const float* node_feats = (const float*)d_in[0];
    const void*  edge_index = d_in[1];
    const float* edge_attrs = (const float*)d_in[2];
    const float* edge_feats = (const float*)d_in[3];
    const float* W_up_s     = (const float*)d_in[4];
    const float* W_up_v     = (const float*)d_in[5];
    const float* W1         = (const float*)d_in[6];
    const float* W2         = (const float*)d_in[7];
    const float* W3         = (const float*)d_in[8];
    const float* W4         = (const float*)d_in[9];
    const float* W_out_s    = (const float*)d_in[10];
    const float* W_out_v    = (const float*)d_in[11];
    float* out = (float*)d_out;

    // ---- SILU_CST on the host (same trapezoid as the reference; runs at capture) ----
    double I = 0.0;
    for (int i = 0; i <= 200000; i++) {
        double z = -12.0 + 24.0 * ((double)i / 200000.0);
        double pdf = exp(-0.5 * z * z) * 0.3989422804014326779399461;
        double s = z / (1.0 + exp(-z));
        double f = s * s * pdf;
        I += (i == 0 || i == 200000) ? 0.5 * f : f;
    }
    I *= 24.0 / 200000.0;
    float cstF = (float)(1.0 / sqrt(I));

    float *pS, *pV;
    ushort_t *pHaH, *pHaL, *pHbH, *pHbL, *pTH, *pTL;
    ushort_t *pW2H, *pW2L, *pW3H, *pW3L, *pW4H, *pW4L, *pWsH, *pWsL, *pWvH, *pWvL;
    cudaGetSymbolAddress((void**)&pS,  gS);
    cudaGetSymbolAddress((void**)&pV,  gV);
    cudaGetSymbolAddress((void**)&pHaH, gHaH);
    cudaGetSymbolAddress((void**)&pHaL, gHaL);
    cudaGetSymbolAddress((void**)&pHbH, gHbH);
    cudaGetSymbolAddress((void**)&pHbL, gHbL);
    cudaGetSymbolAddress((void**)&pTH,  gTH);
    cudaGetSymbolAddress((void**)&pTL,  gTL);
    cudaGetSymbolAddress((void**)&pW2H, gW2H);
    cudaGetSymbolAddress((void**)&pW2L, gW2L);
    cudaGetSymbolAddress((void**)&pW3H, gW3H);
    cudaGetSymbolAddress((void**)&pW3L, gW3L);
    cudaGetSymbolAddress((void**)&pW4H, gW4H);
    cudaGetSymbolAddress((void**)&pW4L, gW4L);
    cudaGetSymbolAddress((void**)&pWsH, gWsH);
    cudaGetSymbolAddress((void**)&pWsL, gWsL);
    cudaGetSymbolAddress((void**)&pWvH, gWvH);
    cudaGetSymbolAddress((void**)&pWvL, gWvL);

    const float inv_m  = 0.08838834764831845f;
    const float inv_8  = 0.35355339059327373f;
    const float inv_64 = 0.125f;

    const int SM1 = 61440;   // NT=1 double-buffered
    const int SM2 = 81920;   // NT=2
    cudaFuncSetAttribute(mma_gemm<1, 1, 1>, cudaFuncAttributeMaxDynamicSharedMemorySize, SM1);
    cudaFuncSetAttribute(mma_gemm<2, 0, 1>, cudaFuncAttributeMaxDynamicSharedMemorySize, SM2);

    detect_idx_kernel<<<1, 32>>>((const int*)edge_index);                  // 1
    // MLP1 (K=8, SIMT) -> bf16 pair Ha
    gemm_k<true><<<dim3(3125, 1), 256>>>(edge_feats, 8, 0, 1, W1, 64,      // 2
                                         nullptr, pHaH, pHaL, 64, 0,
                                         NE, 64, 8, inv_8, 2, cstF);
    prep_w<<<16, 256>>>(W2, 64, 64, pW2H, pW2L);                           // 3
    prep_w<<<16, 256>>>(W3, 64, 64, pW3H, pW3L);                           // 4
    // MLP2 / MLP3 (tc)  — ncu capture lands around here
    mma_gemm<1, 1, 1><<<dim3(1563, 1), 256, SM1>>>(pHaH, pHaL, 64, pW2H, pW2L,
                                                   pHbH, pHbL, 64, NE, 64, inv_64, cstF);
    mma_gemm<1, 1, 1><<<dim3(1563, 1), 256, SM1>>>(pHbH, pHbL, 64, pW3H, pW3L,
                                                   pHaH, pHaL, 64, NE, 64, inv_64, cstF);
    prep_w<<<128, 256>>>(W4, 64, 512, pW4H, pW4L);
    // W4: Ha -> T (bf16 pair)
    mma_gemm<2, 0, 1><<<dim3(1563, 4), 256, SM2>>>(pHaH, pHaL, 64, pW4H, pW4L,
                                                   pTH, pTL, 512, NE, 64, inv_64, cstF);
    // node up-projections (SIMT fp32)
    gemm_k<true><<<dim3(157, 2), 256>>>(node_feats, 512, 0, 1, W_up_s, 128,
                                        pS, nullptr, nullptr, 128, 0,
                                        NN, 128, 128, inv_m, 0, cstF);
    for (int m = 0; m < 3; m++)
        gemm_k<false><<<dim3(157, 2), 256>>>(node_feats, 512, 128 + m, 3, W_up_v, 128,
                                             pV, nullptr, nullptr, 384, m * 128,
                                             NN, 128, 128, inv_m, 0, cstF);
    prep_w<<<128, 256>>>(W_out_s, 256, 128, pWsH, pWsL);
    prep_w<<<128, 256>>>(W_out_v, 256, 128, pWvH, pWvL);
    // fused output GEMMs (gather + tensor-product inside A staging)
    mma_outs<<<1563, 256>>>(edge_index, edge_attrs, out);
    mma_outv<<<4688, 256>>>(edge_index, edge_attrs, out);
    (void)in_sizes; (void)n_in; (void)out_size;
}

// round 12
// speedup vs baseline: 3.9417x; 1.2156x over previous
#include <cuda_runtime.h>
#include <cuda_bf16.h>
#include <cuda_fp16.h>
#include <math.h>
#include <stdint.h>

#define NE 200000
#define NN 10000
typedef unsigned short ushort_t;

// ---------------- scratch ----------------
__device__ float gS[NN * 128];
__device__ float gV[NN * 384];                       // [n][m][u]
__device__ ushort_t gTH[(size_t)NE * 512];           // tpw, fp16 (single plane)
// MLP-internal weights: bf16 hi/lo [N][K]
__device__ ushort_t gW2H[64 * 64],  gW2L[64 * 64];
__device__ ushort_t gW3H[64 * 64],  gW3L[64 * 64];
__device__ ushort_t gW4H[512 * 64], gW4L[512 * 64];
// output weights: fp16 hi/lo [N][K]
__device__ ushort_t gWsH[128 * 256], gWsL[128 * 256];
__device__ ushort_t gWvH[128 * 256], gWvL[128 * 256];
__device__ int gIdx64;

// ---------------- helpers ----------------
__device__ __forceinline__ uint32_t smem_u32(const void* p) {
    uint32_t a;
    asm("{ .reg .u64 t; cvta.to.shared.u64 t, %1; cvt.u32.u64 %0, t; }" : "=r"(a) : "l"(p));
    return a;
}
__device__ __forceinline__ void split_bf(float x, ushort_t& h, ushort_t& l) {
    __nv_bfloat16 hb = __float2bfloat16_rn(x);
    float r = x - __bfloat162float(hb);
    __nv_bfloat16 lb = __float2bfloat16_rn(r);
    h = *(ushort_t*)&hb; l = *(ushort_t*)&lb;
}
__device__ __forceinline__ void split_fp16(float x, ushort_t& h, ushort_t& l) {
    __half hb = __float2half_rn(x);
    float r = x - __half2float(hb);
    __half lb = __float2half_rn(r);
    h = *(ushort_t*)&hb; l = *(ushort_t*)&lb;
}
__device__ __forceinline__ ushort_t fp16q(float x) {
    __half hb = __float2half_rn(x);
    return *(ushort_t*)&hb;
}
__device__ __forceinline__ float fp2f(ushort_t u) {
    __half b = *(__half*)&u;
    return __half2float(b);
}
__device__ __forceinline__ void mma_bf16(float c[4], const unsigned a[4], const unsigned b[2]) {
    asm volatile("mma.sync.aligned.m16n8k16.row.col.f32.bf16.bf16.f32 "
        "{%0,%1,%2,%3}, {%4,%5,%6,%7}, {%8,%9}, {%0,%1,%2,%3};\n"
        : "+f"(c[0]), "+f"(c[1]), "+f"(c[2]), "+f"(c[3])
        : "r"(a[0]), "r"(a[1]), "r"(a[2]), "r"(a[3]), "r"(b[0]), "r"(b[1]));
}
__device__ __forceinline__ void mma_f16(float c[4], const unsigned a[4], const unsigned b[2]) {
    asm volatile("mma.sync.aligned.m16n8k16.row.col.f32.f16.f16.f32 "
        "{%0,%1,%2,%3}, {%4,%5,%6,%7}, {%8,%9}, {%0,%1,%2,%3};\n"
        : "+f"(c[0]), "+f"(c[1]), "+f"(c[2]), "+f"(c[3])
        : "r"(a[0]), "r"(a[1]), "r"(a[2]), "r"(a[3]), "r"(b[0]), "r"(b[1]));
}
__device__ __forceinline__ void ldsm4(unsigned r[4], uint32_t addr) {
    asm volatile("ldmatrix.sync.aligned.m8n8.x4.shared.b16 {%0,%1,%2,%3}, [%4];"
        : "=r"(r[0]), "=r"(r[1]), "=r"(r[2]), "=r"(r[3]) : "r"(addr));
}

// ---------------- weight prep: W[K][N] fp32 -> WT[N][K] hi/lo -------------------
template <int FP16>
__global__ void prep_w(const float* __restrict__ W, int Kd, int Nd,
                       ushort_t* __restrict__ Th, ushort_t* __restrict__ Tl) {
    int idx = blockIdx.x * 256 + threadIdx.x;
    if (idx >= Kd * Nd) return;
    int n = idx / Kd, k = idx - n * Kd;
    float x = W[(size_t)k * Nd + n];
    ushort_t h, l;
    if (FP16) split_fp16(x, h, l); else split_bf(x, h, l);
    Th[(size_t)n * Kd + k] = h;
    Tl[(size_t)n * Kd + k] = l;
}

// ---------------- idx dtype detector ----------------
__global__ void detect_idx_kernel(const int* __restrict__ idx32) {
    if (threadIdx.x == 0) {
        int any = 0;
        for (int i = 1; i < 256; i += 2) any |= (idx32[i] != 0);
        gIdx64 = (any == 0) ? 1 : 0;
    }
}

// ---------------- fused edge MLP: ef -> H1 -> H2 -> H3 -> T (fp16) -------------
#define MLP_SMEM 61440
__global__ __launch_bounds__(256, 2) void mlp_fused(
        const float* __restrict__ EF, const float* __restrict__ W1, float cstv) {
    const int PK = 72;
    const int RB = PK * 2;
    extern __shared__ __align__(16) char sm[];
    float* sEF = (float*)sm;
    float* sW1 = (float*)(sm + 4096);
    ushort_t (*Ah)[PK] = (ushort_t(*)[PK])(sm + 6144);
    ushort_t (*Al)[PK] = (ushort_t(*)[PK])(sm + 24576);
    ushort_t (*Bh)[PK] = (ushort_t(*)[PK])(sm + 43008);
    ushort_t (*Bl)[PK] = (ushort_t(*)[PK])(sm + 52224);

    int tid = threadIdx.x, wid = tid >> 5, lane = tid & 31;
    int warp_m = wid & 3, warp_n = wid >> 2;
    int g = lane >> 2, tg = lane & 3;
    int row0 = blockIdx.x * 128;
    int am = warp_m * 32, bn = warp_n * 32;

    {
        int r = tid >> 1, hf = tid & 1;
        int e = min(row0 + r, NE - 1);
        *(float4*)&sEF[r * 8 + hf * 4] = *(const float4*)(EF + (size_t)e * 8 + hf * 4);
        if (tid < 128) *(float4*)&sW1[tid * 4] = *(const float4*)(W1 + tid * 4);
    }
    __syncthreads();

    {
        int r = tid >> 1, hf = tid & 1;
        float ef[8];
#pragma unroll
        for (int k = 0; k < 8; k++) ef[k] = sEF[r * 8 + k];
#pragma unroll
        for (int c0 = 0; c0 < 32; c0 += 2) {
            int c = hf * 32 + c0;
            float x0 = 0.f, x1 = 0.f;
#pragma unroll
            for (int k = 0; k < 8; k++) {
                x0 += ef[k] * sW1[k * 64 + c];
                x1 += ef[k] * sW1[k * 64 + c + 1];
            }
            x0 *= 0.35355339059327373f; x1 *= 0.35355339059327373f;
            x0 = x0 / (1.f + __expf(-x0)) * cstv;
            x1 = x1 / (1.f + __expf(-x1)) * cstv;
            ushort_t h0, l0, h1, l1;
            split_bf(x0, h0, l0); split_bf(x1, h1, l1);
            ushort2 ph; ph.x = h0; ph.y = h1;
            ushort2 pl; pl.x = l0; pl.y = l1;
            *(ushort2*)&Ah[r][c] = ph;
            *(ushort2*)&Al[r][c] = pl;
        }
    }

    int arow = (lane & 7) + ((lane >> 3) & 1) * 8;
    int acol = (lane >> 4) * 8;
    uint32_t aH = smem_u32(&Ah[am + arow][acol]);
    uint32_t aL = smem_u32(&Al[am + arow][acol]);
    int brow = (lane & 7) + ((lane >> 4) & 1) * 8;
    int bcol = ((lane >> 3) & 1) * 8;
    uint32_t bH = smem_u32(&Bh[bn + brow][bcol]);
    uint32_t bL = smem_u32(&Bl[bn + brow][bcol]);

    float acc[2][4][4];
    auto zacc = [&] {
#pragma unroll
        for (int mt = 0; mt < 2; mt++)
#pragma unroll
            for (int nt = 0; nt < 4; nt++)
#pragma unroll
                for (int j = 0; j < 4; j++) acc[mt][nt][j] = 0.f;
    };
    auto stageB = [&](const ushort_t* TH, const ushort_t* TL, int n0) {
#pragma unroll
        for (int i = 0; i < 2; i++) {
            int idx = tid + i * 256;
            int r = idx >> 3, c8 = (idx & 7) * 8;
            *(uint4*)&Bh[r][c8] = *(const uint4*)(TH + (size_t)(n0 + r) * 64 + c8);
            *(uint4*)&Bl[r][c8] = *(const uint4*)(TL + (size_t)(n0 + r) * 64 + c8);
        }
    };
    auto mmaAB = [&] {
#pragma unroll
        for (int ks = 0; ks < 4; ks++) {
            unsigned ah[2][4], al[2][4], bh[2][4], bl[2][4];
#pragma unroll
            for (int mt = 0; mt < 2; mt++) {
                ldsm4(ah[mt], aH + mt * (16 * RB) + ks * 32);
                ldsm4(al[mt], aL + mt * (16 * RB) + ks * 32);
            }
#pragma unroll
            for (int np = 0; np < 2; np++) {
                ldsm4(bh[np], bH + np * (16 * RB) + ks * 32);
                ldsm4(bl[np], bL + np * (16 * RB) + ks * 32);
            }
#pragma unroll
            for (int mt = 0; mt < 2; mt++)
#pragma unroll
                for (int nt = 0; nt < 4; nt++)
                    mma_bf16(acc[mt][nt], ah[mt], &bh[nt >> 1][(nt & 1) * 2]);
#pragma unroll
            for (int mt = 0; mt < 2; mt++)
#pragma unroll
                for (int nt = 0; nt < 4; nt++)
                    mma_bf16(acc[mt][nt], ah[mt], &bl[nt >> 1][(nt & 1) * 2]);
#pragma unroll
            for (int mt = 0; mt < 2; mt++)
#pragma unroll
                for (int nt = 0; nt < 4; nt++)
                    mma_bf16(acc[mt][nt], al[mt], &bh[nt >> 1][(nt & 1) * 2]);
        }
    };
    auto epiH = [&](float scale) {
#pragma unroll
        for (int mt = 0; mt < 2; mt++) {
            int r1 = am + mt * 16 + g, r2 = r1 + 8;
#pragma unroll
            for (int nt = 0; nt < 4; nt++) {
                int cc = bn + nt * 8 + tg * 2;
                float xs[4];
#pragma unroll
                for (int j = 0; j < 4; j++) {
                    float x = acc[mt][nt][j] * scale;
                    xs[j] = x / (1.f + __expf(-x)) * cstv;
                }
                ushort_t h0, l0, h1, l1;
                split_bf(xs[0], h0, l0); split_bf(xs[1], h1, l1);
                ushort2 ph; ph.x = h0; ph.y = h1;
                ushort2 pl; pl.x = l0; pl.y = l1;
                *(ushort2*)&Ah[r1][cc] = ph; *(ushort2*)&Al[r1][cc] = pl;
                split_bf(xs[2], h0, l0); split_bf(xs[3], h1, l1);
                ph.x = h0; ph.y = h1; pl.x = l0; pl.y = l1;
                *(ushort2*)&Ah[r2][cc] = ph; *(ushort2*)&Al[r2][cc] = pl;
            }
        }
    };

    const float inv64 = 0.125f;
    stageB(gW2H, gW2L, 0);
    __syncthreads();
    zacc(); mmaAB();
    __syncthreads();
    epiH(inv64);
    stageB(gW3H, gW3L, 0);
    __syncthreads();
    zacc(); mmaAB();
    __syncthreads();
    epiH(inv64);
    __syncthreads();
    for (int n0 = 0; n0 < 512; n0 += 64) {
        stageB(gW4H, gW4L, n0);
        __syncthreads();
        zacc(); mmaAB();
#pragma unroll
        for (int mt = 0; mt < 2; mt++) {
            int r1 = row0 + am + mt * 16 + g, r2 = r1 + 8;
#pragma unroll
            for (int nt = 0; nt < 4; nt++) {
                int cc = bn + nt * 8 + tg * 2;
                if (r1 < NE) {
                    ushort2 p; p.x = fp16q(acc[mt][nt][0] * inv64);
                    p.y = fp16q(acc[mt][nt][1] * inv64);
                    *(ushort2*)&gTH[(size_t)r1 * 512 + n0 + cc] = p;
                }
                if (r2 < NE) {
                    ushort2 p; p.x = fp16q(acc[mt][nt][2] * inv64);
                    p.y = fp16q(acc[mt][nt][3] * inv64);
                    *(ushort2*)&gTH[(size_t)r2 * 512 + n0 + cc] = p;
                }
            }
        }
        __syncthreads();
    }
}

// ---------------- fused out_s: A = gather/TP (fp16), C = out[:, :128] ----------
__global__ __launch_bounds__(256, 2) void mma_outs(
        const void* __restrict__ eidx, const float* __restrict__ eattr,
        float* __restrict__ C) {
    const int PK = 40;
    __shared__ __align__(16) ushort_t Ah[128][PK];
    __shared__ __align__(16) ushort_t Bh[128][PK], Bl[128][PK];
    __shared__ int sSnd[128];
    __shared__ float4 sY[128];

    int tid = threadIdx.x;
    int wid = tid >> 5, lane = tid & 31;
    int warp_m = wid & 3, warp_n = wid >> 2;
    int g = lane >> 2, tg = lane & 3;
    int row0 = blockIdx.x * 128;
    int am = warp_m * 32, bn = warp_n * 32;

    if (tid < 128) {
        int e = min(row0 + tid, NE - 1);
        int snd = gIdx64 ? (int)((const long long*)eidx)[e] : ((const int*)eidx)[e];
        sSnd[tid] = min(max(snd, 0), NN - 1);
        sY[tid] = *(const float4*)(eattr + 4 * e);
    }
    __syncthreads();

    int arow = (lane & 7) + ((lane >> 3) & 1) * 8;
    int acol = (lane >> 4) * 8;
    uint32_t aH = smem_u32(&Ah[am + arow][acol]);
    int brow = (lane & 7) + ((lane >> 4) & 1) * 8;
    int bcol = ((lane >> 3) & 1) * 8;
    uint32_t bH = smem_u32(&Bh[bn + brow][bcol]);
    uint32_t bL = smem_u32(&Bl[bn + brow][bcol]);

    float acc[2][2][4][4];
#pragma unroll
    for (int n2 = 0; n2 < 2; n2++)
#pragma unroll
        for (int mt = 0; mt < 2; mt++)
#pragma unroll
            for (int nt = 0; nt < 4; nt++)
#pragma unroll
                for (int j = 0; j < 4; j++) acc[n2][mt][nt][j] = 0.f;

    int r = tid >> 1, half = tid & 1;
    int e = min(row0 + r, NE - 1);
    int snd = sSnd[r];
    float4 y = sY[r];

    for (int kc = 0; kc < 8; kc++) {
        int u0 = (kc & 3) * 32 + half * 16;
        size_t tb = (size_t)e * 512 + (kc < 4 ? 0 : 128) + u0;
        __align__(16) ushort_t th[16];
        *(uint4*)&th[0] = *(const uint4*)(gTH + tb);
        *(uint4*)&th[8] = *(const uint4*)(gTH + tb + 8);
        float av[16];
        if (kc < 4) {
            const float* sp = gS + (size_t)snd * 128 + u0;
#pragma unroll
            for (int j = 0; j < 16; j++)
                av[j] = fp2f(th[j]) * sp[j] * y.x;
        } else {
            const float* vp = gV + (size_t)snd * 384 + u0;
#pragma unroll
            for (int j = 0; j < 16; j++) {
                float dv = vp[j] * y.y + vp[128 + j] * y.z + vp[256 + j] * y.w;
                av[j] = fp2f(th[j]) * dv * 0.57735026918962576f;
            }
        }
        __align__(16) ushort_t hh[16];
#pragma unroll
        for (int j = 0; j < 16; j++) hh[j] = fp16q(av[j]);
        *(uint4*)&Ah[r][half * 16] = *(uint4*)&hh[0];
        *(uint4*)&Ah[r][half * 16 + 8] = *(uint4*)&hh[8];
        {
            const ushort_t* ph = gWsH + (size_t)r * 256 + kc * 32 + half * 16;
            const ushort_t* pl = gWsL + (size_t)r * 256 + kc * 32 + half * 16;
            *(uint4*)&Bh[r][half * 16] = *(const uint4*)ph;
            *(uint4*)&Bh[r][half * 16 + 8] = *(const uint4*)(ph + 8);
            *(uint4*)&Bl[r][half * 16] = *(const uint4*)pl;
            *(uint4*)&Bl[r][half * 16 + 8] = *(const uint4*)(pl + 8);
        }
        __syncthreads();

#pragma unroll
        for (int ks = 0; ks < 2; ks++) {
            unsigned ah[2][4];
#pragma unroll
            for (int mt = 0; mt < 2; mt++)
                ldsm4(ah[mt], aH + mt * (16 * PK * 2) + ks * 32);
#pragma unroll
            for (int n2 = 0; n2 < 2; n2++) {
                unsigned bh[2][4], bl[2][4];
#pragma unroll
                for (int np = 0; np < 2; np++) {
                    ldsm4(bh[np], bH + n2 * (64 * PK * 2) + np * (16 * PK * 2) + ks * 32);
                    ldsm4(bl[np], bL + n2 * (64 * PK * 2) + np * (16 * PK * 2) + ks * 32);
                }
#pragma unroll
                for (int mt = 0; mt < 2; mt++)
#pragma unroll
                    for (int nt = 0; nt < 4; nt++)
                        mma_f16(acc[n2][mt][nt], ah[mt], &bh[nt >> 1][(nt & 1) * 2]);
#pragma unroll
                for (int mt = 0; mt < 2; mt++)
#pragma unroll
                    for (int nt = 0; nt < 4; nt++)
                        mma_f16(acc[n2][mt][nt], ah[mt], &bl[nt >> 1][(nt & 1) * 2]);
            }
        }
        __syncthreads();
    }

#pragma unroll
    for (int n2 = 0; n2 < 2; n2++) {
#pragma unroll
        for (int mt = 0; mt < 2; mt++) {
            int rr[2]; rr[0] = row0 + am + mt * 16 + g; rr[1] = rr[0] + 8;
#pragma unroll
            for (int nt = 0; nt < 4; nt++) {
                int cc = n2 * 64 + bn + nt * 8 + tg * 2;
#pragma unroll
                for (int h = 0; h < 2; h++) {
                    int gr = rr[h];
                    if (gr >= NE) continue;
                    float x0 = acc[n2][mt][nt][2 * h] * 0.0625f;
                    float x1 = acc[n2][mt][nt][2 * h + 1] * 0.0625f;
                    *(float2*)&C[(size_t)gr * 512 + cc] = make_float2(x0, x1);
                }
            }
        }
    }
}

// ---------------- fused out_v: rows (e,m)=3e+m, interleaved epilogue ------------
__global__ __launch_bounds__(256, 2) void mma_outv(
        const void* __restrict__ eidx, const float* __restrict__ eattr,
        float* __restrict__ C) {
    const int PK = 40;
    __shared__ __align__(16) ushort_t Ah[128][PK];
    __shared__ __align__(16) ushort_t Bh[128][PK], Bl[128][PK];
    __shared__ int sSnd[128];
    __shared__ float sY0[128], sYm[128];

    int tid = threadIdx.x;
    int wid = tid >> 5, lane = tid & 31;
    int warp_m = wid & 3, warp_n = wid >> 2;
    int g = lane >> 2, tg = lane & 3;
    int row0 = blockIdx.x * 128;
    int am = warp_m * 32, bn = warp_n * 32;

    if (tid < 128) {
        int gr = min(row0 + tid, 3 * NE - 1);
        int e = gr / 3, m = gr - 3 * e;
        int snd = gIdx64 ? (int)((const long long*)eidx)[e] : ((const int*)eidx)[e];
        sSnd[tid] = min(max(snd, 0), NN - 1);
        float4 y = *(const float4*)(eattr + 4 * e);
        sY0[tid] = y.x;
        sYm[tid] = (m == 0) ? y.y : ((m == 1) ? y.z : y.w);
    }
    __syncthreads();

    int arow = (lane & 7) + ((lane >> 3) & 1) * 8;
    int acol = (lane >> 4) * 8;
    uint32_t aH = smem_u32(&Ah[am + arow][acol]);
    int brow = (lane & 7) + ((lane >> 4) & 1) * 8;
    int bcol = ((lane >> 3) & 1) * 8;
    uint32_t bH = smem_u32(&Bh[bn + brow][bcol]);
    uint32_t bL = smem_u32(&Bl[bn + brow][bcol]);

    float acc[2][2][4][4];
#pragma unroll
    for (int n2 = 0; n2 < 2; n2++)
#pragma unroll
        for (int mt = 0; mt < 2; mt++)
#pragma unroll
            for (int nt = 0; nt < 4; nt++)
#pragma unroll
                for (int j = 0; j < 4; j++) acc[n2][mt][nt][j] = 0.f;

    int r = tid >> 1, half = tid & 1;
    int grr = min(row0 + r, 3 * NE - 1);
    int e = grr / 3, m = grr - 3 * e;
    int snd = sSnd[r];
    float y0 = sY0[r], ym = sYm[r];

    for (int kc = 0; kc < 8; kc++) {
        int u0 = (kc & 3) * 32 + half * 16;
        size_t tb = (size_t)e * 512 + (kc < 4 ? 256 : 384) + u0;
        __align__(16) ushort_t th[16];
        *(uint4*)&th[0] = *(const uint4*)(gTH + tb);
        *(uint4*)&th[8] = *(const uint4*)(gTH + tb + 8);
        float av[16];
        if (kc < 4) {
            const float* sp = gS + (size_t)snd * 128 + u0;
#pragma unroll
            for (int j = 0; j < 16; j++)
                av[j] = fp2f(th[j]) * sp[j] * ym;
        } else {
            const float* vp = gV + (size_t)snd * 384 + m * 128 + u0;
#pragma unroll
            for (int j = 0; j < 16; j++)
                av[j] = fp2f(th[j]) * y0 * vp[j];
        }
        __align__(16) ushort_t hh[16];
#pragma unroll
        for (int j = 0; j < 16; j++) hh[j] = fp16q(av[j]);
        *(uint4*)&Ah[r][half * 16] = *(uint4*)&hh[0];
        *(uint4*)&Ah[r][half * 16 + 8] = *(uint4*)&hh[8];
        {
            const ushort_t* ph = gWvH + (size_t)r * 256 + kc * 32 + half * 16;
            const ushort_t* pl = gWvL + (size_t)r * 256 + kc * 32 + half * 16;
            *(uint4*)&Bh[r][half * 16] = *(const uint4*)ph;
            *(uint4*)&Bh[r][half * 16 + 8] = *(const uint4*)(ph + 8);
            *(uint4*)&Bl[r][half * 16] = *(const uint4*)pl;
            *(uint4*)&Bl[r][half * 16 + 8] = *(const uint4*)(pl + 8);
        }
        __syncthreads();

#pragma unroll
        for (int ks = 0; ks < 2; ks++) {
            unsigned ah[2][4];
#pragma unroll
            for (int mt = 0; mt < 2; mt++)
                ldsm4(ah[mt], aH + mt * (16 * PK * 2) + ks * 32);
#pragma unroll
            for (int n2 = 0; n2 < 2; n2++) {
                unsigned bh[2][4], bl[2][4];
#pragma unroll
                for (int np = 0; np < 2; np++) {
                    ldsm4(bh[np], bH + n2 * (64 * PK * 2) + np * (16 * PK * 2) + ks * 32);
                    ldsm4(bl[np], bL + n2 * (64 * PK * 2) + np * (16 * PK * 2) + ks * 32);
                }
#pragma unroll
                for (int mt = 0; mt < 2; mt++)
#pragma unroll
                    for (int nt = 0; nt < 4; nt++)
                        mma_f16(acc[n2][mt][nt], ah[mt], &bh[nt >> 1][(nt & 1) * 2]);
#pragma unroll
                for (int mt = 0; mt < 2; mt++)
#pragma unroll
                    for (int nt = 0; nt < 4; nt++)
                        mma_f16(acc[n2][mt][nt], ah[mt], &bl[nt >> 1][(nt & 1) * 2]);
            }
        }
        __syncthreads();
    }

#pragma unroll
    for (int n2 = 0; n2 < 2; n2++) {
#pragma unroll
        for (int mt = 0; mt < 2; mt++) {
            int rr[2]; rr[0] = row0 + am + mt * 16 + g; rr[1] = rr[0] + 8;
#pragma unroll
            for (int nt = 0; nt < 4; nt++) {
                int cc = n2 * 64 + bn + nt * 8 + tg * 2;
#pragma unroll
                for (int h = 0; h < 2; h++) {
                    int gr = rr[h];
                    if (gr >= 3 * NE) continue;
                    int ee = gr / 3, mm = gr - 3 * ee;
                    float x0 = acc[n2][mt][nt][2 * h] * 0.0625f;
                    float x1 = acc[n2][mt][nt][2 * h + 1] * 0.0625f;
                    C[(size_t)ee * 512 + 128 + mm + 3 * cc] = x0;
                    C[(size_t)ee * 512 + 128 + mm + 3 * (cc + 1)] = x1;
                }
            }
        }
    }
}

// ---------------- SIMT GEMM (node up-proj) ----------------
__device__ __forceinline__ unsigned long long pk2(float x) {
    unsigned long long r; unsigned u = __float_as_uint(x);
    asm("mov.b64 %0, {%1, %1};" : "=l"(r) : "r"(u));
    return r;
}
__device__ __forceinline__ void ffma2(unsigned long long& d, unsigned long long a,
                                      unsigned long long b) {
    asm("fma.rn.f32x2 %0, %1, %2, %0;" : "+l"(d) : "l"(a), "l"(b));
}
__device__ __forceinline__ float2 upk(unsigned long long v) {
    unsigned lo, hi;
    asm("mov.b64 {%0, %1}, %2;" : "=r"(lo), "=r"(hi) : "l"(v));
    return make_float2(__uint_as_float(lo), __uint_as_float(hi));
}

template <bool VECA>
__global__ void gemm_k(const float* __restrict__ A, int lda, int offA, int sA,
                       const float* __restrict__ B, int ldb,
                       float* __restrict__ C, int ldc, int offC,
                       int M, int N, int K, float scale) {
    const int BM = 64, BN = 64, BK = 16;
    __shared__ unsigned long long As2[BK][BM];
    __shared__ __align__(16) float Bs[BK][BN];
    int tid = threadIdx.x;
    int tx = tid & 15, ty = tid >> 4;
    int row0 = blockIdx.x * BM, col0 = blockIdx.y * BN;
    unsigned long long acc[4][2];
#pragma unroll
    for (int i = 0; i < 4; i++) { acc[i][0] = 0ull; acc[i][1] = 0ull; }
    int la_m = tid >> 2, la_k = (tid & 3) * 4;
    int lb_k = tid >> 4, lb_n = (tid & 15) * 4;
    for (int kt = 0; kt < K; kt += BK) {
        float a0 = 0.f, a1 = 0.f, a2 = 0.f, a3 = 0.f;
        int r = row0 + la_m;
        if (r < M) {
            if (VECA) {
                if (kt + la_k < K) {
                    float4 v4 = *(const float4*)(A + (size_t)r * lda + offA + kt + la_k);
                    a0 = v4.x; a1 = v4.y; a2 = v4.z; a3 = v4.w;
                }
            } else {
                int kb = kt + la_k;
                if (kb + 0 < K) a0 = A[(size_t)r * lda + offA + (kb + 0) * sA];
                if (kb + 1 < K) a1 = A[(size_t)r * lda + offA + (kb + 1) * sA];
                if (kb + 2 < K) a2 = A[(size_t)r * lda + offA + (kb + 2) * sA];
                if (kb + 3 < K) a3 = A[(size_t)r * lda + offA + (kb + 3) * sA];
            }
        }
        As2[la_k + 0][la_m] = pk2(a0);
        As2[la_k + 1][la_m] = pk2(a1);
        As2[la_k + 2][la_m] = pk2(a2);
        As2[la_k + 3][la_m] = pk2(a3);
        int kb = kt + lb_k;
        float4 b4 = make_float4(0.f, 0.f, 0.f, 0.f);
        if (kb < K) b4 = *(const float4*)(B + (size_t)kb * ldb + col0 + lb_n);
        *(float4*)&Bs[lb_k][lb_n] = b4;
        __syncthreads();
#pragma unroll
        for (int kk = 0; kk < BK; kk++) {
            ulonglong2 b01 = *(const ulonglong2*)&Bs[kk][tx * 4];
            unsigned long long av[4];
#pragma unroll
            for (int i = 0; i < 4; i++) av[i] = As2[kk][ty * 4 + i];
#pragma unroll
            for (int i = 0; i < 4; i++) {
                ffma2(acc[i][0], av[i], b01.x);
                ffma2(acc[i][1], av[i], b01.y);
            }
        }
        __syncthreads();
    }
#pragma unroll
    for (int i = 0; i < 4; i++) {
        int r = row0 + ty * 4 + i;
        if (r >= M) continue;
#pragma unroll
        for (int jp = 0; jp < 2; jp++) {
            float2 v = upk(acc[i][jp]);
            int c0 = col0 + tx * 4 + jp * 2;
            C[(size_t)r * ldc + offC + c0]     = v.x * scale;
            C[(size_t)r * ldc + offC + c0 + 1] = v.y * scale;
        }
    }
}

// ---------------- launch ----------------
extern "C" void kernel_launch(void* const* d_in, const int* in_sizes, int n_in,
                              void* d_out, int out_size) {
    const float* node_feats = (const float*)d_in[0];
    const void*  edge_index = d_in[1];
    const float* edge_attrs = (const float*)d_in[2];
    const float* edge_feats = (const float*)d_in[3];
    const float* W_up_s     = (const float*)d_in[4];
    const float* W_up_v     = (const float*)d_in[5];
    const float* W1         = (const float*)d_in[6];
    const float* W2         = (const float*)d_in[7];
    const float* W3         = (const float*)d_in[8];
    const float* W4         = (const float*)d_in[9];
    const float* W_out_s    = (const float*)d_in[10];
    const float* W_out_v    = (const float*)d_in[11];
    float* out = (float*)d_out;

    // SILU_CST on host (same trapezoid as reference; runs at capture)
    double I = 0.0;
    for (int i = 0; i <= 200000; i++) {
        double z = -12.0 + 24.0 * ((double)i / 200000.0);
        double pdf = exp(-0.5 * z * z) * 0.3989422804014326779399461;
        double s = z / (1.0 + exp(-z));
        double f = s * s * pdf;
        I += (i == 0 || i == 200000) ? 0.5 * f : f;
    }
    I *= 24.0 / 200000.0;
    float cstF = (float)(1.0 / sqrt(I));

    float *pS, *pV;
    ushort_t *pW2H, *pW2L, *pW3H, *pW3L, *pW4H, *pW4L, *pWsH, *pWsL, *pWvH, *pWvL;
    cudaGetSymbolAddress((void**)&pS,  gS);
    cudaGetSymbolAddress((void**)&pV,  gV);
    cudaGetSymbolAddress((void**)&pW2H, gW2H);
    cudaGetSymbolAddress((void**)&pW2L, gW2L);
    cudaGetSymbolAddress((void**)&pW3H, gW3H);
    cudaGetSymbolAddress((void**)&pW3L, gW3L);
    cudaGetSymbolAddress((void**)&pW4H, gW4H);
    cudaGetSymbolAddress((void**)&pW4L, gW4L);
    cudaGetSymbolAddress((void**)&pWsH, gWsH);
    cudaGetSymbolAddress((void**)&pWsL, gWsL);
    cudaGetSymbolAddress((void**)&pWvH, gWvH);
    cudaGetSymbolAddress((void**)&pWvL, gWvL);

    const float inv_m = 0.08838834764831845f;

    cudaFuncSetAttribute(mlp_fused, cudaFuncAttributeMaxDynamicSharedMemorySize, MLP_SMEM);

    detect_idx_kernel<<<1, 32>>>((const int*)edge_index);            // 1
    prep_w<0><<<16, 256>>>(W2, 64, 64, pW2H, pW2L);                  // 2
    prep_w<0><<<16, 256>>>(W3, 64, 64, pW3H, pW3L);                  // 3
    prep_w<0><<<128, 256>>>(W4, 64, 512, pW4H, pW4L);                // 4
    prep_w<1><<<128, 256>>>(W_out_s, 256, 128, pWsH, pWsL);          // 5
    // fused edge MLP + W4 -> T (fp16)   — ncu captures launch #6
    mlp_fused<<<1563, 256, MLP_SMEM>>>(edge_feats, W1, cstF);        // 6
    // node up-projections (SIMT fp32)
    gemm_k<true><<<dim3(157, 2), 256>>>(node_feats, 512, 0, 1, W_up_s, 128,
                                        pS, 128, 0, NN, 128, 128, inv_m);
    for (int m = 0; m < 3; m++)
        gemm_k<false><<<dim3(157, 2), 256>>>(node_feats, 512, 128 + m, 3, W_up_v, 128,
                                             pV, 384, m * 128, NN, 128, 128, inv_m);
    prep_w<1><<<128, 256>>>(W_out_v, 256, 128, pWvH, pWvL);
    // fused output GEMMs (gather + tensor-product inside A staging)
    mma_outs<<<1563, 256>>>(edge_index, edge_attrs, out);
    mma_outv<<<4688, 256>>>(edge_index, edge_attrs, out);
    (void)in_sizes; (void)n_in; (void)out_size;
}

// round 13
// speedup vs baseline: 4.4378x; 1.1259x over previous
#include <cuda_runtime.h>
#include <cuda_bf16.h>
#include <cuda_fp16.h>
#include <math.h>
#include <stdint.h>

#define NE 200000
#define NN 10000
typedef unsigned short ushort_t;

// ---------------- scratch ----------------
__device__ float gS[NN * 128];
__device__ float gV[NN * 384];                       // [n][m][u]
__device__ ushort_t gTH[(size_t)NE * 512];           // tpw, fp16 (single plane)
// MLP-internal weights: bf16 hi/lo [N][K]
__device__ ushort_t gW2H[64 * 64],  gW2L[64 * 64];
__device__ ushort_t gW3H[64 * 64],  gW3L[64 * 64];
__device__ ushort_t gW4H[512 * 64], gW4L[512 * 64];
// output weights: fp16 hi only [N][K]
__device__ ushort_t gWsH[128 * 256];
__device__ ushort_t gWvH[128 * 256];
__device__ int gIdx64;

// ---------------- helpers ----------------
__device__ __forceinline__ uint32_t smem_u32(const void* p) {
    uint32_t a;
    asm("{ .reg .u64 t; cvta.to.shared.u64 t, %1; cvt.u32.u64 %0, t; }" : "=r"(a) : "l"(p));
    return a;
}
__device__ __forceinline__ void split_bf(float x, ushort_t& h, ushort_t& l) {
    __nv_bfloat16 hb = __float2bfloat16_rn(x);
    float r = x - __bfloat162float(hb);
    __nv_bfloat16 lb = __float2bfloat16_rn(r);
    h = *(ushort_t*)&hb; l = *(ushort_t*)&lb;
}
__device__ __forceinline__ ushort_t fp16q(float x) {
    __half hb = __float2half_rn(x);
    return *(ushort_t*)&hb;
}
__device__ __forceinline__ float fp2f(ushort_t u) {
    __half b = *(__half*)&u;
    return __half2float(b);
}
__device__ __forceinline__ void mma_bf16(float c[4], const unsigned a[4], const unsigned b[2]) {
    asm volatile("mma.sync.aligned.m16n8k16.row.col.f32.bf16.bf16.f32 "
        "{%0,%1,%2,%3}, {%4,%5,%6,%7}, {%8,%9}, {%0,%1,%2,%3};\n"
        : "+f"(c[0]), "+f"(c[1]), "+f"(c[2]), "+f"(c[3])
        : "r"(a[0]), "r"(a[1]), "r"(a[2]), "r"(a[3]), "r"(b[0]), "r"(b[1]));
}
__device__ __forceinline__ void mma_f16(float c[4], const unsigned a[4], const unsigned b[2]) {
    asm volatile("mma.sync.aligned.m16n8k16.row.col.f32.f16.f16.f32 "
        "{%0,%1,%2,%3}, {%4,%5,%6,%7}, {%8,%9}, {%0,%1,%2,%3};\n"
        : "+f"(c[0]), "+f"(c[1]), "+f"(c[2]), "+f"(c[3])
        : "r"(a[0]), "r"(a[1]), "r"(a[2]), "r"(a[3]), "r"(b[0]), "r"(b[1]));
}
__device__ __forceinline__ void ldsm4(unsigned r[4], uint32_t addr) {
    asm volatile("ldmatrix.sync.aligned.m8n8.x4.shared.b16 {%0,%1,%2,%3}, [%4];"
        : "=r"(r[0]), "=r"(r[1]), "=r"(r[2]), "=r"(r[3]) : "r"(addr));
}

// ---------------- weight prep ----------------
// FP16=0: bf16 hi/lo planes. FP16=1: fp16 hi plane only.
template <int FP16>
__global__ void prep_w(const float* __restrict__ W, int Kd, int Nd,
                       ushort_t* __restrict__ Th, ushort_t* __restrict__ Tl) {
    int idx = blockIdx.x * 256 + threadIdx.x;
    if (idx >= Kd * Nd) return;
    int n = idx / Kd, k = idx - n * Kd;
    float x = W[(size_t)k * Nd + n];
    if (FP16) {
        Th[(size_t)n * Kd + k] = fp16q(x);
    } else {
        ushort_t h, l; split_bf(x, h, l);
        Th[(size_t)n * Kd + k] = h;
        Tl[(size_t)n * Kd + k] = l;
    }
}

// ---------------- idx dtype detector ----------------
__global__ void detect_idx_kernel(const int* __restrict__ idx32) {
    if (threadIdx.x == 0) {
        int any = 0;
        for (int i = 1; i < 256; i += 2) any |= (idx32[i] != 0);
        gIdx64 = (any == 0) ? 1 : 0;
    }
}

// ---------------- fused edge MLP: ef -> H1 -> H2 -> H3 -> T (fp16) -------------
#define MLP_SMEM 61440
__global__ __launch_bounds__(256, 2) void mlp_fused(
        const float* __restrict__ EF, const float* __restrict__ W1, float cstv) {
    const int PK = 72;
    const int RB = PK * 2;
    extern __shared__ __align__(16) char sm[];
    float* sEF = (float*)sm;
    float* sW1 = (float*)(sm + 4096);
    ushort_t (*Ah)[PK] = (ushort_t(*)[PK])(sm + 6144);
    ushort_t (*Al)[PK] = (ushort_t(*)[PK])(sm + 24576);
    ushort_t (*Bh)[PK] = (ushort_t(*)[PK])(sm + 43008);
    ushort_t (*Bl)[PK] = (ushort_t(*)[PK])(sm + 52224);

    int tid = threadIdx.x, wid = tid >> 5, lane = tid & 31;
    int warp_m = wid & 3, warp_n = wid >> 2;
    int g = lane >> 2, tg = lane & 3;
    int row0 = blockIdx.x * 128;
    int am = warp_m * 32, bn = warp_n * 32;

    {
        int r = tid >> 1, hf = tid & 1;
        int e = min(row0 + r, NE - 1);
        *(float4*)&sEF[r * 8 + hf * 4] = *(const float4*)(EF + (size_t)e * 8 + hf * 4);
        if (tid < 128) *(float4*)&sW1[tid * 4] = *(const float4*)(W1 + tid * 4);
    }
    __syncthreads();

    {
        int r = tid >> 1, hf = tid & 1;
        float ef[8];
#pragma unroll
        for (int k = 0; k < 8; k++) ef[k] = sEF[r * 8 + k];
#pragma unroll
        for (int c0 = 0; c0 < 32; c0 += 2) {
            int c = hf * 32 + c0;
            float x0 = 0.f, x1 = 0.f;
#pragma unroll
            for (int k = 0; k < 8; k++) {
                x0 += ef[k] * sW1[k * 64 + c];
                x1 += ef[k] * sW1[k * 64 + c + 1];
            }
            x0 *= 0.35355339059327373f; x1 *= 0.35355339059327373f;
            x0 = x0 / (1.f + __expf(-x0)) * cstv;
            x1 = x1 / (1.f + __expf(-x1)) * cstv;
            ushort_t h0, l0, h1, l1;
            split_bf(x0, h0, l0); split_bf(x1, h1, l1);
            ushort2 ph; ph.x = h0; ph.y = h1;
            ushort2 pl; pl.x = l0; pl.y = l1;
            *(ushort2*)&Ah[r][c] = ph;
            *(ushort2*)&Al[r][c] = pl;
        }
    }

    int arow = (lane & 7) + ((lane >> 3) & 1) * 8;
    int acol = (lane >> 4) * 8;
    uint32_t aH = smem_u32(&Ah[am + arow][acol]);
    uint32_t aL = smem_u32(&Al[am + arow][acol]);
    int brow = (lane & 7) + ((lane >> 4) & 1) * 8;
    int bcol = ((lane >> 3) & 1) * 8;
    uint32_t bH = smem_u32(&Bh[bn + brow][bcol]);
    uint32_t bL = smem_u32(&Bl[bn + brow][bcol]);

    float acc[2][4][4];
    auto zacc = [&] {
#pragma unroll
        for (int mt = 0; mt < 2; mt++)
#pragma unroll
            for (int nt = 0; nt < 4; nt++)
#pragma unroll
                for (int j = 0; j < 4; j++) acc[mt][nt][j] = 0.f;
    };
    auto stageB = [&](const ushort_t* TH, const ushort_t* TL, int n0) {
#pragma unroll
        for (int i = 0; i < 2; i++) {
            int idx = tid + i * 256;
            int r = idx >> 3, c8 = (idx & 7) * 8;
            *(uint4*)&Bh[r][c8] = *(const uint4*)(TH + (size_t)(n0 + r) * 64 + c8);
            *(uint4*)&Bl[r][c8] = *(const uint4*)(TL + (size_t)(n0 + r) * 64 + c8);
        }
    };
    auto mmaAB = [&] {
#pragma unroll
        for (int ks = 0; ks < 4; ks++) {
            unsigned ah[2][4], al[2][4], bh[2][4], bl[2][4];
#pragma unroll
            for (int mt = 0; mt < 2; mt++) {
                ldsm4(ah[mt], aH + mt * (16 * RB) + ks * 32);
                ldsm4(al[mt], aL + mt * (16 * RB) + ks * 32);
            }
#pragma unroll
            for (int np = 0; np < 2; np++) {
                ldsm4(bh[np], bH + np * (16 * RB) + ks * 32);
                ldsm4(bl[np], bL + np * (16 * RB) + ks * 32);
            }
#pragma unroll
            for (int mt = 0; mt < 2; mt++)
#pragma unroll
                for (int nt = 0; nt < 4; nt++)
                    mma_bf16(acc[mt][nt], ah[mt], &bh[nt >> 1][(nt & 1) * 2]);
#pragma unroll
            for (int mt = 0; mt < 2; mt++)
#pragma unroll
                for (int nt = 0; nt < 4; nt++)
                    mma_bf16(acc[mt][nt], ah[mt], &bl[nt >> 1][(nt & 1) * 2]);
#pragma unroll
            for (int mt = 0; mt < 2; mt++)
#pragma unroll
                for (int nt = 0; nt < 4; nt++)
                    mma_bf16(acc[mt][nt], al[mt], &bh[nt >> 1][(nt & 1) * 2]);
        }
    };
    auto epiH = [&](float scale) {
#pragma unroll
        for (int mt = 0; mt < 2; mt++) {
            int r1 = am + mt * 16 + g, r2 = r1 + 8;
#pragma unroll
            for (int nt = 0; nt < 4; nt++) {
                int cc = bn + nt * 8 + tg * 2;
                float xs[4];
#pragma unroll
                for (int j = 0; j < 4; j++) {
                    float x = acc[mt][nt][j] * scale;
                    xs[j] = x / (1.f + __expf(-x)) * cstv;
                }
                ushort_t h0, l0, h1, l1;
                split_bf(xs[0], h0, l0); split_bf(xs[1], h1, l1);
                ushort2 ph; ph.x = h0; ph.y = h1;
                ushort2 pl; pl.x = l0; pl.y = l1;
                *(ushort2*)&Ah[r1][cc] = ph; *(ushort2*)&Al[r1][cc] = pl;
                split_bf(xs[2], h0, l0); split_bf(xs[3], h1, l1);
                ph.x = h0; ph.y = h1; pl.x = l0; pl.y = l1;
                *(ushort2*)&Ah[r2][cc] = ph; *(ushort2*)&Al[r2][cc] = pl;
            }
        }
    };

    const float inv64 = 0.125f;
    stageB(gW2H, gW2L, 0);
    __syncthreads();
    zacc(); mmaAB();
    __syncthreads();
    epiH(inv64);
    stageB(gW3H, gW3L, 0);
    __syncthreads();
    zacc(); mmaAB();
    __syncthreads();
    epiH(inv64);
    __syncthreads();

    // ---- W4 loop with register-prefetched B chunks ----
    int pr = tid >> 3, pc8 = (tid & 7) * 8;
    int pr2 = (tid + 256) >> 3, pc82 = ((tid + 256) & 7) * 8;
    uint4 pbh0, pbl0, pbh1, pbl1;
    auto loadB4 = [&](int n0) {
        pbh0 = *(const uint4*)(gW4H + (size_t)(n0 + pr) * 64 + pc8);
        pbl0 = *(const uint4*)(gW4L + (size_t)(n0 + pr) * 64 + pc8);
        pbh1 = *(const uint4*)(gW4H + (size_t)(n0 + pr2) * 64 + pc82);
        pbl1 = *(const uint4*)(gW4L + (size_t)(n0 + pr2) * 64 + pc82);
    };
    loadB4(0);
    for (int n0 = 0; n0 < 512; n0 += 64) {
        *(uint4*)&Bh[pr][pc8] = pbh0;  *(uint4*)&Bl[pr][pc8] = pbl0;
        *(uint4*)&Bh[pr2][pc82] = pbh1; *(uint4*)&Bl[pr2][pc82] = pbl1;
        __syncthreads();
        if (n0 + 64 < 512) loadB4(n0 + 64);
        zacc(); mmaAB();
#pragma unroll
        for (int mt = 0; mt < 2; mt++) {
            int r1 = row0 + am + mt * 16 + g, r2 = r1 + 8;
#pragma unroll
            for (int nt = 0; nt < 4; nt++) {
                int cc = bn + nt * 8 + tg * 2;
                if (r1 < NE) {
                    ushort2 p; p.x = fp16q(acc[mt][nt][0] * inv64);
                    p.y = fp16q(acc[mt][nt][1] * inv64);
                    *(ushort2*)&gTH[(size_t)r1 * 512 + n0 + cc] = p;
                }
                if (r2 < NE) {
                    ushort2 p; p.x = fp16q(acc[mt][nt][2] * inv64);
                    p.y = fp16q(acc[mt][nt][3] * inv64);
                    *(ushort2*)&gTH[(size_t)r2 * 512 + n0 + cc] = p;
                }
            }
        }
        __syncthreads();
    }
}

// ---------------- fused out_s: pipelined A, B fp16-hi only ---------------------
__global__ __launch_bounds__(256, 2) void mma_outs(
        const void* __restrict__ eidx, const float* __restrict__ eattr,
        float* __restrict__ C) {
    const int PK = 40;
    __shared__ __align__(16) ushort_t Ah[128][PK];
    __shared__ __align__(16) ushort_t Bhs[128][PK];
    __shared__ int sSnd[128];
    __shared__ float4 sY[128];

    int tid = threadIdx.x;
    int wid = tid >> 5, lane = tid & 31;
    int warp_m = wid & 3, warp_n = wid >> 2;
    int g = lane >> 2, tg = lane & 3;
    int row0 = blockIdx.x * 128;
    int am = warp_m * 32, bn = warp_n * 32;

    if (tid < 128) {
        int e = min(row0 + tid, NE - 1);
        int snd = gIdx64 ? (int)((const long long*)eidx)[e] : ((const int*)eidx)[e];
        sSnd[tid] = min(max(snd, 0), NN - 1);
        sY[tid] = *(const float4*)(eattr + 4 * e);
    }
    __syncthreads();

    int arow = (lane & 7) + ((lane >> 3) & 1) * 8;
    int acol = (lane >> 4) * 8;
    uint32_t aH = smem_u32(&Ah[am + arow][acol]);
    int brow = (lane & 7) + ((lane >> 4) & 1) * 8;
    int bcol = ((lane >> 3) & 1) * 8;
    uint32_t bH = smem_u32(&Bhs[bn + brow][bcol]);

    float acc[2][2][4][4];
#pragma unroll
    for (int n2 = 0; n2 < 2; n2++)
#pragma unroll
        for (int mt = 0; mt < 2; mt++)
#pragma unroll
            for (int nt = 0; nt < 4; nt++)
#pragma unroll
                for (int j = 0; j < 4; j++) acc[n2][mt][nt][j] = 0.f;

    int r = tid >> 1, half = tid & 1;
    int e = min(row0 + r, NE - 1);
    int snd = sSnd[r];
    float4 y = sY[r];

    // compute A fragment row (16 fp16) for chunk kc into hh
    auto computeA = [&](int kc, ushort_t* hh) {
        int u0 = (kc & 3) * 32 + half * 16;
        size_t tb = (size_t)e * 512 + (kc < 4 ? 0 : 128) + u0;
        __align__(16) ushort_t th[16];
        *(uint4*)&th[0] = *(const uint4*)(gTH + tb);
        *(uint4*)&th[8] = *(const uint4*)(gTH + tb + 8);
        if (kc < 4) {
            const float* sp = gS + (size_t)snd * 128 + u0;
#pragma unroll
            for (int j = 0; j < 16; j++)
                hh[j] = fp16q(fp2f(th[j]) * sp[j] * y.x);
        } else {
            const float* vp = gV + (size_t)snd * 384 + u0;
#pragma unroll
            for (int j = 0; j < 16; j++) {
                float dv = vp[j] * y.y + vp[128 + j] * y.z + vp[256 + j] * y.w;
                hh[j] = fp16q(fp2f(th[j]) * dv * 0.57735026918962576f);
            }
        }
    };

    __align__(16) ushort_t hc[16], hn[16];
    computeA(0, hc);

    for (int kc = 0; kc < 8; kc++) {
        *(uint4*)&Ah[r][half * 16] = *(uint4*)&hc[0];
        *(uint4*)&Ah[r][half * 16 + 8] = *(uint4*)&hc[8];
        {
            const ushort_t* ph = gWsH + (size_t)r * 256 + kc * 32 + half * 16;
            *(uint4*)&Bhs[r][half * 16] = *(const uint4*)ph;
            *(uint4*)&Bhs[r][half * 16 + 8] = *(const uint4*)(ph + 8);
        }
        __syncthreads();
        if (kc < 7) computeA(kc + 1, hn);

#pragma unroll
        for (int ks = 0; ks < 2; ks++) {
            unsigned ah[2][4];
#pragma unroll
            for (int mt = 0; mt < 2; mt++)
                ldsm4(ah[mt], aH + mt * (16 * PK * 2) + ks * 32);
#pragma unroll
            for (int n2 = 0; n2 < 2; n2++) {
                unsigned bh[2][4];
#pragma unroll
                for (int np = 0; np < 2; np++)
                    ldsm4(bh[np], bH + n2 * (64 * PK * 2) + np * (16 * PK * 2) + ks * 32);
#pragma unroll
                for (int mt = 0; mt < 2; mt++)
#pragma unroll
                    for (int nt = 0; nt < 4; nt++)
                        mma_f16(acc[n2][mt][nt], ah[mt], &bh[nt >> 1][(nt & 1) * 2]);
            }
        }
        __syncthreads();
#pragma unroll
        for (int j = 0; j < 16; j++) hc[j] = hn[j];
    }

#pragma unroll
    for (int n2 = 0; n2 < 2; n2++) {
#pragma unroll
        for (int mt = 0; mt < 2; mt++) {
            int rr[2]; rr[0] = row0 + am + mt * 16 + g; rr[1] = rr[0] + 8;
#pragma unroll
            for (int nt = 0; nt < 4; nt++) {
                int cc = n2 * 64 + bn + nt * 8 + tg * 2;
#pragma unroll
                for (int h = 0; h < 2; h++) {
                    int gr = rr[h];
                    if (gr >= NE) continue;
                    float x0 = acc[n2][mt][nt][2 * h] * 0.0625f;
                    float x1 = acc[n2][mt][nt][2 * h + 1] * 0.0625f;
                    *(float2*)&C[(size_t)gr * 512 + cc] = make_float2(x0, x1);
                }
            }
        }
    }
}

// ---------------- fused out_v: pipelined A, B fp16-hi only ---------------------
__global__ __launch_bounds__(256, 2) void mma_outv(
        const void* __restrict__ eidx, const float* __restrict__ eattr,
        float* __restrict__ C) {
    const int PK = 40;
    __shared__ __align__(16) ushort_t Ah[128][PK];
    __shared__ __align__(16) ushort_t Bhs[128][PK];
    __shared__ int sSnd[128];
    __shared__ float sY0[128], sYm[128];

    int tid = threadIdx.x;
    int wid = tid >> 5, lane = tid & 31;
    int warp_m = wid & 3, warp_n = wid >> 2;
    int g = lane >> 2, tg = lane & 3;
    int row0 = blockIdx.x * 128;
    int am = warp_m * 32, bn = warp_n * 32;

    if (tid < 128) {
        int gr = min(row0 + tid, 3 * NE - 1);
        int e = gr / 3, m = gr - 3 * e;
        int snd = gIdx64 ? (int)((const long long*)eidx)[e] : ((const int*)eidx)[e];
        sSnd[tid] = min(max(snd, 0), NN - 1);
        float4 y = *(const float4*)(eattr + 4 * e);
        sY0[tid] = y.x;
        sYm[tid] = (m == 0) ? y.y : ((m == 1) ? y.z : y.w);
    }
    __syncthreads();

    int arow = (lane & 7) + ((lane >> 3) & 1) * 8;
    int acol = (lane >> 4) * 8;
    uint32_t aH = smem_u32(&Ah[am + arow][acol]);
    int brow = (lane & 7) + ((lane >> 4) & 1) * 8;
    int bcol = ((lane >> 3) & 1) * 8;
    uint32_t bH = smem_u32(&Bhs[bn + brow][bcol]);

    float acc[2][2][4][4];
#pragma unroll
    for (int n2 = 0; n2 < 2; n2++)
#pragma unroll
        for (int mt = 0; mt < 2; mt++)
#pragma unroll
            for (int nt = 0; nt < 4; nt++)
#pragma unroll
                for (int j = 0; j < 4; j++) acc[n2][mt][nt][j] = 0.f;

    int r = tid >> 1, half = tid & 1;
    int grr = min(row0 + r, 3 * NE - 1);
    int e = grr / 3, m = grr - 3 * e;
    int snd = sSnd[r];
    float y0 = sY0[r], ym = sYm[r];

    auto computeA = [&](int kc, ushort_t* hh) {
        int u0 = (kc & 3) * 32 + half * 16;
        size_t tb = (size_t)e * 512 + (kc < 4 ? 256 : 384) + u0;
        __align__(16) ushort_t th[16];
        *(uint4*)&th[0] = *(const uint4*)(gTH + tb);
        *(uint4*)&th[8] = *(const uint4*)(gTH + tb + 8);
        if (kc < 4) {
            const float* sp = gS + (size_t)snd * 128 + u0;
#pragma unroll
            for (int j = 0; j < 16; j++)
                hh[j] = fp16q(fp2f(th[j]) * sp[j] * ym);
        } else {
            const float* vp = gV + (size_t)snd * 384 + m * 128 + u0;
#pragma unroll
            for (int j = 0; j < 16; j++)
                hh[j] = fp16q(fp2f(th[j]) * y0 * vp[j]);
        }
    };

    __align__(16) ushort_t hc[16], hn[16];
    computeA(0, hc);

    for (int kc = 0; kc < 8; kc++) {
        *(uint4*)&Ah[r][half * 16] = *(uint4*)&hc[0];
        *(uint4*)&Ah[r][half * 16 + 8] = *(uint4*)&hc[8];
        {
            const ushort_t* ph = gWvH + (size_t)r * 256 + kc * 32 + half * 16;
            *(uint4*)&Bhs[r][half * 16] = *(const uint4*)ph;
            *(uint4*)&Bhs[r][half * 16 + 8] = *(const uint4*)(ph + 8);
        }
        __syncthreads();
        if (kc < 7) computeA(kc + 1, hn);

#pragma unroll
        for (int ks = 0; ks < 2; ks++) {
            unsigned ah[2][4];
#pragma unroll
            for (int mt = 0; mt < 2; mt++)
                ldsm4(ah[mt], aH + mt * (16 * PK * 2) + ks * 32);
#pragma unroll
            for (int n2 = 0; n2 < 2; n2++) {
                unsigned bh[2][4];
#pragma unroll
                for (int np = 0; np < 2; np++)
                    ldsm4(bh[np], bH + n2 * (64 * PK * 2) + np * (16 * PK * 2) + ks * 32);
#pragma unroll
                for (int mt = 0; mt < 2; mt++)
#pragma unroll
                    for (int nt = 0; nt < 4; nt++)
                        mma_f16(acc[n2][mt][nt], ah[mt], &bh[nt >> 1][(nt & 1) * 2]);
            }
        }
        __syncthreads();
#pragma unroll
        for (int j = 0; j < 16; j++) hc[j] = hn[j];
    }

#pragma unroll
    for (int n2 = 0; n2 < 2; n2++) {
#pragma unroll
        for (int mt = 0; mt < 2; mt++) {
            int rr[2]; rr[0] = row0 + am + mt * 16 + g; rr[1] = rr[0] + 8;
#pragma unroll
            for (int nt = 0; nt < 4; nt++) {
                int cc = n2 * 64 + bn + nt * 8 + tg * 2;
#pragma unroll
                for (int h = 0; h < 2; h++) {
                    int gr = rr[h];
                    if (gr >= 3 * NE) continue;
                    int ee = gr / 3, mm = gr - 3 * ee;
                    float x0 = acc[n2][mt][nt][2 * h] * 0.0625f;
                    float x1 = acc[n2][mt][nt][2 * h + 1] * 0.0625f;
                    C[(size_t)ee * 512 + 128 + mm + 3 * cc] = x0;
                    C[(size_t)ee * 512 + 128 + mm + 3 * (cc + 1)] = x1;
                }
            }
        }
    }
}

// ---------------- SIMT GEMM (node up-proj) ----------------
__device__ __forceinline__ unsigned long long pk2(float x) {
    unsigned long long r; unsigned u = __float_as_uint(x);
    asm("mov.b64 %0, {%1, %1};" : "=l"(r) : "r"(u));
    return r;
}
__device__ __forceinline__ void ffma2(unsigned long long& d, unsigned long long a,
                                      unsigned long long b) {
    asm("fma.rn.f32x2 %0, %1, %2, %0;" : "+l"(d) : "l"(a), "l"(b));
}
__device__ __forceinline__ float2 upk(unsigned long long v) {
    unsigned lo, hi;
    asm("mov.b64 {%0, %1}, %2;" : "=r"(lo), "=r"(hi) : "l"(v));
    return make_float2(__uint_as_float(lo), __uint_as_float(hi));
}

template <bool VECA>
__global__ void gemm_k(const float* __restrict__ A, int lda, int offA, int sA,
                       const float* __restrict__ B, int ldb,
                       float* __restrict__ C, int ldc, int offC,
                       int M, int N, int K, float scale) {
    const int BM = 64, BN = 64, BK = 16;
    __shared__ unsigned long long As2[BK][BM];
    __shared__ __align__(16) float Bs[BK][BN];
    int tid = threadIdx.x;
    int tx = tid & 15, ty = tid >> 4;
    int row0 = blockIdx.x * BM, col0 = blockIdx.y * BN;
    unsigned long long acc[4][2];
#pragma unroll
    for (int i = 0; i < 4; i++) { acc[i][0] = 0ull; acc[i][1] = 0ull; }
    int la_m = tid >> 2, la_k = (tid & 3) * 4;
    int lb_k = tid >> 4, lb_n = (tid & 15) * 4;
    for (int kt = 0; kt < K; kt += BK) {
        float a0 = 0.f, a1 = 0.f, a2 = 0.f, a3 = 0.f;
        int r = row0 + la_m;
        if (r < M) {
            if (VECA) {
                if (kt + la_k < K) {
                    float4 v4 = *(const float4*)(A + (size_t)r * lda + offA + kt + la_k);
                    a0 = v4.x; a1 = v4.y; a2 = v4.z; a3 = v4.w;
                }
            } else {
                int kb = kt + la_k;
                if (kb + 0 < K) a0 = A[(size_t)r * lda + offA + (kb + 0) * sA];
                if (kb + 1 < K) a1 = A[(size_t)r * lda + offA + (kb + 1) * sA];
                if (kb + 2 < K) a2 = A[(size_t)r * lda + offA + (kb + 2) * sA];
                if (kb + 3 < K) a3 = A[(size_t)r * lda + offA + (kb + 3) * sA];
            }
        }
        As2[la_k + 0][la_m] = pk2(a0);
        As2[la_k + 1][la_m] = pk2(a1);
        As2[la_k + 2][la_m] = pk2(a2);
        As2[la_k + 3][la_m] = pk2(a3);
        int kb = kt + lb_k;
        float4 b4 = make_float4(0.f, 0.f, 0.f, 0.f);
        if (kb < K) b4 = *(const float4*)(B + (size_t)kb * ldb + col0 + lb_n);
        *(float4*)&Bs[lb_k][lb_n] = b4;
        __syncthreads();
#pragma unroll
        for (int kk = 0; kk < BK; kk++) {
            ulonglong2 b01 = *(const ulonglong2*)&Bs[kk][tx * 4];
            unsigned long long av[4];
#pragma unroll
            for (int i = 0; i < 4; i++) av[i] = As2[kk][ty * 4 + i];
#pragma unroll
            for (int i = 0; i < 4; i++) {
                ffma2(acc[i][0], av[i], b01.x);
                ffma2(acc[i][1], av[i], b01.y);
            }
        }
        __syncthreads();
    }
#pragma unroll
    for (int i = 0; i < 4; i++) {
        int r = row0 + ty * 4 + i;
        if (r >= M) continue;
#pragma unroll
        for (int jp = 0; jp < 2; jp++) {
            float2 v = upk(acc[i][jp]);
            int c0 = col0 + tx * 4 + jp * 2;
            C[(size_t)r * ldc + offC + c0]     = v.x * scale;
            C[(size_t)r * ldc + offC + c0 + 1] = v.y * scale;
        }
    }
}

// ---------------- launch ----------------
extern "C" void kernel_launch(void* const* d_in, const int* in_sizes, int n_in,
                              void* d_out, int out_size) {
    const float* node_feats = (const float*)d_in[0];
    const void*  edge_index = d_in[1];
    const float* edge_attrs = (const float*)d_in[2];
    const float* edge_feats = (const float*)d_in[3];
    const float* W_up_s     = (const float*)d_in[4];
    const float* W_up_v     = (const float*)d_in[5];
    const float* W1         = (const float*)d_in[6];
    const float* W2         = (const float*)d_in[7];
    const float* W3         = (const float*)d_in[8];
    const float* W4         = (const float*)d_in[9];
    const float* W_out_s    = (const float*)d_in[10];
    const float* W_out_v    = (const float*)d_in[11];
    float* out = (float*)d_out;

    // SILU_CST on host (same trapezoid as reference; runs at capture)
    double I = 0.0;
    for (int i = 0; i <= 200000; i++) {
        double z = -12.0 + 24.0 * ((double)i / 200000.0);
        double pdf = exp(-0.5 * z * z) * 0.3989422804014326779399461;
        double s = z / (1.0 + exp(-z));
        double f = s * s * pdf;
        I += (i == 0 || i == 200000) ? 0.5 * f : f;
    }
    I *= 24.0 / 200000.0;
    float cstF = (float)(1.0 / sqrt(I));

    float *pS, *pV;
    ushort_t *pW2H, *pW2L, *pW3H, *pW3L, *pW4H, *pW4L, *pWsH, *pWvH;
    cudaGetSymbolAddress((void**)&pS,  gS);
    cudaGetSymbolAddress((void**)&pV,  gV);
    cudaGetSymbolAddress((void**)&pW2H, gW2H);
    cudaGetSymbolAddress((void**)&pW2L, gW2L);
    cudaGetSymbolAddress((void**)&pW3H, gW3H);
    cudaGetSymbolAddress((void**)&pW3L, gW3L);
    cudaGetSymbolAddress((void**)&pW4H, gW4H);
    cudaGetSymbolAddress((void**)&pW4L, gW4L);
    cudaGetSymbolAddress((void**)&pWsH, gWsH);
    cudaGetSymbolAddress((void**)&pWvH, gWvH);

    const float inv_m = 0.08838834764831845f;

    cudaFuncSetAttribute(mlp_fused, cudaFuncAttributeMaxDynamicSharedMemorySize, MLP_SMEM);

    detect_idx_kernel<<<1, 32>>>((const int*)edge_index);            // 1
    prep_w<0><<<16, 256>>>(W2, 64, 64, pW2H, pW2L);                  // 2
    prep_w<0><<<16, 256>>>(W3, 64, 64, pW3H, pW3L);                  // 3
    prep_w<0><<<128, 256>>>(W4, 64, 512, pW4H, pW4L);                // 4
    prep_w<1><<<128, 256>>>(W_out_s, 256, 128, pWsH, nullptr);       // 5
    // fused edge MLP + W4 -> T (fp16)
    mlp_fused<<<1563, 256, MLP_SMEM>>>(edge_feats, W1, cstF);        // 6
    // node up-projections (SIMT fp32)
    gemm_k<true><<<dim3(157, 2), 256>>>(node_feats, 512, 0, 1, W_up_s, 128,
                                        pS, 128, 0, NN, 128, 128, inv_m);
    for (int m = 0; m < 3; m++)
        gemm_k<false><<<dim3(157, 2), 256>>>(node_feats, 512, 128 + m, 3, W_up_v, 128,
                                             pV, 384, m * 128, NN, 128, 128, inv_m);
    prep_w<1><<<128, 256>>>(W_out_v, 256, 128, pWvH, nullptr);
    // fused output GEMMs (gather + tensor-product inside A staging)
    mma_outs<<<1563, 256>>>(edge_index, edge_attrs, out);
    mma_outv<<<4688, 256>>>(edge_index, edge_attrs, out);
    (void)in_sizes; (void)n_in; (void)out_size;
}

// round 14
// speedup vs baseline: 4.6808x; 1.0548x over previous
#include <cuda_runtime.h>
#include <cuda_bf16.h>
#include <cuda_fp16.h>
#include <math.h>
#include <stdint.h>

#define NE 200000
#define NN 10000
typedef unsigned short ushort_t;

// ---------------- scratch ----------------
__device__ float gS[NN * 128];
__device__ float gV[NN * 384];                       // [n][m][u]
__device__ ushort_t gTH[(size_t)NE * 512];           // tpw fp16; only cols 256..511 used
// MLP-internal weights: bf16 hi/lo [N][K]
__device__ ushort_t gW2H[64 * 64],  gW2L[64 * 64];
__device__ ushort_t gW3H[64 * 64],  gW3L[64 * 64];
__device__ ushort_t gW4H[512 * 64], gW4L[512 * 64];
// output weights: fp16 hi only [N][K]
__device__ ushort_t gWsH[128 * 256];
__device__ ushort_t gWvH[128 * 256];
__device__ int gIdx64;

// ---------------- helpers ----------------
__device__ __forceinline__ uint32_t smem_u32(const void* p) {
    uint32_t a;
    asm("{ .reg .u64 t; cvta.to.shared.u64 t, %1; cvt.u32.u64 %0, t; }" : "=r"(a) : "l"(p));
    return a;
}
__device__ __forceinline__ void split_bf(float x, ushort_t& h, ushort_t& l) {
    __nv_bfloat16 hb = __float2bfloat16_rn(x);
    float r = x - __bfloat162float(hb);
    __nv_bfloat16 lb = __float2bfloat16_rn(r);
    h = *(ushort_t*)&hb; l = *(ushort_t*)&lb;
}
__device__ __forceinline__ ushort_t fp16q(float x) {
    __half hb = __float2half_rn(x);
    return *(ushort_t*)&hb;
}
__device__ __forceinline__ float fp2f(ushort_t u) {
    __half b = *(__half*)&u;
    return __half2float(b);
}
__device__ __forceinline__ void mma_bf16(float c[4], const unsigned a[4], const unsigned b[2]) {
    asm volatile("mma.sync.aligned.m16n8k16.row.col.f32.bf16.bf16.f32 "
        "{%0,%1,%2,%3}, {%4,%5,%6,%7}, {%8,%9}, {%0,%1,%2,%3};\n"
        : "+f"(c[0]), "+f"(c[1]), "+f"(c[2]), "+f"(c[3])
        : "r"(a[0]), "r"(a[1]), "r"(a[2]), "r"(a[3]), "r"(b[0]), "r"(b[1]));
}
__device__ __forceinline__ void mma_f16(float c[4], const unsigned a[4], const unsigned b[2]) {
    asm volatile("mma.sync.aligned.m16n8k16.row.col.f32.f16.f16.f32 "
        "{%0,%1,%2,%3}, {%4,%5,%6,%7}, {%8,%9}, {%0,%1,%2,%3};\n"
        : "+f"(c[0]), "+f"(c[1]), "+f"(c[2]), "+f"(c[3])
        : "r"(a[0]), "r"(a[1]), "r"(a[2]), "r"(a[3]), "r"(b[0]), "r"(b[1]));
}
__device__ __forceinline__ void ldsm4(unsigned r[4], uint32_t addr) {
    asm volatile("ldmatrix.sync.aligned.m8n8.x4.shared.b16 {%0,%1,%2,%3}, [%4];"
        : "=r"(r[0]), "=r"(r[1]), "=r"(r[2]), "=r"(r[3]) : "r"(addr));
}

// ---------------- weight prep ----------------
template <int FP16>
__global__ void prep_w(const float* __restrict__ W, int Kd, int Nd,
                       ushort_t* __restrict__ Th, ushort_t* __restrict__ Tl) {
    int idx = blockIdx.x * 256 + threadIdx.x;
    if (idx >= Kd * Nd) return;
    int n = idx / Kd, k = idx - n * Kd;
    float x = W[(size_t)k * Nd + n];
    if (FP16) {
        Th[(size_t)n * Kd + k] = fp16q(x);
    } else {
        ushort_t h, l; split_bf(x, h, l);
        Th[(size_t)n * Kd + k] = h;
        Tl[(size_t)n * Kd + k] = l;
    }
}

// ---------------- idx dtype detector ----------------
__global__ void detect_idx_kernel(const int* __restrict__ idx32) {
    if (threadIdx.x == 0) {
        int any = 0;
        for (int i = 1; i < 256; i += 2) any |= (idx32[i] != 0);
        gIdx64 = (any == 0) ? 1 : 0;
    }
}

// ---------------- fused: edge MLP -> W4; cols<256 feed out_s in-kernel ----------
// smem layout (pitch 72 el = 144B rows):
//   sEF  [128*8] f32   @ 0       (4096)
//   sW1  [512]   f32   @ 4096    (2048)
//   Ah   [128][72]     @ 6144    (18432)   H bf16-hi
//   Al   [128][72]     @ 24576   (18432)   H bf16-lo
//   Ao   [128][72]     @ 43008   (18432)   out_s A tile (fp16)
//   Bw   [128][72]     @ 61440   (18432)   MLP: hi rows 0-63, lo rows 64-127; out_s: Ws 128 rows
//   sSnd [128] int     @ 79872   (512)
//   sY   [128] float4  @ 80384   (2048)    total 82432
#define FUSE_SMEM 82432
__global__ __launch_bounds__(256, 1) void mlp_outs_fused(
        const float* __restrict__ EF, const float* __restrict__ W1,
        const void* __restrict__ eidx, const float* __restrict__ eattr,
        float* __restrict__ C, float cstv) {
    const int PK = 72;
    const int RB = PK * 2;
    extern __shared__ __align__(16) char sm[];
    float* sEF = (float*)sm;
    float* sW1 = (float*)(sm + 4096);
    ushort_t (*Ah)[PK] = (ushort_t(*)[PK])(sm + 6144);
    ushort_t (*Al)[PK] = (ushort_t(*)[PK])(sm + 24576);
    ushort_t (*Ao)[PK] = (ushort_t(*)[PK])(sm + 43008);
    ushort_t (*Bw)[PK] = (ushort_t(*)[PK])(sm + 61440);
    int*    sSnd = (int*)(sm + 79872);
    float4* sY   = (float4*)(sm + 80384);

    int tid = threadIdx.x, wid = tid >> 5, lane = tid & 31;
    int warp_m = wid & 3, warp_n = wid >> 2;
    int g = lane >> 2, tg = lane & 3;
    int row0 = blockIdx.x * 128;
    int am = warp_m * 32, bn = warp_n * 32;

    // prologue: EF tile, W1, gather snd + y
    {
        int r = tid >> 1, hf = tid & 1;
        int e = min(row0 + r, NE - 1);
        *(float4*)&sEF[r * 8 + hf * 4] = *(const float4*)(EF + (size_t)e * 8 + hf * 4);
        if (tid < 128) *(float4*)&sW1[tid * 4] = *(const float4*)(W1 + tid * 4);
        if (tid < 128) {
            int ee = min(row0 + tid, NE - 1);
            int snd = gIdx64 ? (int)((const long long*)eidx)[ee] : ((const int*)eidx)[ee];
            sSnd[tid] = min(max(snd, 0), NN - 1);
            sY[tid] = *(const float4*)(eattr + 4 * ee);
        }
    }
    __syncthreads();

    // H1 = silu(ef @ W1 * inv8) * cst  -> Ah/Al
    {
        int r = tid >> 1, hf = tid & 1;
        float ef[8];
#pragma unroll
        for (int k = 0; k < 8; k++) ef[k] = sEF[r * 8 + k];
#pragma unroll
        for (int c0 = 0; c0 < 32; c0 += 2) {
            int c = hf * 32 + c0;
            float x0 = 0.f, x1 = 0.f;
#pragma unroll
            for (int k = 0; k < 8; k++) {
                x0 += ef[k] * sW1[k * 64 + c];
                x1 += ef[k] * sW1[k * 64 + c + 1];
            }
            x0 *= 0.35355339059327373f; x1 *= 0.35355339059327373f;
            x0 = x0 / (1.f + __expf(-x0)) * cstv;
            x1 = x1 / (1.f + __expf(-x1)) * cstv;
            ushort_t h0, l0, h1, l1;
            split_bf(x0, h0, l0); split_bf(x1, h1, l1);
            ushort2 ph; ph.x = h0; ph.y = h1;
            ushort2 pl; pl.x = l0; pl.y = l1;
            *(ushort2*)&Ah[r][c] = ph;
            *(ushort2*)&Al[r][c] = pl;
        }
    }

    int arow = (lane & 7) + ((lane >> 3) & 1) * 8;
    int acol = (lane >> 4) * 8;
    uint32_t aH = smem_u32(&Ah[am + arow][acol]);
    uint32_t aL = smem_u32(&Al[am + arow][acol]);
    uint32_t aO = smem_u32(&Ao[am + arow][acol]);
    int brow = (lane & 7) + ((lane >> 4) & 1) * 8;
    int bcol = ((lane >> 3) & 1) * 8;
    uint32_t bH = smem_u32(&Bw[bn + brow][bcol]);     // MLP hi; out_s Ws (n2=0)
    uint32_t bL = bH + 64 * RB;                       // MLP lo; out_s Ws (n2=1)

    float acc[2][4][4];
    float acco[2][2][4][4];
#pragma unroll
    for (int n2 = 0; n2 < 2; n2++)
#pragma unroll
        for (int mt = 0; mt < 2; mt++)
#pragma unroll
            for (int nt = 0; nt < 4; nt++)
#pragma unroll
                for (int j = 0; j < 4; j++) acco[n2][mt][nt][j] = 0.f;

    auto zacc = [&] {
#pragma unroll
        for (int mt = 0; mt < 2; mt++)
#pragma unroll
            for (int nt = 0; nt < 4; nt++)
#pragma unroll
                for (int j = 0; j < 4; j++) acc[mt][nt][j] = 0.f;
    };
    auto stageB = [&](const ushort_t* TH, const ushort_t* TL, int n0) {
#pragma unroll
        for (int i = 0; i < 2; i++) {
            int idx = tid + i * 256;
            int r = idx >> 3, c8 = (idx & 7) * 8;
            *(uint4*)&Bw[r][c8] = *(const uint4*)(TH + (size_t)(n0 + r) * 64 + c8);
            *(uint4*)&Bw[r + 64][c8] = *(const uint4*)(TL + (size_t)(n0 + r) * 64 + c8);
        }
    };
    auto mmaAB = [&] {
#pragma unroll
        for (int ks = 0; ks < 4; ks++) {
            unsigned ah[2][4], al[2][4], bh[2][4], bl[2][4];
#pragma unroll
            for (int mt = 0; mt < 2; mt++) {
                ldsm4(ah[mt], aH + mt * (16 * RB) + ks * 32);
                ldsm4(al[mt], aL + mt * (16 * RB) + ks * 32);
            }
#pragma unroll
            for (int np = 0; np < 2; np++) {
                ldsm4(bh[np], bH + np * (16 * RB) + ks * 32);
                ldsm4(bl[np], bL + np * (16 * RB) + ks * 32);
            }
#pragma unroll
            for (int mt = 0; mt < 2; mt++)
#pragma unroll
                for (int nt = 0; nt < 4; nt++)
                    mma_bf16(acc[mt][nt], ah[mt], &bh[nt >> 1][(nt & 1) * 2]);
#pragma unroll
            for (int mt = 0; mt < 2; mt++)
#pragma unroll
                for (int nt = 0; nt < 4; nt++)
                    mma_bf16(acc[mt][nt], ah[mt], &bl[nt >> 1][(nt & 1) * 2]);
#pragma unroll
            for (int mt = 0; mt < 2; mt++)
#pragma unroll
                for (int nt = 0; nt < 4; nt++)
                    mma_bf16(acc[mt][nt], al[mt], &bh[nt >> 1][(nt & 1) * 2]);
        }
    };
    auto epiH = [&](float scale) {
#pragma unroll
        for (int mt = 0; mt < 2; mt++) {
            int r1 = am + mt * 16 + g, r2 = r1 + 8;
#pragma unroll
            for (int nt = 0; nt < 4; nt++) {
                int cc = bn + nt * 8 + tg * 2;
                float xs[4];
#pragma unroll
                for (int j = 0; j < 4; j++) {
                    float x = acc[mt][nt][j] * scale;
                    xs[j] = x / (1.f + __expf(-x)) * cstv;
                }
                ushort_t h0, l0, h1, l1;
                split_bf(xs[0], h0, l0); split_bf(xs[1], h1, l1);
                ushort2 ph; ph.x = h0; ph.y = h1;
                ushort2 pl; pl.x = l0; pl.y = l1;
                *(ushort2*)&Ah[r1][cc] = ph; *(ushort2*)&Al[r1][cc] = pl;
                split_bf(xs[2], h0, l0); split_bf(xs[3], h1, l1);
                ph.x = h0; ph.y = h1; pl.x = l0; pl.y = l1;
                *(ushort2*)&Ah[r2][cc] = ph; *(ushort2*)&Al[r2][cc] = pl;
            }
        }
    };

    const float inv64 = 0.125f;
    stageB(gW2H, gW2L, 0);
    __syncthreads();
    zacc(); mmaAB();
    __syncthreads();
    epiH(inv64);
    stageB(gW3H, gW3L, 0);
    __syncthreads();
    zacc(); mmaAB();
    __syncthreads();
    epiH(inv64);
    __syncthreads();

    // ---- W4 loop; chunks n0<256 feed out_s; n0>=256 -> gTH for out_v ----
    int pr = tid >> 3, pc8 = (tid & 7) * 8;
    int pr2 = (tid + 256) >> 3, pc82 = ((tid + 256) & 7) * 8;
    uint4 pbh0, pbl0, pbh1, pbl1;
    auto loadB4 = [&](int n0) {
        pbh0 = *(const uint4*)(gW4H + (size_t)(n0 + pr) * 64 + pc8);
        pbl0 = *(const uint4*)(gW4L + (size_t)(n0 + pr) * 64 + pc8);
        pbh1 = *(const uint4*)(gW4H + (size_t)(n0 + pr2) * 64 + pc82);
        pbl1 = *(const uint4*)(gW4L + (size_t)(n0 + pr2) * 64 + pc82);
    };
    loadB4(0);
    for (int n0 = 0; n0 < 512; n0 += 64) {
        *(uint4*)&Bw[pr][pc8] = pbh0;   *(uint4*)&Bw[pr + 64][pc8] = pbl0;
        *(uint4*)&Bw[pr2][pc82] = pbh1; *(uint4*)&Bw[pr2 + 64][pc82] = pbl1;
        __syncthreads();
        if (n0 + 64 < 512) loadB4(n0 + 64);
        zacc(); mmaAB();

        if (n0 < 256) {
            __syncthreads();   // done reading Bw (W4); about to overwrite with Ws
            // multiply T-chunk accumulators by gather factor -> Ao (fp16)
#pragma unroll
            for (int mt = 0; mt < 2; mt++) {
#pragma unroll
                for (int hrow = 0; hrow < 2; hrow++) {
                    int rloc = am + mt * 16 + g + hrow * 8;
                    int snd = sSnd[rloc];
                    float4 y = sY[rloc];
#pragma unroll
                    for (int nt = 0; nt < 4; nt++) {
                        int cc = bn + nt * 8 + tg * 2;
                        int k = n0 + cc;
                        float f0, f1;
                        if (n0 < 128) {
                            const float* sp = gS + (size_t)snd * 128 + k;
                            f0 = sp[0] * y.x; f1 = sp[1] * y.x;
                        } else {
                            int u = k - 128;
                            const float* vp = gV + (size_t)snd * 384 + u;
                            f0 = (vp[0] * y.y + vp[128] * y.z + vp[256] * y.w) * 0.57735026918962576f;
                            f1 = (vp[1] * y.y + vp[129] * y.z + vp[257] * y.w) * 0.57735026918962576f;
                        }
                        float a0 = acc[mt][nt][2 * hrow + 0] * inv64 * f0;
                        float a1 = acc[mt][nt][2 * hrow + 1] * inv64 * f1;
                        ushort2 p; p.x = fp16q(a0); p.y = fp16q(a1);
                        *(ushort2*)&Ao[rloc][cc] = p;
                    }
                }
            }
            // stage Ws chunk [128 N][64 K] -> Bw rows 0..127
#pragma unroll
            for (int i = 0; i < 4; i++) {
                int idx = tid + i * 256;
                int r = idx >> 3, c8 = (idx & 7) * 8;
                *(uint4*)&Bw[r][c8] = *(const uint4*)(gWsH + (size_t)r * 256 + n0 + c8);
            }
            __syncthreads();
            // out_s MMA: acco += Ao(128x64) * Ws^T
#pragma unroll
            for (int ks = 0; ks < 4; ks++) {
                unsigned ah[2][4];
#pragma unroll
                for (int mt = 0; mt < 2; mt++)
                    ldsm4(ah[mt], aO + mt * (16 * RB) + ks * 32);
#pragma unroll
                for (int n2 = 0; n2 < 2; n2++) {
                    unsigned bh[2][4];
#pragma unroll
                    for (int np = 0; np < 2; np++)
                        ldsm4(bh[np], bH + n2 * (64 * RB) + np * (16 * RB) + ks * 32);
#pragma unroll
                    for (int mt = 0; mt < 2; mt++)
#pragma unroll
                        for (int nt = 0; nt < 4; nt++)
                            mma_f16(acco[n2][mt][nt], ah[mt], &bh[nt >> 1][(nt & 1) * 2]);
                }
            }
            __syncthreads();   // before next iteration's Bw store
        } else {
#pragma unroll
            for (int mt = 0; mt < 2; mt++) {
                int r1 = row0 + am + mt * 16 + g, r2 = r1 + 8;
#pragma unroll
                for (int nt = 0; nt < 4; nt++) {
                    int cc = bn + nt * 8 + tg * 2;
                    if (r1 < NE) {
                        ushort2 p; p.x = fp16q(acc[mt][nt][0] * inv64);
                        p.y = fp16q(acc[mt][nt][1] * inv64);
                        *(ushort2*)&gTH[(size_t)r1 * 512 + n0 + cc] = p;
                    }
                    if (r2 < NE) {
                        ushort2 p; p.x = fp16q(acc[mt][nt][2] * inv64);
                        p.y = fp16q(acc[mt][nt][3] * inv64);
                        *(ushort2*)&gTH[(size_t)r2 * 512 + n0 + cc] = p;
                    }
                }
            }
            __syncthreads();
        }
    }

    // ---- out_s epilogue: C[:, :128] ----
#pragma unroll
    for (int n2 = 0; n2 < 2; n2++) {
#pragma unroll
        for (int mt = 0; mt < 2; mt++) {
            int rr[2]; rr[0] = row0 + am + mt * 16 + g; rr[1] = rr[0] + 8;
#pragma unroll
            for (int nt = 0; nt < 4; nt++) {
                int cc = n2 * 64 + bn + nt * 8 + tg * 2;
#pragma unroll
                for (int h = 0; h < 2; h++) {
                    int gr = rr[h];
                    if (gr >= NE) continue;
                    float x0 = acco[n2][mt][nt][2 * h] * 0.0625f;
                    float x1 = acco[n2][mt][nt][2 * h + 1] * 0.0625f;
                    *(float2*)&C[(size_t)gr * 512 + cc] = make_float2(x0, x1);
                }
            }
        }
    }
}

// ---------------- fused out_v: pipelined A, B fp16-hi only ---------------------
__global__ __launch_bounds__(256, 2) void mma_outv(
        const void* __restrict__ eidx, const float* __restrict__ eattr,
        float* __restrict__ C) {
    const int PK = 40;
    __shared__ __align__(16) ushort_t Ah[128][PK];
    __shared__ __align__(16) ushort_t Bhs[128][PK];
    __shared__ int sSnd[128];
    __shared__ float sY0[128], sYm[128];

    int tid = threadIdx.x;
    int wid = tid >> 5, lane = tid & 31;
    int warp_m = wid & 3, warp_n = wid >> 2;
    int g = lane >> 2, tg = lane & 3;
    int row0 = blockIdx.x * 128;
    int am = warp_m * 32, bn = warp_n * 32;

    if (tid < 128) {
        int gr = min(row0 + tid, 3 * NE - 1);
        int e = gr / 3, m = gr - 3 * e;
        int snd = gIdx64 ? (int)((const long long*)eidx)[e] : ((const int*)eidx)[e];
        sSnd[tid] = min(max(snd, 0), NN - 1);
        float4 y = *(const float4*)(eattr + 4 * e);
        sY0[tid] = y.x;
        sYm[tid] = (m == 0) ? y.y : ((m == 1) ? y.z : y.w);
    }
    __syncthreads();

    int arow = (lane & 7) + ((lane >> 3) & 1) * 8;
    int acol = (lane >> 4) * 8;
    uint32_t aH = smem_u32(&Ah[am + arow][acol]);
    int brow = (lane & 7) + ((lane >> 4) & 1) * 8;
    int bcol = ((lane >> 3) & 1) * 8;
    uint32_t bH = smem_u32(&Bhs[bn + brow][bcol]);

    float acc[2][2][4][4];
#pragma unroll
    for (int n2 = 0; n2 < 2; n2++)
#pragma unroll
        for (int mt = 0; mt < 2; mt++)
#pragma unroll
            for (int nt = 0; nt < 4; nt++)
#pragma unroll
                for (int j = 0; j < 4; j++) acc[n2][mt][nt][j] = 0.f;

    int r = tid >> 1, half = tid & 1;
    int grr = min(row0 + r, 3 * NE - 1);
    int e = grr / 3, m = grr - 3 * e;
    int snd = sSnd[r];
    float y0 = sY0[r], ym = sYm[r];

    auto computeA = [&](int kc, ushort_t* hh) {
        int u0 = (kc & 3) * 32 + half * 16;
        size_t tb = (size_t)e * 512 + (kc < 4 ? 256 : 384) + u0;
        __align__(16) ushort_t th[16];
        *(uint4*)&th[0] = *(const uint4*)(gTH + tb);
        *(uint4*)&th[8] = *(const uint4*)(gTH + tb + 8);
        if (kc < 4) {
            const float* sp = gS + (size_t)snd * 128 + u0;
#pragma unroll
            for (int j = 0; j < 16; j++)
                hh[j] = fp16q(fp2f(th[j]) * sp[j] * ym);
        } else {
            const float* vp = gV + (size_t)snd * 384 + m * 128 + u0;
#pragma unroll
            for (int j = 0; j < 16; j++)
                hh[j] = fp16q(fp2f(th[j]) * y0 * vp[j]);
        }
    };

    __align__(16) ushort_t hc[16], hn[16];
    computeA(0, hc);

    for (int kc = 0; kc < 8; kc++) {
        *(uint4*)&Ah[r][half * 16] = *(uint4*)&hc[0];
        *(uint4*)&Ah[r][half * 16 + 8] = *(uint4*)&hc[8];
        {
            const ushort_t* ph = gWvH + (size_t)r * 256 + kc * 32 + half * 16;
            *(uint4*)&Bhs[r][half * 16] = *(const uint4*)ph;
            *(uint4*)&Bhs[r][half * 16 + 8] = *(const uint4*)(ph + 8);
        }
        __syncthreads();
        if (kc < 7) computeA(kc + 1, hn);

#pragma unroll
        for (int ks = 0; ks < 2; ks++) {
            unsigned ah[2][4];
#pragma unroll
            for (int mt = 0; mt < 2; mt++)
                ldsm4(ah[mt], aH + mt * (16 * PK * 2) + ks * 32);
#pragma unroll
            for (int n2 = 0; n2 < 2; n2++) {
                unsigned bh[2][4];
#pragma unroll
                for (int np = 0; np < 2; np++)
                    ldsm4(bh[np], bH + n2 * (64 * PK * 2) + np * (16 * PK * 2) + ks * 32);
#pragma unroll
                for (int mt = 0; mt < 2; mt++)
#pragma unroll
                    for (int nt = 0; nt < 4; nt++)
                        mma_f16(acc[n2][mt][nt], ah[mt], &bh[nt >> 1][(nt & 1) * 2]);
            }
        }
        __syncthreads();
#pragma unroll
        for (int j = 0; j < 16; j++) hc[j] = hn[j];
    }

#pragma unroll
    for (int n2 = 0; n2 < 2; n2++) {
#pragma unroll
        for (int mt = 0; mt < 2; mt++) {
            int rr[2]; rr[0] = row0 + am + mt * 16 + g; rr[1] = rr[0] + 8;
#pragma unroll
            for (int nt = 0; nt < 4; nt++) {
                int cc = n2 * 64 + bn + nt * 8 + tg * 2;
#pragma unroll
                for (int h = 0; h < 2; h++) {
                    int gr = rr[h];
                    if (gr >= 3 * NE) continue;
                    int ee = gr / 3, mm = gr - 3 * ee;
                    float x0 = acc[n2][mt][nt][2 * h] * 0.0625f;
                    float x1 = acc[n2][mt][nt][2 * h + 1] * 0.0625f;
                    C[(size_t)ee * 512 + 128 + mm + 3 * cc] = x0;
                    C[(size_t)ee * 512 + 128 + mm + 3 * (cc + 1)] = x1;
                }
            }
        }
    }
}

// ---------------- SIMT GEMM (node up-proj) ----------------
__device__ __forceinline__ unsigned long long pk2(float x) {
    unsigned long long r; unsigned u = __float_as_uint(x);
    asm("mov.b64 %0, {%1, %1};" : "=l"(r) : "r"(u));
    return r;
}
__device__ __forceinline__ void ffma2(unsigned long long& d, unsigned long long a,
                                      unsigned long long b) {
    asm("fma.rn.f32x2 %0, %1, %2, %0;" : "+l"(d) : "l"(a), "l"(b));
}
__device__ __forceinline__ float2 upk(unsigned long long v) {
    unsigned lo, hi;
    asm("mov.b64 {%0, %1}, %2;" : "=r"(lo), "=r"(hi) : "l"(v));
    return make_float2(__uint_as_float(lo), __uint_as_float(hi));
}

template <bool VECA>
__global__ void gemm_k(const float* __restrict__ A, int lda, int offA, int sA,
                       const float* __restrict__ B, int ldb,
                       float* __restrict__ C, int ldc, int offC,
                       int M, int N, int K, float scale) {
    const int BM = 64, BN = 64, BK = 16;
    __shared__ unsigned long long As2[BK][BM];
    __shared__ __align__(16) float Bs[BK][BN];
    int tid = threadIdx.x;
    int tx = tid & 15, ty = tid >> 4;
    int row0 = blockIdx.x * BM, col0 = blockIdx.y * BN;
    unsigned long long acc[4][2];
#pragma unroll
    for (int i = 0; i < 4; i++) { acc[i][0] = 0ull; acc[i][1] = 0ull; }
    int la_m = tid >> 2, la_k = (tid & 3) * 4;
    int lb_k = tid >> 4, lb_n = (tid & 15) * 4;
    for (int kt = 0; kt < K; kt += BK) {
        float a0 = 0.f, a1 = 0.f, a2 = 0.f, a3 = 0.f;
        int r = row0 + la_m;
        if (r < M) {
            if (VECA) {
                if (kt + la_k < K) {
                    float4 v4 = *(const float4*)(A + (size_t)r * lda + offA + kt + la_k);
                    a0 = v4.x; a1 = v4.y; a2 = v4.z; a3 = v4.w;
                }
            } else {
                int kb = kt + la_k;
                if (kb + 0 < K) a0 = A[(size_t)r * lda + offA + (kb + 0) * sA];
                if (kb + 1 < K) a1 = A[(size_t)r * lda + offA + (kb + 1) * sA];
                if (kb + 2 < K) a2 = A[(size_t)r * lda + offA + (kb + 2) * sA];
                if (kb + 3 < K) a3 = A[(size_t)r * lda + offA + (kb + 3) * sA];
            }
        }
        As2[la_k + 0][la_m] = pk2(a0);
        As2[la_k + 1][la_m] = pk2(a1);
        As2[la_k + 2][la_m] = pk2(a2);
        As2[la_k + 3][la_m] = pk2(a3);
        int kb = kt + lb_k;
        float4 b4 = make_float4(0.f, 0.f, 0.f, 0.f);
        if (kb < K) b4 = *(const float4*)(B + (size_t)kb * ldb + col0 + lb_n);
        *(float4*)&Bs[lb_k][lb_n] = b4;
        __syncthreads();
#pragma unroll
        for (int kk = 0; kk < BK; kk++) {
            ulonglong2 b01 = *(const ulonglong2*)&Bs[kk][tx * 4];
            unsigned long long av[4];
#pragma unroll
            for (int i = 0; i < 4; i++) av[i] = As2[kk][ty * 4 + i];
#pragma unroll
            for (int i = 0; i < 4; i++) {
                ffma2(acc[i][0], av[i], b01.x);
                ffma2(acc[i][1], av[i], b01.y);
            }
        }
        __syncthreads();
    }
#pragma unroll
    for (int i = 0; i < 4; i++) {
        int r = row0 + ty * 4 + i;
        if (r >= M) continue;
#pragma unroll
        for (int jp = 0; jp < 2; jp++) {
            float2 v = upk(acc[i][jp]);
            int c0 = col0 + tx * 4 + jp * 2;
            C[(size_t)r * ldc + offC + c0]     = v.x * scale;
            C[(size_t)r * ldc + offC + c0 + 1] = v.y * scale;
        }
    }
}

// ---------------- launch ----------------
extern "C" void kernel_launch(void* const* d_in, const int* in_sizes, int n_in,
                              void* d_out, int out_size) {
    const float* node_feats = (const float*)d_in[0];
    const void*  edge_index = d_in[1];
    const float* edge_attrs = (const float*)d_in[2];
    const float* edge_feats = (const float*)d_in[3];
    const float* W_up_s     = (const float*)d_in[4];
    const float* W_up_v     = (const float*)d_in[5];
    const float* W1         = (const float*)d_in[6];
    const float* W2         = (const float*)d_in[7];
    const float* W3         = (const float*)d_in[8];
    const float* W4         = (const float*)d_in[9];
    const float* W_out_s    = (const float*)d_in[10];
    const float* W_out_v    = (const float*)d_in[11];
    float* out = (float*)d_out;

    // SILU_CST on host (same trapezoid as reference; runs at capture)
    double I = 0.0;
    for (int i = 0; i <= 200000; i++) {
        double z = -12.0 + 24.0 * ((double)i / 200000.0);
        double pdf = exp(-0.5 * z * z) * 0.3989422804014326779399461;
        double s = z / (1.0 + exp(-z));
        double f = s * s * pdf;
        I += (i == 0 || i == 200000) ? 0.5 * f : f;
    }
    I *= 24.0 / 200000.0;
    float cstF = (float)(1.0 / sqrt(I));

    float *pS, *pV;
    ushort_t *pW2H, *pW2L, *pW3H, *pW3L, *pW4H, *pW4L, *pWsH, *pWvH;
    cudaGetSymbolAddress((void**)&pS,  gS);
    cudaGetSymbolAddress((void**)&pV,  gV);
    cudaGetSymbolAddress((void**)&pW2H, gW2H);
    cudaGetSymbolAddress((void**)&pW2L, gW2L);
    cudaGetSymbolAddress((void**)&pW3H, gW3H);
    cudaGetSymbolAddress((void**)&pW3L, gW3L);
    cudaGetSymbolAddress((void**)&pW4H, gW4H);
    cudaGetSymbolAddress((void**)&pW4L, gW4L);
    cudaGetSymbolAddress((void**)&pWsH, gWsH);
    cudaGetSymbolAddress((void**)&pWvH, gWvH);

    const float inv_m = 0.08838834764831845f;

    cudaFuncSetAttribute(mlp_outs_fused, cudaFuncAttributeMaxDynamicSharedMemorySize, FUSE_SMEM);

    detect_idx_kernel<<<1, 32>>>((const int*)edge_index);
    prep_w<0><<<16, 256>>>(W2, 64, 64, pW2H, pW2L);
    prep_w<0><<<16, 256>>>(W3, 64, 64, pW3H, pW3L);
    prep_w<0><<<128, 256>>>(W4, 64, 512, pW4H, pW4L);
    prep_w<1><<<128, 256>>>(W_out_s, 256, 128, pWsH, nullptr);
    prep_w<1><<<128, 256>>>(W_out_v, 256, 128, pWvH, nullptr);
    // node up-projections first (gS/gV needed by fused kernel)
    gemm_k<true><<<dim3(157, 2), 256>>>(node_feats, 512, 0, 1, W_up_s, 128,
                                        pS, 128, 0, NN, 128, 128, inv_m);
    for (int m = 0; m < 3; m++)
        gemm_k<false><<<dim3(157, 2), 256>>>(node_feats, 512, 128 + m, 3, W_up_v, 128,
                                             pV, 384, m * 128, NN, 128, 128, inv_m);
    // fused MLP + W4 + out_s; writes T[:,256:512] + out[:, :128]
    mlp_outs_fused<<<1563, 256, FUSE_SMEM>>>(edge_feats, W1, edge_index, edge_attrs,
                                             out, cstF);
    // out_v from T[:,256:512]
    mma_outv<<<4688, 256>>>(edge_index, edge_attrs, out);
    (void)in_sizes; (void)n_in; (void)out_size;
}